// round 2
// baseline (speedup 1.0000x reference)
#include <cuda_runtime.h>
#include <math.h>

// ---------------------------------------------------------------------------
// Shapes (fixed by the problem)
// ---------------------------------------------------------------------------
namespace {
constexpr int kD   = 1024;
constexpr int kDff = 4096;
constexpr int kB   = 8;
constexpr int kS   = 1024;
constexpr int kM   = kB * kS;   // 8192 rows
constexpr int kH   = 16;        // heads
}

// ---------------------------------------------------------------------------
// Scratch (static device globals -- no allocation allowed)
// ---------------------------------------------------------------------------
__device__ float g_h [(size_t)kM * kD];
__device__ float g_q [(size_t)kM * kD];
__device__ float g_k [(size_t)kM * kD];
__device__ float g_v [(size_t)kM * kD];
__device__ float g_wv[(size_t)kM * kD];
__device__ float g_x1[(size_t)kM * kD];
__device__ float g_u [(size_t)kM * kDff];
__device__ float g_t [kM * 4];

// ---------------------------------------------------------------------------
// LayerNorm: one block per row of 1024, 256 threads, float4 per thread
// ---------------------------------------------------------------------------
__global__ void ln_kernel(const float* __restrict__ x, const float* __restrict__ g,
                          const float* __restrict__ b, float* __restrict__ y)
{
    const int row = blockIdx.x;
    const int tid = threadIdx.x;
    float4 v = ((const float4*)(x + (size_t)row * kD))[tid];
    float s  = v.x + v.y + v.z + v.w;
    float sq = v.x*v.x + v.y*v.y + v.z*v.z + v.w*v.w;
#pragma unroll
    for (int o = 16; o; o >>= 1) {
        s  += __shfl_xor_sync(0xffffffffu, s,  o);
        sq += __shfl_xor_sync(0xffffffffu, sq, o);
    }
    __shared__ float ss[8], ssq[8];
    const int w = tid >> 5, lane = tid & 31;
    if (lane == 0) { ss[w] = s; ssq[w] = sq; }
    __syncthreads();
    if (w == 0) {
        float a = (lane < 8) ? ss[lane]  : 0.f;
        float c = (lane < 8) ? ssq[lane] : 0.f;
#pragma unroll
        for (int o = 4; o; o >>= 1) {
            a += __shfl_xor_sync(0xffffffffu, a, o);
            c += __shfl_xor_sync(0xffffffffu, c, o);
        }
        if (lane == 0) { ss[0] = a; ssq[0] = c; }
    }
    __syncthreads();
    const float mean = ss[0] * (1.f / kD);
    const float var  = ssq[0] * (1.f / kD) - mean * mean;
    const float rstd = rsqrtf(var + 1e-5f);
    float4 gv = ((const float4*)g)[tid];
    float4 bv = ((const float4*)b)[tid];
    float4 o4;
    o4.x = (v.x - mean) * rstd * gv.x + bv.x;
    o4.y = (v.y - mean) * rstd * gv.y + bv.y;
    o4.z = (v.z - mean) * rstd * gv.z + bv.z;
    o4.w = (v.w - mean) * rstd * gv.w + bv.w;
    ((float4*)(y + (size_t)row * kD))[tid] = o4;
}

// ---------------------------------------------------------------------------
// GEMM: C[M,N] = A[M,K] @ B[N,K]^T (+bias[N]) (+GELU) (+residual)
// Both operands K-major (rows contiguous). 128x128 tile, BK=8, 256 thr, 8x8.
// ---------------------------------------------------------------------------
template <int GELU>
__global__ void __launch_bounds__(256)
gemm_tn(const float* __restrict__ A, const float* __restrict__ B,
        const float* __restrict__ bias, const float* __restrict__ res,
        float* __restrict__ C, int M, int N, int K)
{
    __shared__ float As[8][128];
    __shared__ float Bs[8][128];
    const int tid = threadIdx.x;
    const int tx = tid & 15;
    const int ty = tid >> 4;
    const int bm = blockIdx.y * 128;
    const int bn = blockIdx.x * 128;
    const int lr = tid >> 1;          // 0..127 tile row
    const int lk = (tid & 1) * 4;     // 0 or 4
    const float* Ap = A + (size_t)(bm + lr) * K + lk;
    const float* Bp = B + (size_t)(bn + lr) * K + lk;

    float acc[8][8];
#pragma unroll
    for (int i = 0; i < 8; i++)
#pragma unroll
        for (int j = 0; j < 8; j++) acc[i][j] = 0.f;

    for (int kb = 0; kb < K; kb += 8) {
        float4 av = *(const float4*)(Ap + kb);
        float4 bv = *(const float4*)(Bp + kb);
        __syncthreads();
        As[lk + 0][lr] = av.x; As[lk + 1][lr] = av.y;
        As[lk + 2][lr] = av.z; As[lk + 3][lr] = av.w;
        Bs[lk + 0][lr] = bv.x; Bs[lk + 1][lr] = bv.y;
        Bs[lk + 2][lr] = bv.z; Bs[lk + 3][lr] = bv.w;
        __syncthreads();
#pragma unroll
        for (int kk = 0; kk < 8; kk++) {
            float4 a0 = *(const float4*)&As[kk][ty * 8];
            float4 a1 = *(const float4*)&As[kk][ty * 8 + 4];
            float4 b0 = *(const float4*)&Bs[kk][tx * 8];
            float4 b1 = *(const float4*)&Bs[kk][tx * 8 + 4];
            float a[8]  = {a0.x, a0.y, a0.z, a0.w, a1.x, a1.y, a1.z, a1.w};
            float bb[8] = {b0.x, b0.y, b0.z, b0.w, b1.x, b1.y, b1.z, b1.w};
#pragma unroll
            for (int i = 0; i < 8; i++)
#pragma unroll
                for (int j = 0; j < 8; j++) acc[i][j] += a[i] * bb[j];
        }
    }

    float bcol[8];
#pragma unroll
    for (int j = 0; j < 8; j++) bcol[j] = bias ? bias[bn + tx * 8 + j] : 0.f;

#pragma unroll
    for (int i = 0; i < 8; i++) {
        const size_t off = (size_t)(bm + ty * 8 + i) * N + bn + tx * 8;
        float v[8];
#pragma unroll
        for (int j = 0; j < 8; j++) {
            float t = acc[i][j] + bcol[j];
            if (GELU) t = 0.5f * t * (1.f + erff(t * 0.70710678118f));
            v[j] = t;
        }
        if (res) {
            float4 r0 = *(const float4*)(res + off);
            float4 r1 = *(const float4*)(res + off + 4);
            v[0] += r0.x; v[1] += r0.y; v[2] += r0.z; v[3] += r0.w;
            v[4] += r1.x; v[5] += r1.y; v[6] += r1.z; v[7] += r1.w;
        }
        *(float4*)(C + off)     = make_float4(v[0], v[1], v[2], v[3]);
        *(float4*)(C + off + 4) = make_float4(v[4], v[5], v[6], v[7]);
    }
}

// ---------------------------------------------------------------------------
// LoRA rank-4 down-projection: t[m,r] = sum_k h[m,k] * la[r,k]
// ---------------------------------------------------------------------------
__global__ void lora_t_kernel(const float* __restrict__ h, const float* __restrict__ la,
                              float* __restrict__ t)
{
    const int row = blockIdx.x, tid = threadIdx.x;
    float4 hv = ((const float4*)(h + (size_t)row * kD))[tid];
    float acc[4];
#pragma unroll
    for (int r = 0; r < 4; r++) {
        float4 av = ((const float4*)(la + r * kD))[tid];
        acc[r] = hv.x*av.x + hv.y*av.y + hv.z*av.z + hv.w*av.w;
    }
#pragma unroll
    for (int o = 16; o; o >>= 1)
#pragma unroll
        for (int r = 0; r < 4; r++)
            acc[r] += __shfl_xor_sync(0xffffffffu, acc[r], o);
    __shared__ float sm[8][4];
    const int w = tid >> 5, lane = tid & 31;
    if (lane == 0) { sm[w][0]=acc[0]; sm[w][1]=acc[1]; sm[w][2]=acc[2]; sm[w][3]=acc[3]; }
    __syncthreads();
    if (tid < 4) {
        float s = 0.f;
#pragma unroll
        for (int w2 = 0; w2 < 8; w2++) s += sm[w2][tid];
        t[row * 4 + tid] = s;
    }
}

// C[m,n] += 0.25 * sum_r t[m,r] * lb[n,r]   (N fixed at 1024)
__global__ void rank4_add_kernel(float* __restrict__ C, const float* __restrict__ t,
                                 const float* __restrict__ lb)
{
    const int idx = blockIdx.x * 256 + threadIdx.x;
    const int m = idx >> 10;
    const int n = idx & 1023;
    const float* tm  = t + m * 4;
    const float* lbn = lb + n * 4;
    C[idx] += 0.25f * (tm[0]*lbn[0] + tm[1]*lbn[1] + tm[2]*lbn[2] + tm[3]*lbn[3]);
}

// ---------------------------------------------------------------------------
// Flash attention (fp32, online softmax). Block: 64 q-rows of one (b,h).
// grid = (16 q-tiles, 128 b*h), 256 threads (16x16, 4x4 micro-tile).
// smem (dynamic, 64KB): Qt[k][r], Kt[k][r], Vs[r][c], Pt[key][r]
// ---------------------------------------------------------------------------
__global__ void __launch_bounds__(256)
attn_kernel(const float* __restrict__ Q, const float* __restrict__ K,
            const float* __restrict__ V, float* __restrict__ O)
{
    extern __shared__ float smf[];
    float* Qt = smf;            // 64x64 transposed [k*64 + r]
    float* Kt = smf + 4096;     // 64x64 transposed [k*64 + r]
    float* Vs = smf + 8192;     // 64x64 natural    [r*64 + c]
    float* Pt = smf + 12288;    // 64x64 transposed [key*64 + r]

    const int tid = threadIdx.x;
    const int tx = tid & 15;
    const int ty = tid >> 4;
    const int qt = blockIdx.x;
    const int bh = blockIdx.y;
    const int b  = bh >> 4;
    const int h  = bh & 15;
    const size_t rowbase = (size_t)b * kS;
    const int cb = h * 64;

    // Load Q tile transposed, pre-scaled by 1/sqrt(hd) = 0.125
#pragma unroll
    for (int l = 0; l < 4; l++) {
        int idx = tid + 256 * l;
        int r = idx >> 4;
        int c = (idx & 15) * 4;
        float4 qv = *(const float4*)(Q + (rowbase + qt * 64 + r) * kD + cb + c);
        Qt[(c+0)*64 + r] = qv.x * 0.125f;
        Qt[(c+1)*64 + r] = qv.y * 0.125f;
        Qt[(c+2)*64 + r] = qv.z * 0.125f;
        Qt[(c+3)*64 + r] = qv.w * 0.125f;
    }

    float m_i[4], l_i[4], oa[4][4];
#pragma unroll
    for (int i = 0; i < 4; i++) {
        m_i[i] = -1e30f; l_i[i] = 0.f;
#pragma unroll
        for (int j = 0; j < 4; j++) oa[i][j] = 0.f;
    }

    for (int kt = 0; kt < 16; kt++) {
        __syncthreads();   // previous PV done (also covers Q load at kt=0)
#pragma unroll
        for (int l = 0; l < 4; l++) {
            int idx = tid + 256 * l;
            int r = idx >> 4;
            int c = (idx & 15) * 4;
            size_t goff = (rowbase + kt * 64 + r) * kD + cb + c;
            float4 kv = *(const float4*)(K + goff);
            Kt[(c+0)*64 + r] = kv.x;
            Kt[(c+1)*64 + r] = kv.y;
            Kt[(c+2)*64 + r] = kv.z;
            Kt[(c+3)*64 + r] = kv.w;
            float4 vv = *(const float4*)(V + goff);
            *(float4*)&Vs[r*64 + c] = vv;
        }
        __syncthreads();

        // S = Q K^T  (4x4 per thread)
        float s[4][4];
#pragma unroll
        for (int i = 0; i < 4; i++)
#pragma unroll
            for (int j = 0; j < 4; j++) s[i][j] = 0.f;

#pragma unroll 8
        for (int kk = 0; kk < 64; kk++) {
            float4 a  = *(const float4*)&Qt[kk*64 + ty*4];
            float4 bq = *(const float4*)&Kt[kk*64 + tx*4];
            s[0][0]+=a.x*bq.x; s[0][1]+=a.x*bq.y; s[0][2]+=a.x*bq.z; s[0][3]+=a.x*bq.w;
            s[1][0]+=a.y*bq.x; s[1][1]+=a.y*bq.y; s[1][2]+=a.y*bq.z; s[1][3]+=a.y*bq.w;
            s[2][0]+=a.z*bq.x; s[2][1]+=a.z*bq.y; s[2][2]+=a.z*bq.z; s[2][3]+=a.z*bq.w;
            s[3][0]+=a.w*bq.x; s[3][1]+=a.w*bq.y; s[3][2]+=a.w*bq.z; s[3][3]+=a.w*bq.w;
        }

        // Online softmax per q-row; rows live in 16-lane shuffle groups
#pragma unroll
        for (int i = 0; i < 4; i++) {
            float rm = fmaxf(fmaxf(s[i][0], s[i][1]), fmaxf(s[i][2], s[i][3]));
#pragma unroll
            for (int o = 8; o; o >>= 1)
                rm = fmaxf(rm, __shfl_xor_sync(0xffffffffu, rm, o, 16));
            const float mn  = fmaxf(m_i[i], rm);
            const float fac = __expf(m_i[i] - mn);
            const float p0 = __expf(s[i][0] - mn);
            const float p1 = __expf(s[i][1] - mn);
            const float p2 = __expf(s[i][2] - mn);
            const float p3 = __expf(s[i][3] - mn);
            float rs = p0 + p1 + p2 + p3;
#pragma unroll
            for (int o = 8; o; o >>= 1)
                rs += __shfl_xor_sync(0xffffffffu, rs, o, 16);
            l_i[i] = l_i[i] * fac + rs;
            m_i[i] = mn;
            oa[i][0] *= fac; oa[i][1] *= fac; oa[i][2] *= fac; oa[i][3] *= fac;
            Pt[(tx*4+0)*64 + ty*4+i] = p0;
            Pt[(tx*4+1)*64 + ty*4+i] = p1;
            Pt[(tx*4+2)*64 + ty*4+i] = p2;
            Pt[(tx*4+3)*64 + ty*4+i] = p3;
        }
        __syncthreads();

        // O += P V
#pragma unroll 8
        for (int kk = 0; kk < 64; kk++) {
            float4 a  = *(const float4*)&Pt[kk*64 + ty*4];
            float4 bv = *(const float4*)&Vs[kk*64 + tx*4];
            oa[0][0]+=a.x*bv.x; oa[0][1]+=a.x*bv.y; oa[0][2]+=a.x*bv.z; oa[0][3]+=a.x*bv.w;
            oa[1][0]+=a.y*bv.x; oa[1][1]+=a.y*bv.y; oa[1][2]+=a.y*bv.z; oa[1][3]+=a.y*bv.w;
            oa[2][0]+=a.z*bv.x; oa[2][1]+=a.z*bv.y; oa[2][2]+=a.z*bv.z; oa[2][3]+=a.z*bv.w;
            oa[3][0]+=a.w*bv.x; oa[3][1]+=a.w*bv.y; oa[3][2]+=a.w*bv.z; oa[3][3]+=a.w*bv.w;
        }
    }

#pragma unroll
    for (int i = 0; i < 4; i++) {
        const float inv = 1.f / l_i[i];
        const size_t off = (rowbase + qt*64 + ty*4 + i) * kD + cb + tx*4;
        *(float4*)(O + off) =
            make_float4(oa[i][0]*inv, oa[i][1]*inv, oa[i][2]*inv, oa[i][3]*inv);
    }
}

// ---------------------------------------------------------------------------
// Host launcher
// ---------------------------------------------------------------------------
extern "C" void kernel_launch(void* const* d_in, const int* in_sizes, int n_in,
                              void* d_out, int out_size)
{
    (void)in_sizes; (void)n_in; (void)out_size;
    const float* x    = (const float*)d_in[0];
    const float* Wq   = (const float*)d_in[1];
    const float* bq   = (const float*)d_in[2];
    const float* Wk   = (const float*)d_in[3];
    const float* Wv   = (const float*)d_in[4];
    const float* bv   = (const float*)d_in[5];
    const float* Wo   = (const float*)d_in[6];
    const float* bo   = (const float*)d_in[7];
    const float* la_k = (const float*)d_in[8];
    const float* lb_k = (const float*)d_in[9];
    const float* la_v = (const float*)d_in[10];
    const float* lb_v = (const float*)d_in[11];
    const float* la_o = (const float*)d_in[12];
    const float* lb_o = (const float*)d_in[13];
    const float* ga   = (const float*)d_in[14];
    const float* ba   = (const float*)d_in[15];
    const float* W1   = (const float*)d_in[16];
    const float* b1   = (const float*)d_in[17];
    const float* W2   = (const float*)d_in[18];
    const float* b2   = (const float*)d_in[19];
    const float* gm   = (const float*)d_in[20];
    const float* bmn  = (const float*)d_in[21];
    float* out = (float*)d_out;

    static float *p_h = nullptr, *p_q, *p_k, *p_v, *p_wv, *p_x1, *p_u, *p_t;
    if (!p_h) {
        cudaGetSymbolAddress((void**)&p_q,  g_q);
        cudaGetSymbolAddress((void**)&p_k,  g_k);
        cudaGetSymbolAddress((void**)&p_v,  g_v);
        cudaGetSymbolAddress((void**)&p_wv, g_wv);
        cudaGetSymbolAddress((void**)&p_x1, g_x1);
        cudaGetSymbolAddress((void**)&p_u,  g_u);
        cudaGetSymbolAddress((void**)&p_t,  g_t);
        cudaFuncSetAttribute(attn_kernel,
                             cudaFuncAttributeMaxDynamicSharedMemorySize, 65536);
        cudaGetSymbolAddress((void**)&p_h,  g_h);   // set p_h last (init flag)
    }

    const dim3 blk(256);
    const dim3 gD(kD / 128, kM / 128);      // (8, 64)
    const dim3 gF(kDff / 128, kM / 128);    // (32, 64)
    const int r4_blocks = (kM * kD) / 256;

    // h = LN(x)
    ln_kernel<<<kM, blk>>>(x, ga, ba, p_h);
    // q = h Wq^T + bq
    gemm_tn<0><<<gD, blk>>>(p_h, Wq, bq, nullptr, p_q, kM, kD, kD);
    // k = h Wk^T + lora_k(h)
    gemm_tn<0><<<gD, blk>>>(p_h, Wk, nullptr, nullptr, p_k, kM, kD, kD);
    lora_t_kernel<<<kM, blk>>>(p_h, la_k, p_t);
    rank4_add_kernel<<<r4_blocks, blk>>>(p_k, p_t, lb_k);
    // v = h Wv^T + bv + lora_v(h)
    gemm_tn<0><<<gD, blk>>>(p_h, Wv, bv, nullptr, p_v, kM, kD, kD);
    lora_t_kernel<<<kM, blk>>>(p_h, la_v, p_t);
    rank4_add_kernel<<<r4_blocks, blk>>>(p_v, p_t, lb_v);
    // wv = softmax(q k^T / sqrt(hd)) v
    attn_kernel<<<dim3(16, kB * kH), blk, 65536>>>(p_q, p_k, p_v, p_wv);
    // x1 = x + wv Wo^T + bo + lora_o(wv)
    gemm_tn<0><<<gD, blk>>>(p_wv, Wo, bo, x, p_x1, kM, kD, kD);
    lora_t_kernel<<<kM, blk>>>(p_wv, la_o, p_t);
    rank4_add_kernel<<<r4_blocks, blk>>>(p_x1, p_t, lb_o);
    // h = LN(x1)
    ln_kernel<<<kM, blk>>>(p_x1, gm, bmn, p_h);
    // u = gelu(h W1^T + b1)
    gemm_tn<1><<<gF, blk>>>(p_h, W1, b1, nullptr, p_u, kM, kDff, kD);
    // out = x1 + u W2^T + b2
    gemm_tn<0><<<gD, blk>>>(p_u, W2, b2, p_x1, out, kM, kD, kDff);
}

// round 5
// speedup vs baseline: 1.8752x; 1.8752x over previous
#include <cuda_runtime.h>
#include <cuda_bf16.h>
#include <cstdint>
#include <math.h>

// ---------------------------------------------------------------------------
// Shapes (fixed by the problem)
// ---------------------------------------------------------------------------
namespace {
constexpr int kD   = 1024;
constexpr int kDff = 4096;
constexpr int kB   = 8;
constexpr int kS   = 1024;
constexpr int kM   = kB * kS;   // 8192 rows
constexpr int kH   = 16;        // heads
}

// ---------------------------------------------------------------------------
// Scratch (static device globals -- no allocation allowed)
// ---------------------------------------------------------------------------
__device__ float g_h [(size_t)kM * kD];
__device__ float g_q [(size_t)kM * kD];
__device__ float g_k [(size_t)kM * kD];
__device__ float g_v [(size_t)kM * kD];
__device__ float g_wv[(size_t)kM * kD];
__device__ float g_x1[(size_t)kM * kD];
__device__ float g_u [(size_t)kM * kDff];
__device__ float g_t [kM * 4];
__device__ __nv_bfloat16 g_a_hi[(size_t)kM * kDff];
__device__ __nv_bfloat16 g_a_lo[(size_t)kM * kDff];
__device__ __nv_bfloat16 g_w_hi[(size_t)kDff * kD];
__device__ __nv_bfloat16 g_w_lo[(size_t)kDff * kD];

// ---------------------------------------------------------------------------
// PTX helpers (portable sm_80+: cp.async / ldmatrix / mma.sync)
// ---------------------------------------------------------------------------
__device__ __forceinline__ uint32_t smem_u32(const void* p) {
    uint32_t a;
    asm("{ .reg .u64 t; cvta.to.shared.u64 t, %1; cvt.u32.u64 %0, t; }"
        : "=r"(a) : "l"(p));
    return a;
}

#define CP_ASYNC16(saddr, gptr) \
    asm volatile("cp.async.cg.shared.global [%0], [%1], 16;" \
        :: "r"(saddr), "l"(gptr))

#define CP_COMMIT() asm volatile("cp.async.commit_group;" ::: "memory")

#define LDSM_X4(r0, r1, r2, r3, addr) \
    asm volatile("ldmatrix.sync.aligned.m8n8.x4.shared.b16 {%0,%1,%2,%3}, [%4];" \
        : "=r"(r0), "=r"(r1), "=r"(r2), "=r"(r3) : "r"(addr))

#define MMA16816(d, a, b) \
    asm volatile("mma.sync.aligned.m16n8k16.row.col.f32.bf16.bf16.f32 " \
        "{%0,%1,%2,%3}, {%4,%5,%6,%7}, {%8,%9}, {%0,%1,%2,%3};" \
        : "+f"((d)[0]), "+f"((d)[1]), "+f"((d)[2]), "+f"((d)[3]) \
        : "r"((a)[0]), "r"((a)[1]), "r"((a)[2]), "r"((a)[3]), \
          "r"((b)[0]), "r"((b)[1]))

// ---------------------------------------------------------------------------
// fp32 -> (bf16 hi, bf16 lo) split
// ---------------------------------------------------------------------------
__global__ void split_kernel(const float* __restrict__ x, __nv_bfloat16* __restrict__ hi,
                             __nv_bfloat16* __restrict__ lo, int n4)
{
    const int i = blockIdx.x * 256 + threadIdx.x;
    if (i >= n4) return;
    float4 v = ((const float4*)x)[i];
    __nv_bfloat16 h0 = __float2bfloat16(v.x);
    __nv_bfloat16 h1 = __float2bfloat16(v.y);
    __nv_bfloat16 h2 = __float2bfloat16(v.z);
    __nv_bfloat16 h3 = __float2bfloat16(v.w);
    __nv_bfloat16 l0 = __float2bfloat16(v.x - __bfloat162float(h0));
    __nv_bfloat16 l1 = __float2bfloat16(v.y - __bfloat162float(h1));
    __nv_bfloat16 l2 = __float2bfloat16(v.z - __bfloat162float(h2));
    __nv_bfloat16 l3 = __float2bfloat16(v.w - __bfloat162float(h3));
    __nv_bfloat162 hp0; hp0.x = h0; hp0.y = h1;
    __nv_bfloat162 hp1; hp1.x = h2; hp1.y = h3;
    __nv_bfloat162 lp0; lp0.x = l0; lp0.y = l1;
    __nv_bfloat162 lp1; lp1.x = l2; lp1.y = l3;
    ((__nv_bfloat162*)hi)[i * 2 + 0] = hp0;
    ((__nv_bfloat162*)hi)[i * 2 + 1] = hp1;
    ((__nv_bfloat162*)lo)[i * 2 + 0] = lp0;
    ((__nv_bfloat162*)lo)[i * 2 + 1] = lp1;
}

// ---------------------------------------------------------------------------
// Tensor-core GEMM (mma.sync bf16, split hi/lo 3-term):
//   C[M,N] = A[M,K] @ B[N,K]^T (+bias) (+0.25 * lt @ lb^T) (+GELU) (+res)
// 128x128 tile, BK=32, 256 threads (8 warps, 2x4 of 64x32 warp tiles),
// cp.async double-buffered. Smem rows: 32 bf16 data + 8 pad = 80B stride
// (conflict-free for ldmatrix: 20-word row stride covers all banks per 8 rows).
// ---------------------------------------------------------------------------
namespace {
constexpr uint32_t kTile  = 10240;   // 128 rows * 80 B
constexpr uint32_t kStage = 4 * kTile;
constexpr int      kRowB  = 80;      // bytes per smem row
}

template <int GELU>
__global__ void __launch_bounds__(256)
gemm_mma(const __nv_bfloat16* __restrict__ Ahi, const __nv_bfloat16* __restrict__ Alo,
         const __nv_bfloat16* __restrict__ Bhi, const __nv_bfloat16* __restrict__ Blo,
         const float* __restrict__ bias, const float* __restrict__ res,
         const float* __restrict__ lt, const float* __restrict__ lb,
         float* __restrict__ C, int M, int N, int K)
{
    extern __shared__ char smem[];
    const uint32_t sbase = smem_u32(smem);
    const int tid  = threadIdx.x;
    const int lane = tid & 31;
    const int wid  = tid >> 5;
    const int bm = blockIdx.y * 128;
    const int bn = blockIdx.x * 128;
    const int warp_m = (wid >> 2) * 64;   // 0 or 64
    const int warp_n = (wid & 3) * 32;    // 0,32,64,96

    // ---- global->smem load mapping: 512 16B chunks per tile, 2 per thread
    const int row0 = tid >> 2;            // chunk row for i=0 (chunk=tid)
    const int c16a = tid & 3;
    // second chunk: tid+256 -> row += 64, same c16
    const uint32_t soff0 = (uint32_t)(row0 * kRowB + c16a * 16);
    const uint32_t soff1 = soff0 + 64u * kRowB;

    float acc[4][4][4];
#pragma unroll
    for (int i = 0; i < 4; i++)
#pragma unroll
        for (int j = 0; j < 4; j++)
#pragma unroll
            for (int r = 0; r < 4; r++) acc[i][j][r] = 0.f;

    // ---- ldmatrix base offsets (within a stage)
    const uint32_t a_off = (uint32_t)((warp_m + (lane & 15)) * kRowB + (lane >> 4) * 16);
    const uint32_t b_off = (uint32_t)((warp_n + (lane & 7) + ((lane >> 4) & 1) * 8) * kRowB
                                      + ((lane >> 3) & 1) * 16);

    const int nIter = K >> 5;

    auto load_stage = [&](int it, int s) {
        const int k0 = it << 5;
        const uint32_t sbuf = sbase + (uint32_t)s * kStage;
        const size_t ga0 = (size_t)(bm + row0) * K + k0 + c16a * 8;
        const size_t gb0 = (size_t)(bn + row0) * K + k0 + c16a * 8;
        const size_t ga1 = ga0 + (size_t)64 * K;
        const size_t gb1 = gb0 + (size_t)64 * K;
        CP_ASYNC16(sbuf +             soff0, Ahi + ga0);
        CP_ASYNC16(sbuf +             soff1, Ahi + ga1);
        CP_ASYNC16(sbuf + kTile +     soff0, Alo + ga0);
        CP_ASYNC16(sbuf + kTile +     soff1, Alo + ga1);
        CP_ASYNC16(sbuf + 2 * kTile + soff0, Bhi + gb0);
        CP_ASYNC16(sbuf + 2 * kTile + soff1, Bhi + gb1);
        CP_ASYNC16(sbuf + 3 * kTile + soff0, Blo + gb0);
        CP_ASYNC16(sbuf + 3 * kTile + soff1, Blo + gb1);
        CP_COMMIT();
    };

    load_stage(0, 0);

    for (int it = 0; it < nIter; ++it) {
        if (it + 1 < nIter) {
            load_stage(it + 1, (it + 1) & 1);
            asm volatile("cp.async.wait_group 1;" ::: "memory");
        } else {
            asm volatile("cp.async.wait_group 0;" ::: "memory");
        }
        __syncthreads();

        const uint32_t sbuf = sbase + (uint32_t)(it & 1) * kStage;
        const uint32_t abase = sbuf + a_off;
        const uint32_t bbase = sbuf + 2 * kTile + b_off;

#pragma unroll
        for (int ks = 0; ks < 2; ks++) {
            const uint32_t ko = (uint32_t)ks * 32;   // 16 bf16 = 32 B
            uint32_t ah[4][4], al[4][4], bh[4][2], bl[4][2];
#pragma unroll
            for (int i = 0; i < 4; i++) {
                LDSM_X4(ah[i][0], ah[i][1], ah[i][2], ah[i][3],
                        abase + (uint32_t)i * (16 * kRowB) + ko);
                LDSM_X4(al[i][0], al[i][1], al[i][2], al[i][3],
                        abase + kTile + (uint32_t)i * (16 * kRowB) + ko);
            }
#pragma unroll
            for (int p = 0; p < 2; p++) {
                LDSM_X4(bh[2*p][0], bh[2*p][1], bh[2*p+1][0], bh[2*p+1][1],
                        bbase + (uint32_t)p * (16 * kRowB) + ko);
                LDSM_X4(bl[2*p][0], bl[2*p][1], bl[2*p+1][0], bl[2*p+1][1],
                        bbase + kTile + (uint32_t)p * (16 * kRowB) + ko);
            }
#pragma unroll
            for (int i = 0; i < 4; i++)
#pragma unroll
                for (int j = 0; j < 4; j++) {
                    MMA16816(acc[i][j], ah[i], bh[j]);
                    MMA16816(acc[i][j], ah[i], bl[j]);
                    MMA16816(acc[i][j], al[i], bh[j]);
                }
        }
        __syncthreads();
    }

    // ---- epilogue
    const int g  = lane >> 2;
    const int t4 = lane & 3;
#pragma unroll
    for (int i = 0; i < 4; i++) {
        const int mlo = bm + warp_m + 16 * i + g;
        const int mhi = mlo + 8;
        float4 ltl = make_float4(0.f, 0.f, 0.f, 0.f);
        float4 lth = ltl;
        if (lb) {
            ltl = *(const float4*)(lt + (size_t)mlo * 4);
            lth = *(const float4*)(lt + (size_t)mhi * 4);
        }
#pragma unroll
        for (int j = 0; j < 4; j++) {
            const int n0 = bn + warp_n + 8 * j + 2 * t4;
            float b0 = 0.f, b1 = 0.f;
            if (bias) { b0 = bias[n0]; b1 = bias[n0 + 1]; }
            if (lb) {
                float4 q0 = *(const float4*)(lb + (size_t)n0 * 4);
                float4 q1 = *(const float4*)(lb + (size_t)(n0 + 1) * 4);
                b0 += 0.25f * (ltl.x*q0.x + ltl.y*q0.y + ltl.z*q0.z + ltl.w*q0.w);
                b1 += 0.25f * (ltl.x*q1.x + ltl.y*q1.y + ltl.z*q1.z + ltl.w*q1.w);
            }
            float v0 = acc[i][j][0] + b0;
            float v1 = acc[i][j][1] + b1;
            float b2 = 0.f, b3 = 0.f;
            if (bias) { b2 = bias[n0]; b3 = bias[n0 + 1]; }
            if (lb) {
                float4 q0 = *(const float4*)(lb + (size_t)n0 * 4);
                float4 q1 = *(const float4*)(lb + (size_t)(n0 + 1) * 4);
                b2 += 0.25f * (lth.x*q0.x + lth.y*q0.y + lth.z*q0.z + lth.w*q0.w);
                b3 += 0.25f * (lth.x*q1.x + lth.y*q1.y + lth.z*q1.z + lth.w*q1.w);
            }
            float v2 = acc[i][j][2] + b2;
            float v3 = acc[i][j][3] + b3;
            if (GELU) {
                v0 = 0.5f * v0 * (1.f + erff(v0 * 0.70710678118f));
                v1 = 0.5f * v1 * (1.f + erff(v1 * 0.70710678118f));
                v2 = 0.5f * v2 * (1.f + erff(v2 * 0.70710678118f));
                v3 = 0.5f * v3 * (1.f + erff(v3 * 0.70710678118f));
            }
            const size_t olo = (size_t)mlo * N + n0;
            const size_t ohi = (size_t)mhi * N + n0;
            if (res) {
                float2 r0 = *(const float2*)(res + olo);
                float2 r1 = *(const float2*)(res + ohi);
                v0 += r0.x; v1 += r0.y; v2 += r1.x; v3 += r1.y;
            }
            *(float2*)(C + olo) = make_float2(v0, v1);
            *(float2*)(C + ohi) = make_float2(v2, v3);
        }
    }
}

// ---------------------------------------------------------------------------
// LayerNorm
// ---------------------------------------------------------------------------
__global__ void ln_kernel(const float* __restrict__ x, const float* __restrict__ g,
                          const float* __restrict__ b, float* __restrict__ y)
{
    const int row = blockIdx.x;
    const int tid = threadIdx.x;
    float4 v = ((const float4*)(x + (size_t)row * kD))[tid];
    float s  = v.x + v.y + v.z + v.w;
    float sq = v.x*v.x + v.y*v.y + v.z*v.z + v.w*v.w;
#pragma unroll
    for (int o = 16; o; o >>= 1) {
        s  += __shfl_xor_sync(0xffffffffu, s,  o);
        sq += __shfl_xor_sync(0xffffffffu, sq, o);
    }
    __shared__ float ss[8], ssq[8];
    const int w = tid >> 5, lane = tid & 31;
    if (lane == 0) { ss[w] = s; ssq[w] = sq; }
    __syncthreads();
    if (w == 0) {
        float a = (lane < 8) ? ss[lane]  : 0.f;
        float c = (lane < 8) ? ssq[lane] : 0.f;
#pragma unroll
        for (int o = 4; o; o >>= 1) {
            a += __shfl_xor_sync(0xffffffffu, a, o);
            c += __shfl_xor_sync(0xffffffffu, c, o);
        }
        if (lane == 0) { ss[0] = a; ssq[0] = c; }
    }
    __syncthreads();
    const float mean = ss[0] * (1.f / kD);
    const float var  = ssq[0] * (1.f / kD) - mean * mean;
    const float rstd = rsqrtf(var + 1e-5f);
    float4 gv = ((const float4*)g)[tid];
    float4 bv = ((const float4*)b)[tid];
    float4 o4;
    o4.x = (v.x - mean) * rstd * gv.x + bv.x;
    o4.y = (v.y - mean) * rstd * gv.y + bv.y;
    o4.z = (v.z - mean) * rstd * gv.z + bv.z;
    o4.w = (v.w - mean) * rstd * gv.w + bv.w;
    ((float4*)(y + (size_t)row * kD))[tid] = o4;
}

// ---------------------------------------------------------------------------
// LoRA rank-4 down-projection: t[m,r] = sum_k h[m,k] * la[r,k]
// ---------------------------------------------------------------------------
__global__ void lora_t_kernel(const float* __restrict__ h, const float* __restrict__ la,
                              float* __restrict__ t)
{
    const int row = blockIdx.x, tid = threadIdx.x;
    float4 hv = ((const float4*)(h + (size_t)row * kD))[tid];
    float acc[4];
#pragma unroll
    for (int r = 0; r < 4; r++) {
        float4 av = ((const float4*)(la + r * kD))[tid];
        acc[r] = hv.x*av.x + hv.y*av.y + hv.z*av.z + hv.w*av.w;
    }
#pragma unroll
    for (int o = 16; o; o >>= 1)
#pragma unroll
        for (int r = 0; r < 4; r++)
            acc[r] += __shfl_xor_sync(0xffffffffu, acc[r], o);
    __shared__ float sm[8][4];
    const int w = tid >> 5, lane = tid & 31;
    if (lane == 0) { sm[w][0]=acc[0]; sm[w][1]=acc[1]; sm[w][2]=acc[2]; sm[w][3]=acc[3]; }
    __syncthreads();
    if (tid < 4) {
        float s = 0.f;
#pragma unroll
        for (int w2 = 0; w2 < 8; w2++) s += sm[w2][tid];
        t[row * 4 + tid] = s;
    }
}

// ---------------------------------------------------------------------------
// Flash attention (fp32, online softmax). Block: 64 q-rows of one (b,h).
// ---------------------------------------------------------------------------
__global__ void __launch_bounds__(256)
attn_kernel(const float* __restrict__ Q, const float* __restrict__ K,
            const float* __restrict__ V, float* __restrict__ O)
{
    extern __shared__ float smf[];
    float* Qt = smf;            // 64x64 transposed [k*64 + r]
    float* Kt = smf + 4096;
    float* Vs = smf + 8192;
    float* Pt = smf + 12288;

    const int tid = threadIdx.x;
    const int tx = tid & 15;
    const int ty = tid >> 4;
    const int qt = blockIdx.x;
    const int bh = blockIdx.y;
    const int b  = bh >> 4;
    const int h  = bh & 15;
    const size_t rowbase = (size_t)b * kS;
    const int cb = h * 64;

#pragma unroll
    for (int l = 0; l < 4; l++) {
        int idx = tid + 256 * l;
        int r = idx >> 4;
        int c = (idx & 15) * 4;
        float4 qv = *(const float4*)(Q + (rowbase + qt * 64 + r) * kD + cb + c);
        Qt[(c+0)*64 + r] = qv.x * 0.125f;
        Qt[(c+1)*64 + r] = qv.y * 0.125f;
        Qt[(c+2)*64 + r] = qv.z * 0.125f;
        Qt[(c+3)*64 + r] = qv.w * 0.125f;
    }

    float m_i[4], l_i[4], oa[4][4];
#pragma unroll
    for (int i = 0; i < 4; i++) {
        m_i[i] = -1e30f; l_i[i] = 0.f;
#pragma unroll
        for (int j = 0; j < 4; j++) oa[i][j] = 0.f;
    }

    for (int kt = 0; kt < 16; kt++) {
        __syncthreads();
#pragma unroll
        for (int l = 0; l < 4; l++) {
            int idx = tid + 256 * l;
            int r = idx >> 4;
            int c = (idx & 15) * 4;
            size_t goff = (rowbase + kt * 64 + r) * kD + cb + c;
            float4 kv = *(const float4*)(K + goff);
            Kt[(c+0)*64 + r] = kv.x;
            Kt[(c+1)*64 + r] = kv.y;
            Kt[(c+2)*64 + r] = kv.z;
            Kt[(c+3)*64 + r] = kv.w;
            float4 vv = *(const float4*)(V + goff);
            *(float4*)&Vs[r*64 + c] = vv;
        }
        __syncthreads();

        float s[4][4];
#pragma unroll
        for (int i = 0; i < 4; i++)
#pragma unroll
            for (int j = 0; j < 4; j++) s[i][j] = 0.f;

#pragma unroll 8
        for (int kk = 0; kk < 64; kk++) {
            float4 a  = *(const float4*)&Qt[kk*64 + ty*4];
            float4 bq = *(const float4*)&Kt[kk*64 + tx*4];
            s[0][0]+=a.x*bq.x; s[0][1]+=a.x*bq.y; s[0][2]+=a.x*bq.z; s[0][3]+=a.x*bq.w;
            s[1][0]+=a.y*bq.x; s[1][1]+=a.y*bq.y; s[1][2]+=a.y*bq.z; s[1][3]+=a.y*bq.w;
            s[2][0]+=a.z*bq.x; s[2][1]+=a.z*bq.y; s[2][2]+=a.z*bq.z; s[2][3]+=a.z*bq.w;
            s[3][0]+=a.w*bq.x; s[3][1]+=a.w*bq.y; s[3][2]+=a.w*bq.z; s[3][3]+=a.w*bq.w;
        }

#pragma unroll
        for (int i = 0; i < 4; i++) {
            float rm = fmaxf(fmaxf(s[i][0], s[i][1]), fmaxf(s[i][2], s[i][3]));
#pragma unroll
            for (int o = 8; o; o >>= 1)
                rm = fmaxf(rm, __shfl_xor_sync(0xffffffffu, rm, o, 16));
            const float mn  = fmaxf(m_i[i], rm);
            const float fac = __expf(m_i[i] - mn);
            const float p0 = __expf(s[i][0] - mn);
            const float p1 = __expf(s[i][1] - mn);
            const float p2 = __expf(s[i][2] - mn);
            const float p3 = __expf(s[i][3] - mn);
            float rs = p0 + p1 + p2 + p3;
#pragma unroll
            for (int o = 8; o; o >>= 1)
                rs += __shfl_xor_sync(0xffffffffu, rs, o, 16);
            l_i[i] = l_i[i] * fac + rs;
            m_i[i] = mn;
            oa[i][0] *= fac; oa[i][1] *= fac; oa[i][2] *= fac; oa[i][3] *= fac;
            Pt[(tx*4+0)*64 + ty*4+i] = p0;
            Pt[(tx*4+1)*64 + ty*4+i] = p1;
            Pt[(tx*4+2)*64 + ty*4+i] = p2;
            Pt[(tx*4+3)*64 + ty*4+i] = p3;
        }
        __syncthreads();

#pragma unroll 8
        for (int kk = 0; kk < 64; kk++) {
            float4 a  = *(const float4*)&Pt[kk*64 + ty*4];
            float4 bv = *(const float4*)&Vs[kk*64 + tx*4];
            oa[0][0]+=a.x*bv.x; oa[0][1]+=a.x*bv.y; oa[0][2]+=a.x*bv.z; oa[0][3]+=a.x*bv.w;
            oa[1][0]+=a.y*bv.x; oa[1][1]+=a.y*bv.y; oa[1][2]+=a.y*bv.z; oa[1][3]+=a.y*bv.w;
            oa[2][0]+=a.z*bv.x; oa[2][1]+=a.z*bv.y; oa[2][2]+=a.z*bv.z; oa[2][3]+=a.z*bv.w;
            oa[3][0]+=a.w*bv.x; oa[3][1]+=a.w*bv.y; oa[3][2]+=a.w*bv.z; oa[3][3]+=a.w*bv.w;
        }
    }

#pragma unroll
    for (int i = 0; i < 4; i++) {
        const float inv = 1.f / l_i[i];
        const size_t off = (rowbase + qt*64 + ty*4 + i) * kD + cb + tx*4;
        *(float4*)(O + off) =
            make_float4(oa[i][0]*inv, oa[i][1]*inv, oa[i][2]*inv, oa[i][3]*inv);
    }
}

// ---------------------------------------------------------------------------
// Host launcher
// ---------------------------------------------------------------------------
extern "C" void kernel_launch(void* const* d_in, const int* in_sizes, int n_in,
                              void* d_out, int out_size)
{
    (void)in_sizes; (void)n_in; (void)out_size;
    const float* x    = (const float*)d_in[0];
    const float* Wq   = (const float*)d_in[1];
    const float* bq   = (const float*)d_in[2];
    const float* Wk   = (const float*)d_in[3];
    const float* Wv   = (const float*)d_in[4];
    const float* bv   = (const float*)d_in[5];
    const float* Wo   = (const float*)d_in[6];
    const float* bo   = (const float*)d_in[7];
    const float* la_k = (const float*)d_in[8];
    const float* lb_k = (const float*)d_in[9];
    const float* la_v = (const float*)d_in[10];
    const float* lb_v = (const float*)d_in[11];
    const float* la_o = (const float*)d_in[12];
    const float* lb_o = (const float*)d_in[13];
    const float* ga   = (const float*)d_in[14];
    const float* ba   = (const float*)d_in[15];
    const float* W1   = (const float*)d_in[16];
    const float* b1   = (const float*)d_in[17];
    const float* W2   = (const float*)d_in[18];
    const float* b2   = (const float*)d_in[19];
    const float* gm   = (const float*)d_in[20];
    const float* bmn  = (const float*)d_in[21];
    float* out = (float*)d_out;

    static float *p_h = nullptr, *p_q, *p_k, *p_v, *p_wv, *p_x1, *p_u, *p_t;
    static __nv_bfloat16 *pa_hi, *pa_lo, *pw_hi, *pw_lo;
    if (!p_h) {
        cudaGetSymbolAddress((void**)&p_q,   g_q);
        cudaGetSymbolAddress((void**)&p_k,   g_k);
        cudaGetSymbolAddress((void**)&p_v,   g_v);
        cudaGetSymbolAddress((void**)&p_wv,  g_wv);
        cudaGetSymbolAddress((void**)&p_x1,  g_x1);
        cudaGetSymbolAddress((void**)&p_u,   g_u);
        cudaGetSymbolAddress((void**)&p_t,   g_t);
        cudaGetSymbolAddress((void**)&pa_hi, g_a_hi);
        cudaGetSymbolAddress((void**)&pa_lo, g_a_lo);
        cudaGetSymbolAddress((void**)&pw_hi, g_w_hi);
        cudaGetSymbolAddress((void**)&pw_lo, g_w_lo);
        cudaFuncSetAttribute(attn_kernel,
                             cudaFuncAttributeMaxDynamicSharedMemorySize, 65536);
        cudaFuncSetAttribute(gemm_mma<0>,
                             cudaFuncAttributeMaxDynamicSharedMemorySize, 2 * kStage);
        cudaFuncSetAttribute(gemm_mma<1>,
                             cudaFuncAttributeMaxDynamicSharedMemorySize, 2 * kStage);
        cudaGetSymbolAddress((void**)&p_h,   g_h);   // init flag last
    }

    const dim3 blk(256);
    const dim3 gD(kD / 128, kM / 128);      // (8, 64)
    const dim3 gF(kDff / 128, kM / 128);    // (32, 64)
    const int nAct  = kM * kD / 4;
    const int nActF = kM * kDff / 4;
    const int nWDD  = kD * kD / 4;
    const int nWDF  = kDff * kD / 4;
    const unsigned SMEM_G = 2 * kStage;     // 81920 B

    // ---- attention half ----
    ln_kernel<<<kM, blk>>>(x, ga, ba, p_h);
    split_kernel<<<nAct / 256, blk>>>(p_h, pa_hi, pa_lo, nAct);

    split_kernel<<<nWDD / 256, blk>>>(Wq, pw_hi, pw_lo, nWDD);
    gemm_mma<0><<<gD, blk, SMEM_G>>>(pa_hi, pa_lo, pw_hi, pw_lo,
                                     bq, nullptr, nullptr, nullptr, p_q, kM, kD, kD);

    split_kernel<<<nWDD / 256, blk>>>(Wk, pw_hi, pw_lo, nWDD);
    lora_t_kernel<<<kM, blk>>>(p_h, la_k, p_t);
    gemm_mma<0><<<gD, blk, SMEM_G>>>(pa_hi, pa_lo, pw_hi, pw_lo,
                                     nullptr, nullptr, p_t, lb_k, p_k, kM, kD, kD);

    split_kernel<<<nWDD / 256, blk>>>(Wv, pw_hi, pw_lo, nWDD);
    lora_t_kernel<<<kM, blk>>>(p_h, la_v, p_t);
    gemm_mma<0><<<gD, blk, SMEM_G>>>(pa_hi, pa_lo, pw_hi, pw_lo,
                                     bv, nullptr, p_t, lb_v, p_v, kM, kD, kD);

    attn_kernel<<<dim3(16, kB * kH), blk, 65536>>>(p_q, p_k, p_v, p_wv);

    split_kernel<<<nAct / 256, blk>>>(p_wv, pa_hi, pa_lo, nAct);
    lora_t_kernel<<<kM, blk>>>(p_wv, la_o, p_t);
    split_kernel<<<nWDD / 256, blk>>>(Wo, pw_hi, pw_lo, nWDD);
    gemm_mma<0><<<gD, blk, SMEM_G>>>(pa_hi, pa_lo, pw_hi, pw_lo,
                                     bo, x, p_t, lb_o, p_x1, kM, kD, kD);

    // ---- MLP half ----
    ln_kernel<<<kM, blk>>>(p_x1, gm, bmn, p_h);
    split_kernel<<<nAct / 256, blk>>>(p_h, pa_hi, pa_lo, nAct);
    split_kernel<<<nWDF / 256, blk>>>(W1, pw_hi, pw_lo, nWDF);
    gemm_mma<1><<<gF, blk, SMEM_G>>>(pa_hi, pa_lo, pw_hi, pw_lo,
                                     b1, nullptr, nullptr, nullptr, p_u, kM, kDff, kD);

    split_kernel<<<nActF / 256, blk>>>(p_u, pa_hi, pa_lo, nActF);
    split_kernel<<<nWDF / 256, blk>>>(W2, pw_hi, pw_lo, nWDF);
    gemm_mma<0><<<gD, blk, SMEM_G>>>(pa_hi, pa_lo, pw_hi, pw_lo,
                                     b2, p_x1, nullptr, nullptr, out, kM, kD, kDff);
}

// round 6
// speedup vs baseline: 1.9075x; 1.0172x over previous
#include <cuda_runtime.h>
#include <cuda_bf16.h>
#include <cstdint>
#include <math.h>

// ---------------------------------------------------------------------------
// Shapes (fixed by the problem)
// ---------------------------------------------------------------------------
namespace {
constexpr int kD   = 1024;
constexpr int kDff = 4096;
constexpr int kB   = 8;
constexpr int kS   = 1024;
constexpr int kM   = kB * kS;   // 8192 rows
constexpr int kH   = 16;        // heads
}

// ---------------------------------------------------------------------------
// Scratch (static device globals -- no allocation allowed)
// ---------------------------------------------------------------------------
__device__ float g_q [(size_t)kM * kD];
__device__ float g_k [(size_t)kM * kD];
__device__ float g_v [(size_t)kM * kD];
__device__ float g_x1[(size_t)kM * kD];
__device__ float g_u [(size_t)kM * kDff];   // reused as bf16 hi/lo of u
__device__ float g_t [kM * 4];
__device__ __nv_bfloat16 g_a_hi[(size_t)kM * kD];
__device__ __nv_bfloat16 g_a_lo[(size_t)kM * kD];
__device__ __nv_bfloat16 g_w_hi[(size_t)kDff * kD];
__device__ __nv_bfloat16 g_w_lo[(size_t)kDff * kD];

// ---------------------------------------------------------------------------
// PTX helpers (portable sm_80+: cp.async / ldmatrix / mma.sync)
// ---------------------------------------------------------------------------
__device__ __forceinline__ uint32_t smem_u32(const void* p) {
    uint32_t a;
    asm("{ .reg .u64 t; cvta.to.shared.u64 t, %1; cvt.u32.u64 %0, t; }"
        : "=r"(a) : "l"(p));
    return a;
}

#define CP_ASYNC16(saddr, gptr) \
    asm volatile("cp.async.cg.shared.global [%0], [%1], 16;" \
        :: "r"(saddr), "l"(gptr))

#define CP_COMMIT() asm volatile("cp.async.commit_group;" ::: "memory")

#define LDSM_X4(r0, r1, r2, r3, addr) \
    asm volatile("ldmatrix.sync.aligned.m8n8.x4.shared.b16 {%0,%1,%2,%3}, [%4];" \
        : "=r"(r0), "=r"(r1), "=r"(r2), "=r"(r3) : "r"(addr))

#define MMA16816(d, a, b) \
    asm volatile("mma.sync.aligned.m16n8k16.row.col.f32.bf16.bf16.f32 " \
        "{%0,%1,%2,%3}, {%4,%5,%6,%7}, {%8,%9}, {%0,%1,%2,%3};" \
        : "+f"((d)[0]), "+f"((d)[1]), "+f"((d)[2]), "+f"((d)[3]) \
        : "r"((a)[0]), "r"((a)[1]), "r"((a)[2]), "r"((a)[3]), \
          "r"((b)[0]), "r"((b)[1]))

__device__ __forceinline__ void split1(float v, __nv_bfloat16& h, __nv_bfloat16& l) {
    h = __float2bfloat16(v);
    l = __float2bfloat16(v - __bfloat162float(h));
}

// ---------------------------------------------------------------------------
// fp32 -> (bf16 hi, bf16 lo) split (weights)
// ---------------------------------------------------------------------------
__global__ void split_kernel(const float* __restrict__ x, __nv_bfloat16* __restrict__ hi,
                             __nv_bfloat16* __restrict__ lo, int n4)
{
    const int i = blockIdx.x * 256 + threadIdx.x;
    if (i >= n4) return;
    float4 v = ((const float4*)x)[i];
    __nv_bfloat16 h0, h1, h2, h3, l0, l1, l2, l3;
    split1(v.x, h0, l0); split1(v.y, h1, l1);
    split1(v.z, h2, l2); split1(v.w, h3, l3);
    __nv_bfloat162 hp0; hp0.x = h0; hp0.y = h1;
    __nv_bfloat162 hp1; hp1.x = h2; hp1.y = h3;
    __nv_bfloat162 lp0; lp0.x = l0; lp0.y = l1;
    __nv_bfloat162 lp1; lp1.x = l2; lp1.y = l3;
    ((__nv_bfloat162*)hi)[i * 2 + 0] = hp0;
    ((__nv_bfloat162*)hi)[i * 2 + 1] = hp1;
    ((__nv_bfloat162*)lo)[i * 2 + 0] = lp0;
    ((__nv_bfloat162*)lo)[i * 2 + 1] = lp1;
}

// ---------------------------------------------------------------------------
// Tensor-core GEMM (mma.sync bf16, split hi/lo 3-term, TERM-MAJOR ordering):
//   C = A @ B^T (+bias) (+0.25 * lt @ lb^T) (+GELU) (+res)
// 128x128 tile, BK=32, 256 threads, 3-stage cp.async ring.
// Smem rows: 32 bf16 + 8 pad = 80B stride (ldmatrix conflict-free).
// ---------------------------------------------------------------------------
namespace {
constexpr uint32_t kTile  = 10240;   // 128 rows * 80 B
constexpr uint32_t kStage = 4 * kTile;
constexpr int      kRowB  = 80;
}

template <int GELU, int SPLIT>
__global__ void __launch_bounds__(256)
gemm_mma(const __nv_bfloat16* __restrict__ Ahi, const __nv_bfloat16* __restrict__ Alo,
         const __nv_bfloat16* __restrict__ Bhi, const __nv_bfloat16* __restrict__ Blo,
         const float* __restrict__ bias, const float* __restrict__ res,
         const float* __restrict__ lt, const float* __restrict__ lb,
         float* __restrict__ C,
         __nv_bfloat16* __restrict__ Chi, __nv_bfloat16* __restrict__ Clo,
         int M, int N, int K)
{
    extern __shared__ char smem[];
    const uint32_t sbase = smem_u32(smem);
    const int tid  = threadIdx.x;
    const int lane = tid & 31;
    const int wid  = tid >> 5;
    const int bm = blockIdx.y * 128;
    const int bn = blockIdx.x * 128;
    const int warp_m = (wid >> 2) * 64;
    const int warp_n = (wid & 3) * 32;

    const int row0 = tid >> 2;
    const int c16a = tid & 3;
    const uint32_t soff0 = (uint32_t)(row0 * kRowB + c16a * 16);
    const uint32_t soff1 = soff0 + 64u * kRowB;

    float acc[4][4][4];
#pragma unroll
    for (int i = 0; i < 4; i++)
#pragma unroll
        for (int j = 0; j < 4; j++)
#pragma unroll
            for (int r = 0; r < 4; r++) acc[i][j][r] = 0.f;

    const uint32_t a_off = (uint32_t)((warp_m + (lane & 15)) * kRowB + (lane >> 4) * 16);
    const uint32_t b_off = (uint32_t)((warp_n + (lane & 7) + ((lane >> 4) & 1) * 8) * kRowB
                                      + ((lane >> 3) & 1) * 16);

    const int nIter = K >> 5;

    auto load_stage = [&](int it, int s) {
        const int k0 = it << 5;
        const uint32_t sbuf = sbase + (uint32_t)s * kStage;
        const size_t ga0 = (size_t)(bm + row0) * K + k0 + c16a * 8;
        const size_t gb0 = (size_t)(bn + row0) * K + k0 + c16a * 8;
        const size_t ga1 = ga0 + (size_t)64 * K;
        const size_t gb1 = gb0 + (size_t)64 * K;
        CP_ASYNC16(sbuf +             soff0, Ahi + ga0);
        CP_ASYNC16(sbuf +             soff1, Ahi + ga1);
        CP_ASYNC16(sbuf + kTile +     soff0, Alo + ga0);
        CP_ASYNC16(sbuf + kTile +     soff1, Alo + ga1);
        CP_ASYNC16(sbuf + 2 * kTile + soff0, Bhi + gb0);
        CP_ASYNC16(sbuf + 2 * kTile + soff1, Bhi + gb1);
        CP_ASYNC16(sbuf + 3 * kTile + soff0, Blo + gb0);
        CP_ASYNC16(sbuf + 3 * kTile + soff1, Blo + gb1);
        CP_COMMIT();
    };

    load_stage(0, 0);
    load_stage(1, 1);

    for (int it = 0; it < nIter; ++it) {
        if (it + 1 < nIter) {
            asm volatile("cp.async.wait_group 1;" ::: "memory");
        } else {
            asm volatile("cp.async.wait_group 0;" ::: "memory");
        }
        __syncthreads();
        // safe: all warps passed the barrier, so compute(it-1) on buffer
        // (it+2)%3 is finished everywhere before we overwrite it.
        if (it + 2 < nIter) load_stage(it + 2, (it + 2) % 3);

        const uint32_t sbuf = sbase + (uint32_t)(it % 3) * kStage;
        const uint32_t abase = sbuf + a_off;
        const uint32_t bbase = sbuf + 2 * kTile + b_off;

#pragma unroll
        for (int ks = 0; ks < 2; ks++) {
            const uint32_t ko = (uint32_t)ks * 32;
            uint32_t ah[4][4], al[4][4], bh[4][2], bl[4][2];
#pragma unroll
            for (int i = 0; i < 4; i++) {
                LDSM_X4(ah[i][0], ah[i][1], ah[i][2], ah[i][3],
                        abase + (uint32_t)i * (16 * kRowB) + ko);
                LDSM_X4(al[i][0], al[i][1], al[i][2], al[i][3],
                        abase + kTile + (uint32_t)i * (16 * kRowB) + ko);
            }
#pragma unroll
            for (int p = 0; p < 2; p++) {
                LDSM_X4(bh[2*p][0], bh[2*p][1], bh[2*p+1][0], bh[2*p+1][1],
                        bbase + (uint32_t)p * (16 * kRowB) + ko);
                LDSM_X4(bl[2*p][0], bl[2*p][1], bl[2*p+1][0], bl[2*p+1][1],
                        bbase + kTile + (uint32_t)p * (16 * kRowB) + ko);
            }
            // term-major: consecutive MMAs never share an accumulator
#pragma unroll
            for (int i = 0; i < 4; i++)
#pragma unroll
                for (int j = 0; j < 4; j++)
                    MMA16816(acc[i][j], ah[i], bh[j]);
#pragma unroll
            for (int i = 0; i < 4; i++)
#pragma unroll
                for (int j = 0; j < 4; j++)
                    MMA16816(acc[i][j], ah[i], bl[j]);
#pragma unroll
            for (int i = 0; i < 4; i++)
#pragma unroll
                for (int j = 0; j < 4; j++)
                    MMA16816(acc[i][j], al[i], bh[j]);
        }
        __syncthreads();
    }

    // ---- epilogue
    const int g  = lane >> 2;
    const int t4 = lane & 3;
#pragma unroll
    for (int i = 0; i < 4; i++) {
        const int mlo = bm + warp_m + 16 * i + g;
        const int mhi = mlo + 8;
        float4 ltl = make_float4(0.f, 0.f, 0.f, 0.f);
        float4 lth = ltl;
        if (lb) {
            ltl = *(const float4*)(lt + (size_t)mlo * 4);
            lth = *(const float4*)(lt + (size_t)mhi * 4);
        }
#pragma unroll
        for (int j = 0; j < 4; j++) {
            const int n0 = bn + warp_n + 8 * j + 2 * t4;
            float b0 = 0.f, b1 = 0.f;
            if (bias) { b0 = bias[n0]; b1 = bias[n0 + 1]; }
            float b2 = b0, b3 = b1;
            if (lb) {
                float4 q0 = *(const float4*)(lb + (size_t)n0 * 4);
                float4 q1 = *(const float4*)(lb + (size_t)(n0 + 1) * 4);
                b0 += 0.25f * (ltl.x*q0.x + ltl.y*q0.y + ltl.z*q0.z + ltl.w*q0.w);
                b1 += 0.25f * (ltl.x*q1.x + ltl.y*q1.y + ltl.z*q1.z + ltl.w*q1.w);
                b2 += 0.25f * (lth.x*q0.x + lth.y*q0.y + lth.z*q0.z + lth.w*q0.w);
                b3 += 0.25f * (lth.x*q1.x + lth.y*q1.y + lth.z*q1.z + lth.w*q1.w);
            }
            float v0 = acc[i][j][0] + b0;
            float v1 = acc[i][j][1] + b1;
            float v2 = acc[i][j][2] + b2;
            float v3 = acc[i][j][3] + b3;
            if (GELU) {
                v0 = 0.5f * v0 * (1.f + erff(v0 * 0.70710678118f));
                v1 = 0.5f * v1 * (1.f + erff(v1 * 0.70710678118f));
                v2 = 0.5f * v2 * (1.f + erff(v2 * 0.70710678118f));
                v3 = 0.5f * v3 * (1.f + erff(v3 * 0.70710678118f));
            }
            const size_t olo = (size_t)mlo * N + n0;
            const size_t ohi = (size_t)mhi * N + n0;
            if (SPLIT) {
                __nv_bfloat16 h0, h1, h2, h3, l0, l1, l2, l3;
                split1(v0, h0, l0); split1(v1, h1, l1);
                split1(v2, h2, l2); split1(v3, h3, l3);
                __nv_bfloat162 hp0; hp0.x = h0; hp0.y = h1;
                __nv_bfloat162 hp1; hp1.x = h2; hp1.y = h3;
                __nv_bfloat162 lp0; lp0.x = l0; lp0.y = l1;
                __nv_bfloat162 lp1; lp1.x = l2; lp1.y = l3;
                *(__nv_bfloat162*)(Chi + olo) = hp0;
                *(__nv_bfloat162*)(Chi + ohi) = hp1;
                *(__nv_bfloat162*)(Clo + olo) = lp0;
                *(__nv_bfloat162*)(Clo + ohi) = lp1;
            } else {
                if (res) {
                    float2 r0 = *(const float2*)(res + olo);
                    float2 r1 = *(const float2*)(res + ohi);
                    v0 += r0.x; v1 += r0.y; v2 += r1.x; v3 += r1.y;
                }
                *(float2*)(C + olo) = make_float2(v0, v1);
                *(float2*)(C + ohi) = make_float2(v2, v3);
            }
        }
    }
}

// ---------------------------------------------------------------------------
// LayerNorm -> split bf16 hi/lo directly
// ---------------------------------------------------------------------------
__global__ void ln_split_kernel(const float* __restrict__ x, const float* __restrict__ g,
                                const float* __restrict__ b,
                                __nv_bfloat16* __restrict__ yhi,
                                __nv_bfloat16* __restrict__ ylo)
{
    const int row = blockIdx.x;
    const int tid = threadIdx.x;
    float4 v = ((const float4*)(x + (size_t)row * kD))[tid];
    float s  = v.x + v.y + v.z + v.w;
    float sq = v.x*v.x + v.y*v.y + v.z*v.z + v.w*v.w;
#pragma unroll
    for (int o = 16; o; o >>= 1) {
        s  += __shfl_xor_sync(0xffffffffu, s,  o);
        sq += __shfl_xor_sync(0xffffffffu, sq, o);
    }
    __shared__ float ss[8], ssq[8];
    const int w = tid >> 5, lane = tid & 31;
    if (lane == 0) { ss[w] = s; ssq[w] = sq; }
    __syncthreads();
    if (w == 0) {
        float a = (lane < 8) ? ss[lane]  : 0.f;
        float c = (lane < 8) ? ssq[lane] : 0.f;
#pragma unroll
        for (int o = 4; o; o >>= 1) {
            a += __shfl_xor_sync(0xffffffffu, a, o);
            c += __shfl_xor_sync(0xffffffffu, c, o);
        }
        if (lane == 0) { ss[0] = a; ssq[0] = c; }
    }
    __syncthreads();
    const float mean = ss[0] * (1.f / kD);
    const float var  = ssq[0] * (1.f / kD) - mean * mean;
    const float rstd = rsqrtf(var + 1e-5f);
    float4 gv = ((const float4*)g)[tid];
    float4 bv = ((const float4*)b)[tid];
    float y0 = (v.x - mean) * rstd * gv.x + bv.x;
    float y1 = (v.y - mean) * rstd * gv.y + bv.y;
    float y2 = (v.z - mean) * rstd * gv.z + bv.z;
    float y3 = (v.w - mean) * rstd * gv.w + bv.w;
    __nv_bfloat16 h0, h1, h2, h3, l0, l1, l2, l3;
    split1(y0, h0, l0); split1(y1, h1, l1);
    split1(y2, h2, l2); split1(y3, h3, l3);
    __nv_bfloat162 hp0; hp0.x = h0; hp0.y = h1;
    __nv_bfloat162 hp1; hp1.x = h2; hp1.y = h3;
    __nv_bfloat162 lp0; lp0.x = l0; lp0.y = l1;
    __nv_bfloat162 lp1; lp1.x = l2; lp1.y = l3;
    ((__nv_bfloat162*)(yhi + (size_t)row * kD))[tid * 2 + 0] = hp0;
    ((__nv_bfloat162*)(yhi + (size_t)row * kD))[tid * 2 + 1] = hp1;
    ((__nv_bfloat162*)(ylo + (size_t)row * kD))[tid * 2 + 0] = lp0;
    ((__nv_bfloat162*)(ylo + (size_t)row * kD))[tid * 2 + 1] = lp1;
}

// ---------------------------------------------------------------------------
// LoRA rank-4 down-projection from bf16-hi input: t[m,r] = sum_k h[m,k]*la[r,k]
// ---------------------------------------------------------------------------
__global__ void lora_t_kernel(const __nv_bfloat16* __restrict__ h,
                              const float* __restrict__ la, float* __restrict__ t)
{
    const int row = blockIdx.x, tid = threadIdx.x;
    const __nv_bfloat162* hp = (const __nv_bfloat162*)(h + (size_t)row * kD);
    __nv_bfloat162 a0 = hp[tid * 2], a1 = hp[tid * 2 + 1];
    const float h0 = __bfloat162float(a0.x), h1 = __bfloat162float(a0.y);
    const float h2 = __bfloat162float(a1.x), h3 = __bfloat162float(a1.y);
    float acc[4];
#pragma unroll
    for (int r = 0; r < 4; r++) {
        float4 av = ((const float4*)(la + r * kD))[tid];
        acc[r] = h0*av.x + h1*av.y + h2*av.z + h3*av.w;
    }
#pragma unroll
    for (int o = 16; o; o >>= 1)
#pragma unroll
        for (int r = 0; r < 4; r++)
            acc[r] += __shfl_xor_sync(0xffffffffu, acc[r], o);
    __shared__ float sm[8][4];
    const int w = tid >> 5, lane = tid & 31;
    if (lane == 0) { sm[w][0]=acc[0]; sm[w][1]=acc[1]; sm[w][2]=acc[2]; sm[w][3]=acc[3]; }
    __syncthreads();
    if (tid < 4) {
        float s = 0.f;
#pragma unroll
        for (int w2 = 0; w2 < 8; w2++) s += sm[w2][tid];
        t[row * 4 + tid] = s;
    }
}

// ---------------------------------------------------------------------------
// Flash attention (fp32, online softmax) -> writes wv as bf16 hi/lo
// ---------------------------------------------------------------------------
__global__ void __launch_bounds__(256)
attn_kernel(const float* __restrict__ Q, const float* __restrict__ K,
            const float* __restrict__ V,
            __nv_bfloat16* __restrict__ Ohi, __nv_bfloat16* __restrict__ Olo)
{
    extern __shared__ float smf[];
    float* Qt = smf;
    float* Kt = smf + 4096;
    float* Vs = smf + 8192;
    float* Pt = smf + 12288;

    const int tid = threadIdx.x;
    const int tx = tid & 15;
    const int ty = tid >> 4;
    const int qt = blockIdx.x;
    const int bh = blockIdx.y;
    const int b  = bh >> 4;
    const int h  = bh & 15;
    const size_t rowbase = (size_t)b * kS;
    const int cb = h * 64;

#pragma unroll
    for (int l = 0; l < 4; l++) {
        int idx = tid + 256 * l;
        int r = idx >> 4;
        int c = (idx & 15) * 4;
        float4 qv = *(const float4*)(Q + (rowbase + qt * 64 + r) * kD + cb + c);
        Qt[(c+0)*64 + r] = qv.x * 0.125f;
        Qt[(c+1)*64 + r] = qv.y * 0.125f;
        Qt[(c+2)*64 + r] = qv.z * 0.125f;
        Qt[(c+3)*64 + r] = qv.w * 0.125f;
    }

    float m_i[4], l_i[4], oa[4][4];
#pragma unroll
    for (int i = 0; i < 4; i++) {
        m_i[i] = -1e30f; l_i[i] = 0.f;
#pragma unroll
        for (int j = 0; j < 4; j++) oa[i][j] = 0.f;
    }

    for (int kt = 0; kt < 16; kt++) {
        __syncthreads();
#pragma unroll
        for (int l = 0; l < 4; l++) {
            int idx = tid + 256 * l;
            int r = idx >> 4;
            int c = (idx & 15) * 4;
            size_t goff = (rowbase + kt * 64 + r) * kD + cb + c;
            float4 kv = *(const float4*)(K + goff);
            Kt[(c+0)*64 + r] = kv.x;
            Kt[(c+1)*64 + r] = kv.y;
            Kt[(c+2)*64 + r] = kv.z;
            Kt[(c+3)*64 + r] = kv.w;
            float4 vv = *(const float4*)(V + goff);
            *(float4*)&Vs[r*64 + c] = vv;
        }
        __syncthreads();

        float s[4][4];
#pragma unroll
        for (int i = 0; i < 4; i++)
#pragma unroll
            for (int j = 0; j < 4; j++) s[i][j] = 0.f;

#pragma unroll 8
        for (int kk = 0; kk < 64; kk++) {
            float4 a  = *(const float4*)&Qt[kk*64 + ty*4];
            float4 bq = *(const float4*)&Kt[kk*64 + tx*4];
            s[0][0]+=a.x*bq.x; s[0][1]+=a.x*bq.y; s[0][2]+=a.x*bq.z; s[0][3]+=a.x*bq.w;
            s[1][0]+=a.y*bq.x; s[1][1]+=a.y*bq.y; s[1][2]+=a.y*bq.z; s[1][3]+=a.y*bq.w;
            s[2][0]+=a.z*bq.x; s[2][1]+=a.z*bq.y; s[2][2]+=a.z*bq.z; s[2][3]+=a.z*bq.w;
            s[3][0]+=a.w*bq.x; s[3][1]+=a.w*bq.y; s[3][2]+=a.w*bq.z; s[3][3]+=a.w*bq.w;
        }

#pragma unroll
        for (int i = 0; i < 4; i++) {
            float rm = fmaxf(fmaxf(s[i][0], s[i][1]), fmaxf(s[i][2], s[i][3]));
#pragma unroll
            for (int o = 8; o; o >>= 1)
                rm = fmaxf(rm, __shfl_xor_sync(0xffffffffu, rm, o, 16));
            const float mn  = fmaxf(m_i[i], rm);
            const float fac = __expf(m_i[i] - mn);
            const float p0 = __expf(s[i][0] - mn);
            const float p1 = __expf(s[i][1] - mn);
            const float p2 = __expf(s[i][2] - mn);
            const float p3 = __expf(s[i][3] - mn);
            float rs = p0 + p1 + p2 + p3;
#pragma unroll
            for (int o = 8; o; o >>= 1)
                rs += __shfl_xor_sync(0xffffffffu, rs, o, 16);
            l_i[i] = l_i[i] * fac + rs;
            m_i[i] = mn;
            oa[i][0] *= fac; oa[i][1] *= fac; oa[i][2] *= fac; oa[i][3] *= fac;
            Pt[(tx*4+0)*64 + ty*4+i] = p0;
            Pt[(tx*4+1)*64 + ty*4+i] = p1;
            Pt[(tx*4+2)*64 + ty*4+i] = p2;
            Pt[(tx*4+3)*64 + ty*4+i] = p3;
        }
        __syncthreads();

#pragma unroll 8
        for (int kk = 0; kk < 64; kk++) {
            float4 a  = *(const float4*)&Pt[kk*64 + ty*4];
            float4 bv = *(const float4*)&Vs[kk*64 + tx*4];
            oa[0][0]+=a.x*bv.x; oa[0][1]+=a.x*bv.y; oa[0][2]+=a.x*bv.z; oa[0][3]+=a.x*bv.w;
            oa[1][0]+=a.y*bv.x; oa[1][1]+=a.y*bv.y; oa[1][2]+=a.y*bv.z; oa[1][3]+=a.y*bv.w;
            oa[2][0]+=a.z*bv.x; oa[2][1]+=a.z*bv.y; oa[2][2]+=a.z*bv.z; oa[2][3]+=a.z*bv.w;
            oa[3][0]+=a.w*bv.x; oa[3][1]+=a.w*bv.y; oa[3][2]+=a.w*bv.z; oa[3][3]+=a.w*bv.w;
        }
    }

#pragma unroll
    for (int i = 0; i < 4; i++) {
        const float inv = 1.f / l_i[i];
        const size_t off = (rowbase + qt*64 + ty*4 + i) * kD + cb + tx*4;
        const float o0 = oa[i][0]*inv, o1 = oa[i][1]*inv;
        const float o2 = oa[i][2]*inv, o3 = oa[i][3]*inv;
        __nv_bfloat16 h0, h1, h2, h3, l0, l1, l2, l3;
        split1(o0, h0, l0); split1(o1, h1, l1);
        split1(o2, h2, l2); split1(o3, h3, l3);
        __nv_bfloat162 hp0; hp0.x = h0; hp0.y = h1;
        __nv_bfloat162 hp1; hp1.x = h2; hp1.y = h3;
        __nv_bfloat162 lp0; lp0.x = l0; lp0.y = l1;
        __nv_bfloat162 lp1; lp1.x = l2; lp1.y = l3;
        ((__nv_bfloat162*)(Ohi + off))[0] = hp0;
        ((__nv_bfloat162*)(Ohi + off))[1] = hp1;
        ((__nv_bfloat162*)(Olo + off))[0] = lp0;
        ((__nv_bfloat162*)(Olo + off))[1] = lp1;
    }
}

// ---------------------------------------------------------------------------
// Host launcher
// ---------------------------------------------------------------------------
extern "C" void kernel_launch(void* const* d_in, const int* in_sizes, int n_in,
                              void* d_out, int out_size)
{
    (void)in_sizes; (void)n_in; (void)out_size;
    const float* x    = (const float*)d_in[0];
    const float* Wq   = (const float*)d_in[1];
    const float* bq   = (const float*)d_in[2];
    const float* Wk   = (const float*)d_in[3];
    const float* Wv   = (const float*)d_in[4];
    const float* bv   = (const float*)d_in[5];
    const float* Wo   = (const float*)d_in[6];
    const float* bo   = (const float*)d_in[7];
    const float* la_k = (const float*)d_in[8];
    const float* lb_k = (const float*)d_in[9];
    const float* la_v = (const float*)d_in[10];
    const float* lb_v = (const float*)d_in[11];
    const float* la_o = (const float*)d_in[12];
    const float* lb_o = (const float*)d_in[13];
    const float* ga   = (const float*)d_in[14];
    const float* ba   = (const float*)d_in[15];
    const float* W1   = (const float*)d_in[16];
    const float* b1   = (const float*)d_in[17];
    const float* W2   = (const float*)d_in[18];
    const float* b2   = (const float*)d_in[19];
    const float* gm   = (const float*)d_in[20];
    const float* bmn  = (const float*)d_in[21];
    float* out = (float*)d_out;

    static float *p_q = nullptr, *p_k, *p_v, *p_x1, *p_u, *p_t;
    static __nv_bfloat16 *pa_hi, *pa_lo, *pw_hi, *pw_lo, *pu_hi, *pu_lo;
    if (!p_q) {
        cudaGetSymbolAddress((void**)&p_k,   g_k);
        cudaGetSymbolAddress((void**)&p_v,   g_v);
        cudaGetSymbolAddress((void**)&p_x1,  g_x1);
        cudaGetSymbolAddress((void**)&p_u,   g_u);
        cudaGetSymbolAddress((void**)&p_t,   g_t);
        cudaGetSymbolAddress((void**)&pa_hi, g_a_hi);
        cudaGetSymbolAddress((void**)&pa_lo, g_a_lo);
        cudaGetSymbolAddress((void**)&pw_hi, g_w_hi);
        cudaGetSymbolAddress((void**)&pw_lo, g_w_lo);
        pu_hi = (__nv_bfloat16*)p_u;
        pu_lo = pu_hi + (size_t)kM * kDff;
        cudaFuncSetAttribute(attn_kernel,
                             cudaFuncAttributeMaxDynamicSharedMemorySize, 65536);
        cudaFuncSetAttribute(gemm_mma<0, 0>,
                             cudaFuncAttributeMaxDynamicSharedMemorySize, 3 * kStage);
        cudaFuncSetAttribute(gemm_mma<1, 1>,
                             cudaFuncAttributeMaxDynamicSharedMemorySize, 3 * kStage);
        cudaGetSymbolAddress((void**)&p_q,   g_q);   // init flag last
    }

    const dim3 blk(256);
    const dim3 gD(kD / 128, kM / 128);      // (8, 64)
    const dim3 gF(kDff / 128, kM / 128);    // (32, 64)
    const int nWDD  = kD * kD / 4;
    const int nWDF  = kDff * kD / 4;
    const unsigned SMEM_G = 3 * kStage;     // 122880 B

    // ---- attention half ----
    ln_split_kernel<<<kM, blk>>>(x, ga, ba, pa_hi, pa_lo);

    split_kernel<<<nWDD / 256, blk>>>(Wq, pw_hi, pw_lo, nWDD);
    gemm_mma<0, 0><<<gD, blk, SMEM_G>>>(pa_hi, pa_lo, pw_hi, pw_lo,
                                        bq, nullptr, nullptr, nullptr,
                                        p_q, nullptr, nullptr, kM, kD, kD);

    split_kernel<<<nWDD / 256, blk>>>(Wk, pw_hi, pw_lo, nWDD);
    lora_t_kernel<<<kM, blk>>>(pa_hi, la_k, p_t);
    gemm_mma<0, 0><<<gD, blk, SMEM_G>>>(pa_hi, pa_lo, pw_hi, pw_lo,
                                        nullptr, nullptr, p_t, lb_k,
                                        p_k, nullptr, nullptr, kM, kD, kD);

    split_kernel<<<nWDD / 256, blk>>>(Wv, pw_hi, pw_lo, nWDD);
    lora_t_kernel<<<kM, blk>>>(pa_hi, la_v, p_t);
    gemm_mma<0, 0><<<gD, blk, SMEM_G>>>(pa_hi, pa_lo, pw_hi, pw_lo,
                                        bv, nullptr, p_t, lb_v,
                                        p_v, nullptr, nullptr, kM, kD, kD);

    // attention writes wv split directly into pa_hi/pa_lo (h split dead now)
    attn_kernel<<<dim3(16, kB * kH), blk, 65536>>>(p_q, p_k, p_v, pa_hi, pa_lo);

    lora_t_kernel<<<kM, blk>>>(pa_hi, la_o, p_t);
    split_kernel<<<nWDD / 256, blk>>>(Wo, pw_hi, pw_lo, nWDD);
    gemm_mma<0, 0><<<gD, blk, SMEM_G>>>(pa_hi, pa_lo, pw_hi, pw_lo,
                                        bo, x, p_t, lb_o,
                                        p_x1, nullptr, nullptr, kM, kD, kD);

    // ---- MLP half ----
    ln_split_kernel<<<kM, blk>>>(p_x1, gm, bmn, pa_hi, pa_lo);
    split_kernel<<<nWDF / 256, blk>>>(W1, pw_hi, pw_lo, nWDF);
    gemm_mma<1, 1><<<gF, blk, SMEM_G>>>(pa_hi, pa_lo, pw_hi, pw_lo,
                                        b1, nullptr, nullptr, nullptr,
                                        nullptr, pu_hi, pu_lo, kM, kDff, kD);

    split_kernel<<<nWDF / 256, blk>>>(W2, pw_hi, pw_lo, nWDF);
    gemm_mma<0, 0><<<gD, blk, SMEM_G>>>(pu_hi, pu_lo, pw_hi, pw_lo,
                                        b2, p_x1, nullptr, nullptr,
                                        out, nullptr, nullptr, kM, kD, kDff);
}

// round 7
// speedup vs baseline: 2.6102x; 1.3684x over previous
#include <cuda_runtime.h>
#include <cuda_bf16.h>
#include <cstdint>
#include <math.h>

// ---------------------------------------------------------------------------
// Shapes (fixed by the problem)
// ---------------------------------------------------------------------------
namespace {
constexpr int kD   = 1024;
constexpr int kDff = 4096;
constexpr int kB   = 8;
constexpr int kS   = 1024;
constexpr int kM   = kB * kS;   // 8192 rows
constexpr int kH   = 16;        // heads
}

// ---------------------------------------------------------------------------
// Scratch (static device globals -- no allocation allowed)
// ---------------------------------------------------------------------------
__device__ float g_q [(size_t)kM * kD];     // reused: bf16 q_hi / q_lo
__device__ float g_k [(size_t)kM * kD];     // reused: bf16 k_hi / k_lo
__device__ float g_v [(size_t)kM * kD];     // reused: bf16 v_hi / v_lo
__device__ float g_x1[(size_t)kM * kD];
__device__ float g_u [(size_t)kM * kDff];   // reused: bf16 u_hi / u_lo
__device__ float g_t [kM * 4];
__device__ __nv_bfloat16 g_a_hi[(size_t)kM * kD];
__device__ __nv_bfloat16 g_a_lo[(size_t)kM * kD];
__device__ __nv_bfloat16 g_w_hi[(size_t)kDff * kD];
__device__ __nv_bfloat16 g_w_lo[(size_t)kDff * kD];

// ---------------------------------------------------------------------------
// PTX helpers (portable sm_80+: cp.async / ldmatrix / mma.sync)
// ---------------------------------------------------------------------------
__device__ __forceinline__ uint32_t smem_u32(const void* p) {
    uint32_t a;
    asm("{ .reg .u64 t; cvta.to.shared.u64 t, %1; cvt.u32.u64 %0, t; }"
        : "=r"(a) : "l"(p));
    return a;
}

#define CP_ASYNC16(saddr, gptr) \
    asm volatile("cp.async.cg.shared.global [%0], [%1], 16;" \
        :: "r"(saddr), "l"(gptr))

#define CP_COMMIT() asm volatile("cp.async.commit_group;" ::: "memory")

#define LDSM_X4(r0, r1, r2, r3, addr) \
    asm volatile("ldmatrix.sync.aligned.m8n8.x4.shared.b16 {%0,%1,%2,%3}, [%4];" \
        : "=r"(r0), "=r"(r1), "=r"(r2), "=r"(r3) : "r"(addr))

#define LDSM_X4T(r0, r1, r2, r3, addr) \
    asm volatile("ldmatrix.sync.aligned.m8n8.x4.trans.shared.b16 {%0,%1,%2,%3}, [%4];" \
        : "=r"(r0), "=r"(r1), "=r"(r2), "=r"(r3) : "r"(addr))

#define MMA16816(d, a, b) \
    asm volatile("mma.sync.aligned.m16n8k16.row.col.f32.bf16.bf16.f32 " \
        "{%0,%1,%2,%3}, {%4,%5,%6,%7}, {%8,%9}, {%0,%1,%2,%3};" \
        : "+f"((d)[0]), "+f"((d)[1]), "+f"((d)[2]), "+f"((d)[3]) \
        : "r"((a)[0]), "r"((a)[1]), "r"((a)[2]), "r"((a)[3]), \
          "r"((b)[0]), "r"((b)[1]))

__device__ __forceinline__ void split1(float v, __nv_bfloat16& h, __nv_bfloat16& l) {
    h = __float2bfloat16(v);
    l = __float2bfloat16(v - __bfloat162float(h));
}

__device__ __forceinline__ uint32_t pack_bf16x2(float a, float b) {
    __nv_bfloat162 t = __floats2bfloat162_rn(a, b);   // .x = a (low half)
    return *(uint32_t*)&t;
}

__device__ __forceinline__ void st_shared_v4(uint32_t addr, uint4 v) {
    asm volatile("st.shared.v4.b32 [%0], {%1, %2, %3, %4};"
        :: "r"(addr), "r"(v.x), "r"(v.y), "r"(v.z), "r"(v.w));
}

// ---------------------------------------------------------------------------
// fp32 -> (bf16 hi, bf16 lo) split (weights)
// ---------------------------------------------------------------------------
__global__ void split_kernel(const float* __restrict__ x, __nv_bfloat16* __restrict__ hi,
                             __nv_bfloat16* __restrict__ lo, int n4)
{
    const int i = blockIdx.x * 256 + threadIdx.x;
    if (i >= n4) return;
    float4 v = ((const float4*)x)[i];
    __nv_bfloat16 h0, h1, h2, h3, l0, l1, l2, l3;
    split1(v.x, h0, l0); split1(v.y, h1, l1);
    split1(v.z, h2, l2); split1(v.w, h3, l3);
    __nv_bfloat162 hp0; hp0.x = h0; hp0.y = h1;
    __nv_bfloat162 hp1; hp1.x = h2; hp1.y = h3;
    __nv_bfloat162 lp0; lp0.x = l0; lp0.y = l1;
    __nv_bfloat162 lp1; lp1.x = l2; lp1.y = l3;
    ((__nv_bfloat162*)hi)[i * 2 + 0] = hp0;
    ((__nv_bfloat162*)hi)[i * 2 + 1] = hp1;
    ((__nv_bfloat162*)lo)[i * 2 + 0] = lp0;
    ((__nv_bfloat162*)lo)[i * 2 + 1] = lp1;
}

// ---------------------------------------------------------------------------
// Tensor-core GEMM (mma.sync bf16, split hi/lo 3-term):
//   C = A @ B^T (+bias) (+0.25 * lt @ lb^T) (+GELU) (+res); SPLIT=1 -> bf16 hi/lo out
// 128x128 tile, BK=32, 256 threads, 3-stage cp.async ring. 80B smem row stride.
// ---------------------------------------------------------------------------
namespace {
constexpr uint32_t kTile  = 10240;   // 128 rows * 80 B
constexpr uint32_t kStage = 4 * kTile;
constexpr int      kRowB  = 80;
}

template <int GELU, int SPLIT>
__global__ void __launch_bounds__(256)
gemm_mma(const __nv_bfloat16* __restrict__ Ahi, const __nv_bfloat16* __restrict__ Alo,
         const __nv_bfloat16* __restrict__ Bhi, const __nv_bfloat16* __restrict__ Blo,
         const float* __restrict__ bias, const float* __restrict__ res,
         const float* __restrict__ lt, const float* __restrict__ lb,
         float* __restrict__ C,
         __nv_bfloat16* __restrict__ Chi, __nv_bfloat16* __restrict__ Clo,
         int M, int N, int K)
{
    extern __shared__ char smem[];
    const uint32_t sbase = smem_u32(smem);
    const int tid  = threadIdx.x;
    const int lane = tid & 31;
    const int wid  = tid >> 5;
    const int bm = blockIdx.y * 128;
    const int bn = blockIdx.x * 128;
    const int warp_m = (wid >> 2) * 64;
    const int warp_n = (wid & 3) * 32;

    const int row0 = tid >> 2;
    const int c16a = tid & 3;
    const uint32_t soff0 = (uint32_t)(row0 * kRowB + c16a * 16);
    const uint32_t soff1 = soff0 + 64u * kRowB;

    float acc[4][4][4];
#pragma unroll
    for (int i = 0; i < 4; i++)
#pragma unroll
        for (int j = 0; j < 4; j++)
#pragma unroll
            for (int r = 0; r < 4; r++) acc[i][j][r] = 0.f;

    const uint32_t a_off = (uint32_t)((warp_m + (lane & 15)) * kRowB + (lane >> 4) * 16);
    const uint32_t b_off = (uint32_t)((warp_n + (lane & 7) + ((lane >> 4) & 1) * 8) * kRowB
                                      + ((lane >> 3) & 1) * 16);

    const int nIter = K >> 5;

    auto load_stage = [&](int it, int s) {
        const int k0 = it << 5;
        const uint32_t sbuf = sbase + (uint32_t)s * kStage;
        const size_t ga0 = (size_t)(bm + row0) * K + k0 + c16a * 8;
        const size_t gb0 = (size_t)(bn + row0) * K + k0 + c16a * 8;
        const size_t ga1 = ga0 + (size_t)64 * K;
        const size_t gb1 = gb0 + (size_t)64 * K;
        CP_ASYNC16(sbuf +             soff0, Ahi + ga0);
        CP_ASYNC16(sbuf +             soff1, Ahi + ga1);
        CP_ASYNC16(sbuf + kTile +     soff0, Alo + ga0);
        CP_ASYNC16(sbuf + kTile +     soff1, Alo + ga1);
        CP_ASYNC16(sbuf + 2 * kTile + soff0, Bhi + gb0);
        CP_ASYNC16(sbuf + 2 * kTile + soff1, Bhi + gb1);
        CP_ASYNC16(sbuf + 3 * kTile + soff0, Blo + gb0);
        CP_ASYNC16(sbuf + 3 * kTile + soff1, Blo + gb1);
        CP_COMMIT();
    };

    load_stage(0, 0);
    load_stage(1, 1);

    for (int it = 0; it < nIter; ++it) {
        if (it + 1 < nIter) {
            asm volatile("cp.async.wait_group 1;" ::: "memory");
        } else {
            asm volatile("cp.async.wait_group 0;" ::: "memory");
        }
        __syncthreads();
        if (it + 2 < nIter) load_stage(it + 2, (it + 2) % 3);

        const uint32_t sbuf = sbase + (uint32_t)(it % 3) * kStage;
        const uint32_t abase = sbuf + a_off;
        const uint32_t bbase = sbuf + 2 * kTile + b_off;

#pragma unroll
        for (int ks = 0; ks < 2; ks++) {
            const uint32_t ko = (uint32_t)ks * 32;
            uint32_t ah[4][4], al[4][4], bh[4][2], bl[4][2];
#pragma unroll
            for (int i = 0; i < 4; i++) {
                LDSM_X4(ah[i][0], ah[i][1], ah[i][2], ah[i][3],
                        abase + (uint32_t)i * (16 * kRowB) + ko);
                LDSM_X4(al[i][0], al[i][1], al[i][2], al[i][3],
                        abase + kTile + (uint32_t)i * (16 * kRowB) + ko);
            }
#pragma unroll
            for (int p = 0; p < 2; p++) {
                LDSM_X4(bh[2*p][0], bh[2*p][1], bh[2*p+1][0], bh[2*p+1][1],
                        bbase + (uint32_t)p * (16 * kRowB) + ko);
                LDSM_X4(bl[2*p][0], bl[2*p][1], bl[2*p+1][0], bl[2*p+1][1],
                        bbase + kTile + (uint32_t)p * (16 * kRowB) + ko);
            }
#pragma unroll
            for (int i = 0; i < 4; i++)
#pragma unroll
                for (int j = 0; j < 4; j++)
                    MMA16816(acc[i][j], ah[i], bh[j]);
#pragma unroll
            for (int i = 0; i < 4; i++)
#pragma unroll
                for (int j = 0; j < 4; j++)
                    MMA16816(acc[i][j], ah[i], bl[j]);
#pragma unroll
            for (int i = 0; i < 4; i++)
#pragma unroll
                for (int j = 0; j < 4; j++)
                    MMA16816(acc[i][j], al[i], bh[j]);
        }
        __syncthreads();
    }

    // ---- epilogue
    const int g  = lane >> 2;
    const int t4 = lane & 3;
#pragma unroll
    for (int i = 0; i < 4; i++) {
        const int mlo = bm + warp_m + 16 * i + g;
        const int mhi = mlo + 8;
        float4 ltl = make_float4(0.f, 0.f, 0.f, 0.f);
        float4 lth = ltl;
        if (lb) {
            ltl = *(const float4*)(lt + (size_t)mlo * 4);
            lth = *(const float4*)(lt + (size_t)mhi * 4);
        }
#pragma unroll
        for (int j = 0; j < 4; j++) {
            const int n0 = bn + warp_n + 8 * j + 2 * t4;
            float b0 = 0.f, b1 = 0.f;
            if (bias) { b0 = bias[n0]; b1 = bias[n0 + 1]; }
            float b2 = b0, b3 = b1;
            if (lb) {
                float4 q0 = *(const float4*)(lb + (size_t)n0 * 4);
                float4 q1 = *(const float4*)(lb + (size_t)(n0 + 1) * 4);
                b0 += 0.25f * (ltl.x*q0.x + ltl.y*q0.y + ltl.z*q0.z + ltl.w*q0.w);
                b1 += 0.25f * (ltl.x*q1.x + ltl.y*q1.y + ltl.z*q1.z + ltl.w*q1.w);
                b2 += 0.25f * (lth.x*q0.x + lth.y*q0.y + lth.z*q0.z + lth.w*q0.w);
                b3 += 0.25f * (lth.x*q1.x + lth.y*q1.y + lth.z*q1.z + lth.w*q1.w);
            }
            float v0 = acc[i][j][0] + b0;
            float v1 = acc[i][j][1] + b1;
            float v2 = acc[i][j][2] + b2;
            float v3 = acc[i][j][3] + b3;
            if (GELU) {
                v0 = 0.5f * v0 * (1.f + erff(v0 * 0.70710678118f));
                v1 = 0.5f * v1 * (1.f + erff(v1 * 0.70710678118f));
                v2 = 0.5f * v2 * (1.f + erff(v2 * 0.70710678118f));
                v3 = 0.5f * v3 * (1.f + erff(v3 * 0.70710678118f));
            }
            const size_t olo = (size_t)mlo * N + n0;
            const size_t ohi = (size_t)mhi * N + n0;
            if (SPLIT) {
                __nv_bfloat16 h0, h1, h2, h3, l0, l1, l2, l3;
                split1(v0, h0, l0); split1(v1, h1, l1);
                split1(v2, h2, l2); split1(v3, h3, l3);
                __nv_bfloat162 hp0; hp0.x = h0; hp0.y = h1;
                __nv_bfloat162 hp1; hp1.x = h2; hp1.y = h3;
                __nv_bfloat162 lp0; lp0.x = l0; lp0.y = l1;
                __nv_bfloat162 lp1; lp1.x = l2; lp1.y = l3;
                *(__nv_bfloat162*)(Chi + olo) = hp0;
                *(__nv_bfloat162*)(Chi + ohi) = hp1;
                *(__nv_bfloat162*)(Clo + olo) = lp0;
                *(__nv_bfloat162*)(Clo + ohi) = lp1;
            } else {
                if (res) {
                    float2 r0 = *(const float2*)(res + olo);
                    float2 r1 = *(const float2*)(res + ohi);
                    v0 += r0.x; v1 += r0.y; v2 += r1.x; v3 += r1.y;
                }
                *(float2*)(C + olo) = make_float2(v0, v1);
                *(float2*)(C + ohi) = make_float2(v2, v3);
            }
        }
    }
}

// ---------------------------------------------------------------------------
// LayerNorm -> split bf16 hi/lo directly
// ---------------------------------------------------------------------------
__global__ void ln_split_kernel(const float* __restrict__ x, const float* __restrict__ g,
                                const float* __restrict__ b,
                                __nv_bfloat16* __restrict__ yhi,
                                __nv_bfloat16* __restrict__ ylo)
{
    const int row = blockIdx.x;
    const int tid = threadIdx.x;
    float4 v = ((const float4*)(x + (size_t)row * kD))[tid];
    float s  = v.x + v.y + v.z + v.w;
    float sq = v.x*v.x + v.y*v.y + v.z*v.z + v.w*v.w;
#pragma unroll
    for (int o = 16; o; o >>= 1) {
        s  += __shfl_xor_sync(0xffffffffu, s,  o);
        sq += __shfl_xor_sync(0xffffffffu, sq, o);
    }
    __shared__ float ss[8], ssq[8];
    const int w = tid >> 5, lane = tid & 31;
    if (lane == 0) { ss[w] = s; ssq[w] = sq; }
    __syncthreads();
    if (w == 0) {
        float a = (lane < 8) ? ss[lane]  : 0.f;
        float c = (lane < 8) ? ssq[lane] : 0.f;
#pragma unroll
        for (int o = 4; o; o >>= 1) {
            a += __shfl_xor_sync(0xffffffffu, a, o);
            c += __shfl_xor_sync(0xffffffffu, c, o);
        }
        if (lane == 0) { ss[0] = a; ssq[0] = c; }
    }
    __syncthreads();
    const float mean = ss[0] * (1.f / kD);
    const float var  = ssq[0] * (1.f / kD) - mean * mean;
    const float rstd = rsqrtf(var + 1e-5f);
    float4 gv = ((const float4*)g)[tid];
    float4 bv = ((const float4*)b)[tid];
    float y0 = (v.x - mean) * rstd * gv.x + bv.x;
    float y1 = (v.y - mean) * rstd * gv.y + bv.y;
    float y2 = (v.z - mean) * rstd * gv.z + bv.z;
    float y3 = (v.w - mean) * rstd * gv.w + bv.w;
    __nv_bfloat16 h0, h1, h2, h3, l0, l1, l2, l3;
    split1(y0, h0, l0); split1(y1, h1, l1);
    split1(y2, h2, l2); split1(y3, h3, l3);
    __nv_bfloat162 hp0; hp0.x = h0; hp0.y = h1;
    __nv_bfloat162 hp1; hp1.x = h2; hp1.y = h3;
    __nv_bfloat162 lp0; lp0.x = l0; lp0.y = l1;
    __nv_bfloat162 lp1; lp1.x = l2; lp1.y = l3;
    ((__nv_bfloat162*)(yhi + (size_t)row * kD))[tid * 2 + 0] = hp0;
    ((__nv_bfloat162*)(yhi + (size_t)row * kD))[tid * 2 + 1] = hp1;
    ((__nv_bfloat162*)(ylo + (size_t)row * kD))[tid * 2 + 0] = lp0;
    ((__nv_bfloat162*)(ylo + (size_t)row * kD))[tid * 2 + 1] = lp1;
}

// ---------------------------------------------------------------------------
// LoRA rank-4 down-projection from bf16-hi input
// ---------------------------------------------------------------------------
__global__ void lora_t_kernel(const __nv_bfloat16* __restrict__ h,
                              const float* __restrict__ la, float* __restrict__ t)
{
    const int row = blockIdx.x, tid = threadIdx.x;
    const __nv_bfloat162* hp = (const __nv_bfloat162*)(h + (size_t)row * kD);
    __nv_bfloat162 a0 = hp[tid * 2], a1 = hp[tid * 2 + 1];
    const float h0 = __bfloat162float(a0.x), h1 = __bfloat162float(a0.y);
    const float h2 = __bfloat162float(a1.x), h3 = __bfloat162float(a1.y);
    float acc[4];
#pragma unroll
    for (int r = 0; r < 4; r++) {
        float4 av = ((const float4*)(la + r * kD))[tid];
        acc[r] = h0*av.x + h1*av.y + h2*av.z + h3*av.w;
    }
#pragma unroll
    for (int o = 16; o; o >>= 1)
#pragma unroll
        for (int r = 0; r < 4; r++)
            acc[r] += __shfl_xor_sync(0xffffffffu, acc[r], o);
    __shared__ float sm[8][4];
    const int w = tid >> 5, lane = tid & 31;
    if (lane == 0) { sm[w][0]=acc[0]; sm[w][1]=acc[1]; sm[w][2]=acc[2]; sm[w][3]=acc[3]; }
    __syncthreads();
    if (tid < 4) {
        float s = 0.f;
#pragma unroll
        for (int w2 = 0; w2 < 8; w2++) s += sm[w2][tid];
        t[row * 4 + tid] = s;
    }
}

// ---------------------------------------------------------------------------
// Tensor-core flash attention (split-bf16 3-term for QK^T and PV).
// Block: 128 q-rows of one (b,h); 8 warps, each 16 q-rows x 64 keys.
// smem: Q hi/lo (128x64, 144B rows), 2-stage K/V hi/lo (64x64).
// ---------------------------------------------------------------------------
namespace {
constexpr uint32_t aQH  = 0;
constexpr uint32_t aQL  = 18432;           // 128*144
constexpr uint32_t aKV0 = 36864;           // + stage*36864; Kh,Kl,Vh,Vl @ +9216 each
constexpr uint32_t aSMEM = 36864 + 2 * 36864;  // 110592
}

__global__ void __launch_bounds__(256)
attn_mma(const __nv_bfloat16* __restrict__ Qhi, const __nv_bfloat16* __restrict__ Qlo,
         const __nv_bfloat16* __restrict__ Khi, const __nv_bfloat16* __restrict__ Klo,
         const __nv_bfloat16* __restrict__ Vhi, const __nv_bfloat16* __restrict__ Vlo,
         __nv_bfloat16* __restrict__ Ohi, __nv_bfloat16* __restrict__ Olo)
{
    extern __shared__ char smem[];
    const uint32_t sb = smem_u32(smem);
    const int tid  = threadIdx.x;
    const int lane = tid & 31;
    const int wid  = tid >> 5;           // 0..7
    const int qt = blockIdx.x;           // 0..7
    const int bh = blockIdx.y;
    const int b  = bh >> 4, h = bh & 15;
    const size_t rowbase = (size_t)b * kS;
    const int cb = h * 64;
    const int warp_m = wid * 16;

    // ---- load Q tile (scaled by 1/sqrt(hd)=0.125, exact pow2 on bf16)
    {
        const __nv_bfloat162 sc = __float2bfloat162_rn(0.125f);
#pragma unroll
        for (int i = tid; i < 1024; i += 256) {
            const int r = i >> 3, c = i & 7;
            const size_t go = (rowbase + qt * 128 + r) * kD + cb + c * 8;
            const uint32_t so = (uint32_t)(r * 144 + c * 16);
            uint4 vh = *(const uint4*)(Qhi + go);
            uint4 vl = *(const uint4*)(Qlo + go);
            __nv_bfloat162* ph = (__nv_bfloat162*)&vh;
            __nv_bfloat162* pl = (__nv_bfloat162*)&vl;
#pragma unroll
            for (int k = 0; k < 4; k++) { ph[k] = __hmul2(ph[k], sc); pl[k] = __hmul2(pl[k], sc); }
            st_shared_v4(sb + aQH + so, vh);
            st_shared_v4(sb + aQL + so, vl);
        }
    }

    auto load_kv = [&](int kt, int s) {
        const uint32_t st = sb + aKV0 + (uint32_t)s * 36864u;
#pragma unroll
        for (int i = tid; i < 512; i += 256) {
            const int r = i >> 3, c = i & 7;
            const size_t go = (rowbase + kt * 64 + r) * kD + cb + c * 8;
            const uint32_t so = (uint32_t)(r * 144 + c * 16);
            CP_ASYNC16(st +          so, Khi + go);
            CP_ASYNC16(st +  9216u + so, Klo + go);
            CP_ASYNC16(st + 18432u + so, Vhi + go);
            CP_ASYNC16(st + 27648u + so, Vlo + go);
        }
        CP_COMMIT();
    };
    load_kv(0, 0);
    __syncthreads();   // Q smem visible to all warps

    // ---- Q fragments (resident all kernel): warp rows [warp_m, warp_m+16)
    uint32_t qh[4][4], ql[4][4];
    {
        const uint32_t qa = sb + (uint32_t)((warp_m + (lane & 15)) * 144 + (lane >> 4) * 16);
#pragma unroll
        for (int kk = 0; kk < 4; kk++) {
            LDSM_X4(qh[kk][0], qh[kk][1], qh[kk][2], qh[kk][3], qa + aQH + kk * 32);
            LDSM_X4(ql[kk][0], ql[kk][1], ql[kk][2], ql[kk][3], qa + aQL + kk * 32);
        }
    }

    float m0 = -1e30f, m1 = -1e30f, l0 = 0.f, l1 = 0.f;
    float o[8][4];
#pragma unroll
    for (int j = 0; j < 8; j++)
#pragma unroll
        for (int c = 0; c < 4; c++) o[j][c] = 0.f;

    const uint32_t kboff = (uint32_t)(((lane & 7) + ((lane >> 4) & 1) * 8) * 144
                                      + ((lane >> 3) & 1) * 16);
    const uint32_t vaoff = (uint32_t)((lane & 15) * 144 + (lane >> 4) * 16);

    for (int kt = 0; kt < 16; kt++) {
        asm volatile("cp.async.wait_group 0;" ::: "memory");
        __syncthreads();
        if (kt + 1 < 16) load_kv(kt + 1, (kt + 1) & 1);
        const uint32_t st = sb + aKV0 + (uint32_t)(kt & 1) * 36864u;

        // ---- S = Q K^T (K tile is [keys][hd] = B's native [n][k] layout)
        float s[8][4];
#pragma unroll
        for (int j = 0; j < 8; j++)
#pragma unroll
            for (int c = 0; c < 4; c++) s[j][c] = 0.f;

#pragma unroll
        for (int kk = 0; kk < 4; kk++) {
            uint32_t bh_[8][2], bl_[8][2];
#pragma unroll
            for (int p = 0; p < 4; p++) {
                LDSM_X4(bh_[2*p][0], bh_[2*p][1], bh_[2*p+1][0], bh_[2*p+1][1],
                        st + kboff + (uint32_t)p * (16 * 144) + kk * 32);
                LDSM_X4(bl_[2*p][0], bl_[2*p][1], bl_[2*p+1][0], bl_[2*p+1][1],
                        st + 9216u + kboff + (uint32_t)p * (16 * 144) + kk * 32);
            }
#pragma unroll
            for (int j = 0; j < 8; j++) MMA16816(s[j], qh[kk], bh_[j]);
#pragma unroll
            for (int j = 0; j < 8; j++) MMA16816(s[j], qh[kk], bl_[j]);
#pragma unroll
            for (int j = 0; j < 8; j++) MMA16816(s[j], ql[kk], bh_[j]);
        }

        // ---- online softmax (rows r=lane>>2 and r+8; quad lanes share a row)
        float mx0 = m0, mx1 = m1;
#pragma unroll
        for (int j = 0; j < 8; j++) {
            mx0 = fmaxf(mx0, fmaxf(s[j][0], s[j][1]));
            mx1 = fmaxf(mx1, fmaxf(s[j][2], s[j][3]));
        }
        mx0 = fmaxf(mx0, __shfl_xor_sync(0xffffffffu, mx0, 1));
        mx0 = fmaxf(mx0, __shfl_xor_sync(0xffffffffu, mx0, 2));
        mx1 = fmaxf(mx1, __shfl_xor_sync(0xffffffffu, mx1, 1));
        mx1 = fmaxf(mx1, __shfl_xor_sync(0xffffffffu, mx1, 2));
        const float fac0 = __expf(m0 - mx0);
        const float fac1 = __expf(m1 - mx1);
        float sum0 = 0.f, sum1 = 0.f;
#pragma unroll
        for (int j = 0; j < 8; j++) {
            s[j][0] = __expf(s[j][0] - mx0);
            s[j][1] = __expf(s[j][1] - mx0);
            s[j][2] = __expf(s[j][2] - mx1);
            s[j][3] = __expf(s[j][3] - mx1);
            sum0 += s[j][0] + s[j][1];
            sum1 += s[j][2] + s[j][3];
        }
        sum0 += __shfl_xor_sync(0xffffffffu, sum0, 1);
        sum0 += __shfl_xor_sync(0xffffffffu, sum0, 2);
        sum1 += __shfl_xor_sync(0xffffffffu, sum1, 1);
        sum1 += __shfl_xor_sync(0xffffffffu, sum1, 2);
        l0 = l0 * fac0 + sum0;
        l1 = l1 * fac1 + sum1;
        m0 = mx0; m1 = mx1;
#pragma unroll
        for (int j = 0; j < 8; j++) {
            o[j][0] *= fac0; o[j][1] *= fac0;
            o[j][2] *= fac1; o[j][3] *= fac1;
        }

        // ---- O += P V  (P A-frags built straight from S registers; V via ldmatrix.trans)
#pragma unroll
        for (int kk = 0; kk < 4; kk++) {
            uint32_t vh_[8][2], vl_[8][2];
#pragma unroll
            for (int nn = 0; nn < 4; nn++) {
                LDSM_X4T(vh_[2*nn][0], vh_[2*nn][1], vh_[2*nn+1][0], vh_[2*nn+1][1],
                         st + 18432u + vaoff + (uint32_t)kk * (16 * 144) + nn * 32);
                LDSM_X4T(vl_[2*nn][0], vl_[2*nn][1], vl_[2*nn+1][0], vl_[2*nn+1][1],
                         st + 27648u + vaoff + (uint32_t)kk * (16 * 144) + nn * 32);
            }
            const int j0 = 2 * kk, j1 = 2 * kk + 1;
            uint32_t ph[4], pl[4];
            ph[0] = pack_bf16x2(s[j0][0], s[j0][1]);
            ph[1] = pack_bf16x2(s[j0][2], s[j0][3]);
            ph[2] = pack_bf16x2(s[j1][0], s[j1][1]);
            ph[3] = pack_bf16x2(s[j1][2], s[j1][3]);
            {
                const float r00 = s[j0][0] - __bfloat162float(__float2bfloat16(s[j0][0]));
                const float r01 = s[j0][1] - __bfloat162float(__float2bfloat16(s[j0][1]));
                const float r02 = s[j0][2] - __bfloat162float(__float2bfloat16(s[j0][2]));
                const float r03 = s[j0][3] - __bfloat162float(__float2bfloat16(s[j0][3]));
                const float r10 = s[j1][0] - __bfloat162float(__float2bfloat16(s[j1][0]));
                const float r11 = s[j1][1] - __bfloat162float(__float2bfloat16(s[j1][1]));
                const float r12 = s[j1][2] - __bfloat162float(__float2bfloat16(s[j1][2]));
                const float r13 = s[j1][3] - __bfloat162float(__float2bfloat16(s[j1][3]));
                pl[0] = pack_bf16x2(r00, r01);
                pl[1] = pack_bf16x2(r02, r03);
                pl[2] = pack_bf16x2(r10, r11);
                pl[3] = pack_bf16x2(r12, r13);
            }
#pragma unroll
            for (int j = 0; j < 8; j++) MMA16816(o[j], ph, vh_[j]);
#pragma unroll
            for (int j = 0; j < 8; j++) MMA16816(o[j], ph, vl_[j]);
#pragma unroll
            for (int j = 0; j < 8; j++) MMA16816(o[j], pl, vh_[j]);
        }
    }

    // ---- epilogue: normalize + split-write wv
    const float inv0 = 1.f / l0, inv1 = 1.f / l1;
    const int g = lane >> 2, t4 = lane & 3;
    const size_t row0 = rowbase + qt * 128 + warp_m + g;
#pragma unroll
    for (int j = 0; j < 8; j++) {
        const int col = cb + 8 * j + 2 * t4;
        const float v0 = o[j][0] * inv0, v1 = o[j][1] * inv0;
        const float v2 = o[j][2] * inv1, v3 = o[j][3] * inv1;
        __nv_bfloat16 h0, h1, h2, h3, l0b, l1b, l2b, l3b;
        split1(v0, h0, l0b); split1(v1, h1, l1b);
        split1(v2, h2, l2b); split1(v3, h3, l3b);
        __nv_bfloat162 hp0; hp0.x = h0; hp0.y = h1;
        __nv_bfloat162 hp1; hp1.x = h2; hp1.y = h3;
        __nv_bfloat162 lp0; lp0.x = l0b; lp0.y = l1b;
        __nv_bfloat162 lp1; lp1.x = l2b; lp1.y = l3b;
        *(__nv_bfloat162*)(Ohi + row0 * kD + col)       = hp0;
        *(__nv_bfloat162*)(Olo + row0 * kD + col)       = lp0;
        *(__nv_bfloat162*)(Ohi + (row0 + 8) * kD + col) = hp1;
        *(__nv_bfloat162*)(Olo + (row0 + 8) * kD + col) = lp1;
    }
}

// ---------------------------------------------------------------------------
// Host launcher
// ---------------------------------------------------------------------------
extern "C" void kernel_launch(void* const* d_in, const int* in_sizes, int n_in,
                              void* d_out, int out_size)
{
    (void)in_sizes; (void)n_in; (void)out_size;
    const float* x    = (const float*)d_in[0];
    const float* Wq   = (const float*)d_in[1];
    const float* bq   = (const float*)d_in[2];
    const float* Wk   = (const float*)d_in[3];
    const float* Wv   = (const float*)d_in[4];
    const float* bv   = (const float*)d_in[5];
    const float* Wo   = (const float*)d_in[6];
    const float* bo   = (const float*)d_in[7];
    const float* la_k = (const float*)d_in[8];
    const float* lb_k = (const float*)d_in[9];
    const float* la_v = (const float*)d_in[10];
    const float* lb_v = (const float*)d_in[11];
    const float* la_o = (const float*)d_in[12];
    const float* lb_o = (const float*)d_in[13];
    const float* ga   = (const float*)d_in[14];
    const float* ba   = (const float*)d_in[15];
    const float* W1   = (const float*)d_in[16];
    const float* b1   = (const float*)d_in[17];
    const float* W2   = (const float*)d_in[18];
    const float* b2   = (const float*)d_in[19];
    const float* gm   = (const float*)d_in[20];
    const float* bmn  = (const float*)d_in[21];
    float* out = (float*)d_out;

    static float *p_x1 = nullptr, *p_u, *p_t;
    static __nv_bfloat16 *pa_hi, *pa_lo, *pw_hi, *pw_lo, *pu_hi, *pu_lo;
    static __nv_bfloat16 *pq_hi, *pq_lo, *pk_hi, *pk_lo, *pv_hi, *pv_lo;
    if (!p_x1) {
        float* tmp;
        cudaGetSymbolAddress((void**)&tmp, g_q);
        pq_hi = (__nv_bfloat16*)tmp; pq_lo = pq_hi + (size_t)kM * kD;
        cudaGetSymbolAddress((void**)&tmp, g_k);
        pk_hi = (__nv_bfloat16*)tmp; pk_lo = pk_hi + (size_t)kM * kD;
        cudaGetSymbolAddress((void**)&tmp, g_v);
        pv_hi = (__nv_bfloat16*)tmp; pv_lo = pv_hi + (size_t)kM * kD;
        cudaGetSymbolAddress((void**)&p_u,   g_u);
        pu_hi = (__nv_bfloat16*)p_u; pu_lo = pu_hi + (size_t)kM * kDff;
        cudaGetSymbolAddress((void**)&p_t,   g_t);
        cudaGetSymbolAddress((void**)&pa_hi, g_a_hi);
        cudaGetSymbolAddress((void**)&pa_lo, g_a_lo);
        cudaGetSymbolAddress((void**)&pw_hi, g_w_hi);
        cudaGetSymbolAddress((void**)&pw_lo, g_w_lo);
        cudaFuncSetAttribute(attn_mma,
                             cudaFuncAttributeMaxDynamicSharedMemorySize, aSMEM);
        cudaFuncSetAttribute(gemm_mma<0, 0>,
                             cudaFuncAttributeMaxDynamicSharedMemorySize, 3 * kStage);
        cudaFuncSetAttribute(gemm_mma<0, 1>,
                             cudaFuncAttributeMaxDynamicSharedMemorySize, 3 * kStage);
        cudaFuncSetAttribute(gemm_mma<1, 1>,
                             cudaFuncAttributeMaxDynamicSharedMemorySize, 3 * kStage);
        cudaGetSymbolAddress((void**)&p_x1,  g_x1);   // init flag last
    }

    const dim3 blk(256);
    const dim3 gD(kD / 128, kM / 128);      // (8, 64)
    const dim3 gF(kDff / 128, kM / 128);    // (32, 64)
    const int nWDD  = kD * kD / 4;
    const int nWDF  = kDff * kD / 4;
    const unsigned SMEM_G = 3 * kStage;     // 122880 B

    // ---- attention half ----
    ln_split_kernel<<<kM, blk>>>(x, ga, ba, pa_hi, pa_lo);

    split_kernel<<<nWDD / 256, blk>>>(Wq, pw_hi, pw_lo, nWDD);
    gemm_mma<0, 1><<<gD, blk, SMEM_G>>>(pa_hi, pa_lo, pw_hi, pw_lo,
                                        bq, nullptr, nullptr, nullptr,
                                        nullptr, pq_hi, pq_lo, kM, kD, kD);

    split_kernel<<<nWDD / 256, blk>>>(Wk, pw_hi, pw_lo, nWDD);
    lora_t_kernel<<<kM, blk>>>(pa_hi, la_k, p_t);
    gemm_mma<0, 1><<<gD, blk, SMEM_G>>>(pa_hi, pa_lo, pw_hi, pw_lo,
                                        nullptr, nullptr, p_t, lb_k,
                                        nullptr, pk_hi, pk_lo, kM, kD, kD);

    split_kernel<<<nWDD / 256, blk>>>(Wv, pw_hi, pw_lo, nWDD);
    lora_t_kernel<<<kM, blk>>>(pa_hi, la_v, p_t);
    gemm_mma<0, 1><<<gD, blk, SMEM_G>>>(pa_hi, pa_lo, pw_hi, pw_lo,
                                        bv, nullptr, p_t, lb_v,
                                        nullptr, pv_hi, pv_lo, kM, kD, kD);

    // tensor-core flash attention; writes wv split into pa_hi/pa_lo
    attn_mma<<<dim3(8, kB * kH), blk, aSMEM>>>(pq_hi, pq_lo, pk_hi, pk_lo,
                                               pv_hi, pv_lo, pa_hi, pa_lo);

    lora_t_kernel<<<kM, blk>>>(pa_hi, la_o, p_t);
    split_kernel<<<nWDD / 256, blk>>>(Wo, pw_hi, pw_lo, nWDD);
    gemm_mma<0, 0><<<gD, blk, SMEM_G>>>(pa_hi, pa_lo, pw_hi, pw_lo,
                                        bo, x, p_t, lb_o,
                                        p_x1, nullptr, nullptr, kM, kD, kD);

    // ---- MLP half ----
    ln_split_kernel<<<kM, blk>>>(p_x1, gm, bmn, pa_hi, pa_lo);
    split_kernel<<<nWDF / 256, blk>>>(W1, pw_hi, pw_lo, nWDF);
    gemm_mma<1, 1><<<gF, blk, SMEM_G>>>(pa_hi, pa_lo, pw_hi, pw_lo,
                                        b1, nullptr, nullptr, nullptr,
                                        nullptr, pu_hi, pu_lo, kM, kDff, kD);

    split_kernel<<<nWDF / 256, blk>>>(W2, pw_hi, pw_lo, nWDF);
    gemm_mma<0, 0><<<gD, blk, SMEM_G>>>(pu_hi, pu_lo, pw_hi, pw_lo,
                                        b2, p_x1, nullptr, nullptr,
                                        out, nullptr, nullptr, kM, kD, kDff);
}

// round 8
// speedup vs baseline: 2.8407x; 1.0883x over previous
#include <cuda_runtime.h>
#include <cuda_bf16.h>
#include <cstdint>
#include <math.h>

// ---------------------------------------------------------------------------
// Shapes (fixed by the problem)
// ---------------------------------------------------------------------------
namespace {
constexpr int kD   = 1024;
constexpr int kDff = 4096;
constexpr int kB   = 8;
constexpr int kS   = 1024;
constexpr int kM   = kB * kS;   // 8192 rows
constexpr int kH   = 16;        // heads
}

// ---------------------------------------------------------------------------
// Scratch (static device globals -- no allocation allowed)
// ---------------------------------------------------------------------------
__device__ float g_q [(size_t)kM * kD];     // reused: bf16 q_hi / q_lo
__device__ float g_k [(size_t)kM * kD];     // reused: bf16 k_hi / k_lo
__device__ float g_v [(size_t)kM * kD];     // reused: bf16 v_hi / v_lo
__device__ float g_x1[(size_t)kM * kD];
__device__ float g_u [(size_t)kM * kDff];   // reused: bf16 u_hi / u_lo
__device__ float g_t [kM * 4];
__device__ __nv_bfloat16 g_a_hi[(size_t)kM * kD];
__device__ __nv_bfloat16 g_a_lo[(size_t)kM * kD];
__device__ __nv_bfloat16 g_w_hi[(size_t)kDff * kD];
__device__ __nv_bfloat16 g_w_lo[(size_t)kDff * kD];

// ---------------------------------------------------------------------------
// PTX helpers (portable sm_80+: cp.async / ldmatrix / mma.sync)
// ---------------------------------------------------------------------------
__device__ __forceinline__ uint32_t smem_u32(const void* p) {
    uint32_t a;
    asm("{ .reg .u64 t; cvta.to.shared.u64 t, %1; cvt.u32.u64 %0, t; }"
        : "=r"(a) : "l"(p));
    return a;
}

#define CP_ASYNC16(saddr, gptr) \
    asm volatile("cp.async.cg.shared.global [%0], [%1], 16;" \
        :: "r"(saddr), "l"(gptr))

#define CP_COMMIT() asm volatile("cp.async.commit_group;" ::: "memory")

#define LDSM_X4(r0, r1, r2, r3, addr) \
    asm volatile("ldmatrix.sync.aligned.m8n8.x4.shared.b16 {%0,%1,%2,%3}, [%4];" \
        : "=r"(r0), "=r"(r1), "=r"(r2), "=r"(r3) : "r"(addr))

#define LDSM_X4T(r0, r1, r2, r3, addr) \
    asm volatile("ldmatrix.sync.aligned.m8n8.x4.trans.shared.b16 {%0,%1,%2,%3}, [%4];" \
        : "=r"(r0), "=r"(r1), "=r"(r2), "=r"(r3) : "r"(addr))

#define MMA16816(d, a, b) \
    asm volatile("mma.sync.aligned.m16n8k16.row.col.f32.bf16.bf16.f32 " \
        "{%0,%1,%2,%3}, {%4,%5,%6,%7}, {%8,%9}, {%0,%1,%2,%3};" \
        : "+f"((d)[0]), "+f"((d)[1]), "+f"((d)[2]), "+f"((d)[3]) \
        : "r"((a)[0]), "r"((a)[1]), "r"((a)[2]), "r"((a)[3]), \
          "r"((b)[0]), "r"((b)[1]))

__device__ __forceinline__ void split1(float v, __nv_bfloat16& h, __nv_bfloat16& l) {
    h = __float2bfloat16(v);
    l = __float2bfloat16(v - __bfloat162float(h));
}

__device__ __forceinline__ uint32_t pack_bf16x2(float a, float b) {
    __nv_bfloat162 t = __floats2bfloat162_rn(a, b);   // .x = a (low half)
    return *(uint32_t*)&t;
}

__device__ __forceinline__ void st_shared_v4(uint32_t addr, uint4 v) {
    asm volatile("st.shared.v4.b32 [%0], {%1, %2, %3, %4};"
        :: "r"(addr), "r"(v.x), "r"(v.y), "r"(v.z), "r"(v.w));
}

// ---------------------------------------------------------------------------
// fp32 -> (bf16 hi, bf16 lo) split (weights)
// ---------------------------------------------------------------------------
__global__ void split_kernel(const float* __restrict__ x, __nv_bfloat16* __restrict__ hi,
                             __nv_bfloat16* __restrict__ lo, int n4)
{
    const int i = blockIdx.x * 256 + threadIdx.x;
    if (i >= n4) return;
    float4 v = ((const float4*)x)[i];
    __nv_bfloat16 h0, h1, h2, h3, l0, l1, l2, l3;
    split1(v.x, h0, l0); split1(v.y, h1, l1);
    split1(v.z, h2, l2); split1(v.w, h3, l3);
    __nv_bfloat162 hp0; hp0.x = h0; hp0.y = h1;
    __nv_bfloat162 hp1; hp1.x = h2; hp1.y = h3;
    __nv_bfloat162 lp0; lp0.x = l0; lp0.y = l1;
    __nv_bfloat162 lp1; lp1.x = l2; lp1.y = l3;
    ((__nv_bfloat162*)hi)[i * 2 + 0] = hp0;
    ((__nv_bfloat162*)hi)[i * 2 + 1] = hp1;
    ((__nv_bfloat162*)lo)[i * 2 + 0] = lp0;
    ((__nv_bfloat162*)lo)[i * 2 + 1] = lp1;
}

// ---------------------------------------------------------------------------
// Tensor-core GEMM (mma.sync bf16, split hi/lo 3-term):
//   C = A @ B^T (+bias) (+0.25 * lt @ lb^T) (+GELU) (+res); SPLIT=1 -> bf16 hi/lo out
// CTA tile 256x128, warp tile 64x64 (8 warps = 4x2), BK=32,
// 3-stage cp.async ring. 80B smem row stride (ldmatrix conflict-free).
// ---------------------------------------------------------------------------
namespace {
constexpr int      kRowB   = 80;
constexpr uint32_t kTileA  = 256 * kRowB;   // 20480
constexpr uint32_t kTileB  = 128 * kRowB;   // 10240
constexpr uint32_t kStageG = 2 * kTileA + 2 * kTileB;  // 61440
constexpr uint32_t oAl = kTileA;            // 20480
constexpr uint32_t oBh = 2 * kTileA;        // 40960
constexpr uint32_t oBl = 2 * kTileA + kTileB;  // 51200
}

template <int GELU, int SPLIT>
__global__ void __launch_bounds__(256)
gemm_mma(const __nv_bfloat16* __restrict__ Ahi, const __nv_bfloat16* __restrict__ Alo,
         const __nv_bfloat16* __restrict__ Bhi, const __nv_bfloat16* __restrict__ Blo,
         const float* __restrict__ bias, const float* __restrict__ res,
         const float* __restrict__ lt, const float* __restrict__ lb,
         float* __restrict__ C,
         __nv_bfloat16* __restrict__ Chi, __nv_bfloat16* __restrict__ Clo,
         int M, int N, int K)
{
    extern __shared__ char smem[];
    const uint32_t sbase = smem_u32(smem);
    const int tid  = threadIdx.x;
    const int lane = tid & 31;
    const int wid  = tid >> 5;
    const int bm = blockIdx.y * 256;
    const int bn = blockIdx.x * 128;
    const int warp_m = (wid >> 1) * 64;    // 0,64,128,192
    const int warp_n = (wid & 1) * 64;     // 0,64

    const int r0  = tid >> 2;              // 0..63
    const int c8  = (tid & 3) * 8;
    const uint32_t so = (uint32_t)(r0 * kRowB + (tid & 3) * 16);

    float acc[4][8][4];
#pragma unroll
    for (int i = 0; i < 4; i++)
#pragma unroll
        for (int j = 0; j < 8; j++)
#pragma unroll
            for (int r = 0; r < 4; r++) acc[i][j][r] = 0.f;

    const uint32_t a_off = (uint32_t)((warp_m + (lane & 15)) * kRowB + (lane >> 4) * 16);
    const uint32_t b_off = (uint32_t)((warp_n + (lane & 7) + ((lane >> 4) & 1) * 8) * kRowB
                                      + ((lane >> 3) & 1) * 16);

    const int nIter = K >> 5;

    auto load_stage = [&](int it, int s) {
        const int k0 = it << 5;
        const uint32_t sbuf = sbase + (uint32_t)s * kStageG;
#pragma unroll
        for (int q = 0; q < 4; q++) {
            const size_t ga = (size_t)(bm + r0 + 64 * q) * K + k0 + c8;
            const uint32_t sq = so + (uint32_t)q * (64u * kRowB);
            CP_ASYNC16(sbuf +       sq, Ahi + ga);
            CP_ASYNC16(sbuf + oAl + sq, Alo + ga);
        }
#pragma unroll
        for (int q = 0; q < 2; q++) {
            const size_t gb = (size_t)(bn + r0 + 64 * q) * K + k0 + c8;
            const uint32_t sq = so + (uint32_t)q * (64u * kRowB);
            CP_ASYNC16(sbuf + oBh + sq, Bhi + gb);
            CP_ASYNC16(sbuf + oBl + sq, Blo + gb);
        }
        CP_COMMIT();
    };

    load_stage(0, 0);
    load_stage(1, 1);

    for (int it = 0; it < nIter; ++it) {
        if (it + 1 < nIter) {
            asm volatile("cp.async.wait_group 1;" ::: "memory");
        } else {
            asm volatile("cp.async.wait_group 0;" ::: "memory");
        }
        __syncthreads();
        if (it + 2 < nIter) load_stage(it + 2, (it + 2) % 3);

        const uint32_t sbuf = sbase + (uint32_t)(it % 3) * kStageG;
        const uint32_t abase = sbuf + a_off;
        const uint32_t bbase = sbuf + oBh + b_off;

#pragma unroll
        for (int ks = 0; ks < 2; ks++) {
            const uint32_t ko = (uint32_t)ks * 32;
            uint32_t ah[4][4], al[4][4], bb[8][2];
#pragma unroll
            for (int i = 0; i < 4; i++) {
                LDSM_X4(ah[i][0], ah[i][1], ah[i][2], ah[i][3],
                        abase + (uint32_t)i * (16 * kRowB) + ko);
            }
#pragma unroll
            for (int p = 0; p < 4; p++) {
                LDSM_X4(bb[2*p][0], bb[2*p][1], bb[2*p+1][0], bb[2*p+1][1],
                        bbase + (uint32_t)p * (16 * kRowB) + ko);
            }
#pragma unroll
            for (int i = 0; i < 4; i++) {
                LDSM_X4(al[i][0], al[i][1], al[i][2], al[i][3],
                        abase + oAl + (uint32_t)i * (16 * kRowB) + ko);
            }
            // term 1: Ahi * Bhi
#pragma unroll
            for (int i = 0; i < 4; i++)
#pragma unroll
                for (int j = 0; j < 8; j++)
                    MMA16816(acc[i][j], ah[i], bb[j]);
            // term 3: Alo * Bhi
#pragma unroll
            for (int i = 0; i < 4; i++)
#pragma unroll
                for (int j = 0; j < 8; j++)
                    MMA16816(acc[i][j], al[i], bb[j]);
            // reload bb <- Blo (reuses registers)
#pragma unroll
            for (int p = 0; p < 4; p++) {
                LDSM_X4(bb[2*p][0], bb[2*p][1], bb[2*p+1][0], bb[2*p+1][1],
                        bbase + (kTileB) + (uint32_t)p * (16 * kRowB) + ko);
            }
            // term 2: Ahi * Blo
#pragma unroll
            for (int i = 0; i < 4; i++)
#pragma unroll
                for (int j = 0; j < 8; j++)
                    MMA16816(acc[i][j], ah[i], bb[j]);
        }
        __syncthreads();
    }

    // ---- epilogue
    const int g  = lane >> 2;
    const int t4 = lane & 3;
#pragma unroll
    for (int i = 0; i < 4; i++) {
        const int mlo = bm + warp_m + 16 * i + g;
        const int mhi = mlo + 8;
        float4 ltl = make_float4(0.f, 0.f, 0.f, 0.f);
        float4 lth = ltl;
        if (lb) {
            ltl = *(const float4*)(lt + (size_t)mlo * 4);
            lth = *(const float4*)(lt + (size_t)mhi * 4);
        }
#pragma unroll
        for (int j = 0; j < 8; j++) {
            const int n0 = bn + warp_n + 8 * j + 2 * t4;
            float b0 = 0.f, b1 = 0.f;
            if (bias) { b0 = bias[n0]; b1 = bias[n0 + 1]; }
            float b2 = b0, b3 = b1;
            if (lb) {
                float4 q0 = *(const float4*)(lb + (size_t)n0 * 4);
                float4 q1 = *(const float4*)(lb + (size_t)(n0 + 1) * 4);
                b0 += 0.25f * (ltl.x*q0.x + ltl.y*q0.y + ltl.z*q0.z + ltl.w*q0.w);
                b1 += 0.25f * (ltl.x*q1.x + ltl.y*q1.y + ltl.z*q1.z + ltl.w*q1.w);
                b2 += 0.25f * (lth.x*q0.x + lth.y*q0.y + lth.z*q0.z + lth.w*q0.w);
                b3 += 0.25f * (lth.x*q1.x + lth.y*q1.y + lth.z*q1.z + lth.w*q1.w);
            }
            float v0 = acc[i][j][0] + b0;
            float v1 = acc[i][j][1] + b1;
            float v2 = acc[i][j][2] + b2;
            float v3 = acc[i][j][3] + b3;
            if (GELU) {
                v0 = 0.5f * v0 * (1.f + erff(v0 * 0.70710678118f));
                v1 = 0.5f * v1 * (1.f + erff(v1 * 0.70710678118f));
                v2 = 0.5f * v2 * (1.f + erff(v2 * 0.70710678118f));
                v3 = 0.5f * v3 * (1.f + erff(v3 * 0.70710678118f));
            }
            const size_t olo = (size_t)mlo * N + n0;
            const size_t ohi = (size_t)mhi * N + n0;
            if (SPLIT) {
                __nv_bfloat16 h0, h1, h2, h3, l0, l1, l2, l3;
                split1(v0, h0, l0); split1(v1, h1, l1);
                split1(v2, h2, l2); split1(v3, h3, l3);
                __nv_bfloat162 hp0; hp0.x = h0; hp0.y = h1;
                __nv_bfloat162 hp1; hp1.x = h2; hp1.y = h3;
                __nv_bfloat162 lp0; lp0.x = l0; lp0.y = l1;
                __nv_bfloat162 lp1; lp1.x = l2; lp1.y = l3;
                *(__nv_bfloat162*)(Chi + olo) = hp0;
                *(__nv_bfloat162*)(Chi + ohi) = hp1;
                *(__nv_bfloat162*)(Clo + olo) = lp0;
                *(__nv_bfloat162*)(Clo + ohi) = lp1;
            } else {
                if (res) {
                    float2 r0_ = *(const float2*)(res + olo);
                    float2 r1_ = *(const float2*)(res + ohi);
                    v0 += r0_.x; v1 += r0_.y; v2 += r1_.x; v3 += r1_.y;
                }
                *(float2*)(C + olo) = make_float2(v0, v1);
                *(float2*)(C + ohi) = make_float2(v2, v3);
            }
        }
    }
}

// ---------------------------------------------------------------------------
// LayerNorm -> split bf16 hi/lo directly
// ---------------------------------------------------------------------------
__global__ void ln_split_kernel(const float* __restrict__ x, const float* __restrict__ g,
                                const float* __restrict__ b,
                                __nv_bfloat16* __restrict__ yhi,
                                __nv_bfloat16* __restrict__ ylo)
{
    const int row = blockIdx.x;
    const int tid = threadIdx.x;
    float4 v = ((const float4*)(x + (size_t)row * kD))[tid];
    float s  = v.x + v.y + v.z + v.w;
    float sq = v.x*v.x + v.y*v.y + v.z*v.z + v.w*v.w;
#pragma unroll
    for (int o = 16; o; o >>= 1) {
        s  += __shfl_xor_sync(0xffffffffu, s,  o);
        sq += __shfl_xor_sync(0xffffffffu, sq, o);
    }
    __shared__ float ss[8], ssq[8];
    const int w = tid >> 5, lane = tid & 31;
    if (lane == 0) { ss[w] = s; ssq[w] = sq; }
    __syncthreads();
    if (w == 0) {
        float a = (lane < 8) ? ss[lane]  : 0.f;
        float c = (lane < 8) ? ssq[lane] : 0.f;
#pragma unroll
        for (int o = 4; o; o >>= 1) {
            a += __shfl_xor_sync(0xffffffffu, a, o);
            c += __shfl_xor_sync(0xffffffffu, c, o);
        }
        if (lane == 0) { ss[0] = a; ssq[0] = c; }
    }
    __syncthreads();
    const float mean = ss[0] * (1.f / kD);
    const float var  = ssq[0] * (1.f / kD) - mean * mean;
    const float rstd = rsqrtf(var + 1e-5f);
    float4 gv = ((const float4*)g)[tid];
    float4 bv = ((const float4*)b)[tid];
    float y0 = (v.x - mean) * rstd * gv.x + bv.x;
    float y1 = (v.y - mean) * rstd * gv.y + bv.y;
    float y2 = (v.z - mean) * rstd * gv.z + bv.z;
    float y3 = (v.w - mean) * rstd * gv.w + bv.w;
    __nv_bfloat16 h0, h1, h2, h3, l0, l1, l2, l3;
    split1(y0, h0, l0); split1(y1, h1, l1);
    split1(y2, h2, l2); split1(y3, h3, l3);
    __nv_bfloat162 hp0; hp0.x = h0; hp0.y = h1;
    __nv_bfloat162 hp1; hp1.x = h2; hp1.y = h3;
    __nv_bfloat162 lp0; lp0.x = l0; lp0.y = l1;
    __nv_bfloat162 lp1; lp1.x = l2; lp1.y = l3;
    ((__nv_bfloat162*)(yhi + (size_t)row * kD))[tid * 2 + 0] = hp0;
    ((__nv_bfloat162*)(yhi + (size_t)row * kD))[tid * 2 + 1] = hp1;
    ((__nv_bfloat162*)(ylo + (size_t)row * kD))[tid * 2 + 0] = lp0;
    ((__nv_bfloat162*)(ylo + (size_t)row * kD))[tid * 2 + 1] = lp1;
}

// ---------------------------------------------------------------------------
// LoRA rank-4 down-projection from bf16-hi input
// ---------------------------------------------------------------------------
__global__ void lora_t_kernel(const __nv_bfloat16* __restrict__ h,
                              const float* __restrict__ la, float* __restrict__ t)
{
    const int row = blockIdx.x, tid = threadIdx.x;
    const __nv_bfloat162* hp = (const __nv_bfloat162*)(h + (size_t)row * kD);
    __nv_bfloat162 a0 = hp[tid * 2], a1 = hp[tid * 2 + 1];
    const float h0 = __bfloat162float(a0.x), h1 = __bfloat162float(a0.y);
    const float h2 = __bfloat162float(a1.x), h3 = __bfloat162float(a1.y);
    float acc[4];
#pragma unroll
    for (int r = 0; r < 4; r++) {
        float4 av = ((const float4*)(la + r * kD))[tid];
        acc[r] = h0*av.x + h1*av.y + h2*av.z + h3*av.w;
    }
#pragma unroll
    for (int o = 16; o; o >>= 1)
#pragma unroll
        for (int r = 0; r < 4; r++)
            acc[r] += __shfl_xor_sync(0xffffffffu, acc[r], o);
    __shared__ float sm[8][4];
    const int w = tid >> 5, lane = tid & 31;
    if (lane == 0) { sm[w][0]=acc[0]; sm[w][1]=acc[1]; sm[w][2]=acc[2]; sm[w][3]=acc[3]; }
    __syncthreads();
    if (tid < 4) {
        float s = 0.f;
#pragma unroll
        for (int w2 = 0; w2 < 8; w2++) s += sm[w2][tid];
        t[row * 4 + tid] = s;
    }
}

// ---------------------------------------------------------------------------
// Tensor-core flash attention (split-bf16 3-term for QK^T and PV).
// Block: 128 q-rows of one (b,h); 8 warps, each 16 q-rows x 64 keys.
// ---------------------------------------------------------------------------
namespace {
constexpr uint32_t aQH  = 0;
constexpr uint32_t aQL  = 18432;           // 128*144
constexpr uint32_t aKV0 = 36864;           // + stage*36864; Kh,Kl,Vh,Vl @ +9216 each
constexpr uint32_t aSMEM = 36864 + 2 * 36864;  // 110592
}

__global__ void __launch_bounds__(256)
attn_mma(const __nv_bfloat16* __restrict__ Qhi, const __nv_bfloat16* __restrict__ Qlo,
         const __nv_bfloat16* __restrict__ Khi, const __nv_bfloat16* __restrict__ Klo,
         const __nv_bfloat16* __restrict__ Vhi, const __nv_bfloat16* __restrict__ Vlo,
         __nv_bfloat16* __restrict__ Ohi, __nv_bfloat16* __restrict__ Olo)
{
    extern __shared__ char smem[];
    const uint32_t sb = smem_u32(smem);
    const int tid  = threadIdx.x;
    const int lane = tid & 31;
    const int wid  = tid >> 5;           // 0..7
    const int qt = blockIdx.x;           // 0..7
    const int bh = blockIdx.y;
    const int b  = bh >> 4, h = bh & 15;
    const size_t rowbase = (size_t)b * kS;
    const int cb = h * 64;
    const int warp_m = wid * 16;

    {
        const __nv_bfloat162 sc = __float2bfloat162_rn(0.125f);
#pragma unroll
        for (int i = tid; i < 1024; i += 256) {
            const int r = i >> 3, c = i & 7;
            const size_t go = (rowbase + qt * 128 + r) * kD + cb + c * 8;
            const uint32_t so = (uint32_t)(r * 144 + c * 16);
            uint4 vh = *(const uint4*)(Qhi + go);
            uint4 vl = *(const uint4*)(Qlo + go);
            __nv_bfloat162* ph = (__nv_bfloat162*)&vh;
            __nv_bfloat162* pl = (__nv_bfloat162*)&vl;
#pragma unroll
            for (int k = 0; k < 4; k++) { ph[k] = __hmul2(ph[k], sc); pl[k] = __hmul2(pl[k], sc); }
            st_shared_v4(sb + aQH + so, vh);
            st_shared_v4(sb + aQL + so, vl);
        }
    }

    auto load_kv = [&](int kt, int s) {
        const uint32_t st = sb + aKV0 + (uint32_t)s * 36864u;
#pragma unroll
        for (int i = tid; i < 512; i += 256) {
            const int r = i >> 3, c = i & 7;
            const size_t go = (rowbase + kt * 64 + r) * kD + cb + c * 8;
            const uint32_t so = (uint32_t)(r * 144 + c * 16);
            CP_ASYNC16(st +          so, Khi + go);
            CP_ASYNC16(st +  9216u + so, Klo + go);
            CP_ASYNC16(st + 18432u + so, Vhi + go);
            CP_ASYNC16(st + 27648u + so, Vlo + go);
        }
        CP_COMMIT();
    };
    load_kv(0, 0);
    __syncthreads();

    uint32_t qh[4][4], ql[4][4];
    {
        const uint32_t qa = sb + (uint32_t)((warp_m + (lane & 15)) * 144 + (lane >> 4) * 16);
#pragma unroll
        for (int kk = 0; kk < 4; kk++) {
            LDSM_X4(qh[kk][0], qh[kk][1], qh[kk][2], qh[kk][3], qa + aQH + kk * 32);
            LDSM_X4(ql[kk][0], ql[kk][1], ql[kk][2], ql[kk][3], qa + aQL + kk * 32);
        }
    }

    float m0 = -1e30f, m1 = -1e30f, l0 = 0.f, l1 = 0.f;
    float o[8][4];
#pragma unroll
    for (int j = 0; j < 8; j++)
#pragma unroll
        for (int c = 0; c < 4; c++) o[j][c] = 0.f;

    const uint32_t kboff = (uint32_t)(((lane & 7) + ((lane >> 4) & 1) * 8) * 144
                                      + ((lane >> 3) & 1) * 16);
    const uint32_t vaoff = (uint32_t)((lane & 15) * 144 + (lane >> 4) * 16);

    for (int kt = 0; kt < 16; kt++) {
        asm volatile("cp.async.wait_group 0;" ::: "memory");
        __syncthreads();
        if (kt + 1 < 16) load_kv(kt + 1, (kt + 1) & 1);
        const uint32_t st = sb + aKV0 + (uint32_t)(kt & 1) * 36864u;

        float s[8][4];
#pragma unroll
        for (int j = 0; j < 8; j++)
#pragma unroll
            for (int c = 0; c < 4; c++) s[j][c] = 0.f;

#pragma unroll
        for (int kk = 0; kk < 4; kk++) {
            uint32_t bh_[8][2], bl_[8][2];
#pragma unroll
            for (int p = 0; p < 4; p++) {
                LDSM_X4(bh_[2*p][0], bh_[2*p][1], bh_[2*p+1][0], bh_[2*p+1][1],
                        st + kboff + (uint32_t)p * (16 * 144) + kk * 32);
                LDSM_X4(bl_[2*p][0], bl_[2*p][1], bl_[2*p+1][0], bl_[2*p+1][1],
                        st + 9216u + kboff + (uint32_t)p * (16 * 144) + kk * 32);
            }
#pragma unroll
            for (int j = 0; j < 8; j++) MMA16816(s[j], qh[kk], bh_[j]);
#pragma unroll
            for (int j = 0; j < 8; j++) MMA16816(s[j], qh[kk], bl_[j]);
#pragma unroll
            for (int j = 0; j < 8; j++) MMA16816(s[j], ql[kk], bh_[j]);
        }

        float mx0 = m0, mx1 = m1;
#pragma unroll
        for (int j = 0; j < 8; j++) {
            mx0 = fmaxf(mx0, fmaxf(s[j][0], s[j][1]));
            mx1 = fmaxf(mx1, fmaxf(s[j][2], s[j][3]));
        }
        mx0 = fmaxf(mx0, __shfl_xor_sync(0xffffffffu, mx0, 1));
        mx0 = fmaxf(mx0, __shfl_xor_sync(0xffffffffu, mx0, 2));
        mx1 = fmaxf(mx1, __shfl_xor_sync(0xffffffffu, mx1, 1));
        mx1 = fmaxf(mx1, __shfl_xor_sync(0xffffffffu, mx1, 2));
        const float fac0 = __expf(m0 - mx0);
        const float fac1 = __expf(m1 - mx1);
        float sum0 = 0.f, sum1 = 0.f;
#pragma unroll
        for (int j = 0; j < 8; j++) {
            s[j][0] = __expf(s[j][0] - mx0);
            s[j][1] = __expf(s[j][1] - mx0);
            s[j][2] = __expf(s[j][2] - mx1);
            s[j][3] = __expf(s[j][3] - mx1);
            sum0 += s[j][0] + s[j][1];
            sum1 += s[j][2] + s[j][3];
        }
        sum0 += __shfl_xor_sync(0xffffffffu, sum0, 1);
        sum0 += __shfl_xor_sync(0xffffffffu, sum0, 2);
        sum1 += __shfl_xor_sync(0xffffffffu, sum1, 1);
        sum1 += __shfl_xor_sync(0xffffffffu, sum1, 2);
        l0 = l0 * fac0 + sum0;
        l1 = l1 * fac1 + sum1;
        m0 = mx0; m1 = mx1;
#pragma unroll
        for (int j = 0; j < 8; j++) {
            o[j][0] *= fac0; o[j][1] *= fac0;
            o[j][2] *= fac1; o[j][3] *= fac1;
        }

#pragma unroll
        for (int kk = 0; kk < 4; kk++) {
            uint32_t vh_[8][2], vl_[8][2];
#pragma unroll
            for (int nn = 0; nn < 4; nn++) {
                LDSM_X4T(vh_[2*nn][0], vh_[2*nn][1], vh_[2*nn+1][0], vh_[2*nn+1][1],
                         st + 18432u + vaoff + (uint32_t)kk * (16 * 144) + nn * 32);
                LDSM_X4T(vl_[2*nn][0], vl_[2*nn][1], vl_[2*nn+1][0], vl_[2*nn+1][1],
                         st + 27648u + vaoff + (uint32_t)kk * (16 * 144) + nn * 32);
            }
            const int j0 = 2 * kk, j1 = 2 * kk + 1;
            uint32_t ph[4], pl[4];
            ph[0] = pack_bf16x2(s[j0][0], s[j0][1]);
            ph[1] = pack_bf16x2(s[j0][2], s[j0][3]);
            ph[2] = pack_bf16x2(s[j1][0], s[j1][1]);
            ph[3] = pack_bf16x2(s[j1][2], s[j1][3]);
            {
                const float r00 = s[j0][0] - __bfloat162float(__float2bfloat16(s[j0][0]));
                const float r01 = s[j0][1] - __bfloat162float(__float2bfloat16(s[j0][1]));
                const float r02 = s[j0][2] - __bfloat162float(__float2bfloat16(s[j0][2]));
                const float r03 = s[j0][3] - __bfloat162float(__float2bfloat16(s[j0][3]));
                const float r10 = s[j1][0] - __bfloat162float(__float2bfloat16(s[j1][0]));
                const float r11 = s[j1][1] - __bfloat162float(__float2bfloat16(s[j1][1]));
                const float r12 = s[j1][2] - __bfloat162float(__float2bfloat16(s[j1][2]));
                const float r13 = s[j1][3] - __bfloat162float(__float2bfloat16(s[j1][3]));
                pl[0] = pack_bf16x2(r00, r01);
                pl[1] = pack_bf16x2(r02, r03);
                pl[2] = pack_bf16x2(r10, r11);
                pl[3] = pack_bf16x2(r12, r13);
            }
#pragma unroll
            for (int j = 0; j < 8; j++) MMA16816(o[j], ph, vh_[j]);
#pragma unroll
            for (int j = 0; j < 8; j++) MMA16816(o[j], ph, vl_[j]);
#pragma unroll
            for (int j = 0; j < 8; j++) MMA16816(o[j], pl, vh_[j]);
        }
    }

    const float inv0 = 1.f / l0, inv1 = 1.f / l1;
    const int g = lane >> 2, t4 = lane & 3;
    const size_t row0 = rowbase + qt * 128 + warp_m + g;
#pragma unroll
    for (int j = 0; j < 8; j++) {
        const int col = cb + 8 * j + 2 * t4;
        const float v0 = o[j][0] * inv0, v1 = o[j][1] * inv0;
        const float v2 = o[j][2] * inv1, v3 = o[j][3] * inv1;
        __nv_bfloat16 h0, h1, h2, h3, l0b, l1b, l2b, l3b;
        split1(v0, h0, l0b); split1(v1, h1, l1b);
        split1(v2, h2, l2b); split1(v3, h3, l3b);
        __nv_bfloat162 hp0; hp0.x = h0; hp0.y = h1;
        __nv_bfloat162 hp1; hp1.x = h2; hp1.y = h3;
        __nv_bfloat162 lp0; lp0.x = l0b; lp0.y = l1b;
        __nv_bfloat162 lp1; lp1.x = l2b; lp1.y = l3b;
        *(__nv_bfloat162*)(Ohi + row0 * kD + col)       = hp0;
        *(__nv_bfloat162*)(Olo + row0 * kD + col)       = lp0;
        *(__nv_bfloat162*)(Ohi + (row0 + 8) * kD + col) = hp1;
        *(__nv_bfloat162*)(Olo + (row0 + 8) * kD + col) = lp1;
    }
}

// ---------------------------------------------------------------------------
// Host launcher
// ---------------------------------------------------------------------------
extern "C" void kernel_launch(void* const* d_in, const int* in_sizes, int n_in,
                              void* d_out, int out_size)
{
    (void)in_sizes; (void)n_in; (void)out_size;
    const float* x    = (const float*)d_in[0];
    const float* Wq   = (const float*)d_in[1];
    const float* bq   = (const float*)d_in[2];
    const float* Wk   = (const float*)d_in[3];
    const float* Wv   = (const float*)d_in[4];
    const float* bv   = (const float*)d_in[5];
    const float* Wo   = (const float*)d_in[6];
    const float* bo   = (const float*)d_in[7];
    const float* la_k = (const float*)d_in[8];
    const float* lb_k = (const float*)d_in[9];
    const float* la_v = (const float*)d_in[10];
    const float* lb_v = (const float*)d_in[11];
    const float* la_o = (const float*)d_in[12];
    const float* lb_o = (const float*)d_in[13];
    const float* ga   = (const float*)d_in[14];
    const float* ba   = (const float*)d_in[15];
    const float* W1   = (const float*)d_in[16];
    const float* b1   = (const float*)d_in[17];
    const float* W2   = (const float*)d_in[18];
    const float* b2   = (const float*)d_in[19];
    const float* gm   = (const float*)d_in[20];
    const float* bmn  = (const float*)d_in[21];
    float* out = (float*)d_out;

    static float *p_x1 = nullptr, *p_u, *p_t;
    static __nv_bfloat16 *pa_hi, *pa_lo, *pw_hi, *pw_lo, *pu_hi, *pu_lo;
    static __nv_bfloat16 *pq_hi, *pq_lo, *pk_hi, *pk_lo, *pv_hi, *pv_lo;
    if (!p_x1) {
        float* tmp;
        cudaGetSymbolAddress((void**)&tmp, g_q);
        pq_hi = (__nv_bfloat16*)tmp; pq_lo = pq_hi + (size_t)kM * kD;
        cudaGetSymbolAddress((void**)&tmp, g_k);
        pk_hi = (__nv_bfloat16*)tmp; pk_lo = pk_hi + (size_t)kM * kD;
        cudaGetSymbolAddress((void**)&tmp, g_v);
        pv_hi = (__nv_bfloat16*)tmp; pv_lo = pv_hi + (size_t)kM * kD;
        cudaGetSymbolAddress((void**)&p_u,   g_u);
        pu_hi = (__nv_bfloat16*)p_u; pu_lo = pu_hi + (size_t)kM * kDff;
        cudaGetSymbolAddress((void**)&p_t,   g_t);
        cudaGetSymbolAddress((void**)&pa_hi, g_a_hi);
        cudaGetSymbolAddress((void**)&pa_lo, g_a_lo);
        cudaGetSymbolAddress((void**)&pw_hi, g_w_hi);
        cudaGetSymbolAddress((void**)&pw_lo, g_w_lo);
        cudaFuncSetAttribute(attn_mma,
                             cudaFuncAttributeMaxDynamicSharedMemorySize, aSMEM);
        cudaFuncSetAttribute(gemm_mma<0, 0>,
                             cudaFuncAttributeMaxDynamicSharedMemorySize, 3 * kStageG);
        cudaFuncSetAttribute(gemm_mma<0, 1>,
                             cudaFuncAttributeMaxDynamicSharedMemorySize, 3 * kStageG);
        cudaFuncSetAttribute(gemm_mma<1, 1>,
                             cudaFuncAttributeMaxDynamicSharedMemorySize, 3 * kStageG);
        cudaGetSymbolAddress((void**)&p_x1,  g_x1);   // init flag last
    }

    const dim3 blk(256);
    const dim3 gD(kD / 128, kM / 256);      // (8, 32)
    const dim3 gF(kDff / 128, kM / 256);    // (32, 32)
    const int nWDD  = kD * kD / 4;
    const int nWDF  = kDff * kD / 4;
    const unsigned SMEM_G = 3 * kStageG;    // 184320 B

    // ---- attention half ----
    ln_split_kernel<<<kM, blk>>>(x, ga, ba, pa_hi, pa_lo);

    split_kernel<<<nWDD / 256, blk>>>(Wq, pw_hi, pw_lo, nWDD);
    gemm_mma<0, 1><<<gD, blk, SMEM_G>>>(pa_hi, pa_lo, pw_hi, pw_lo,
                                        bq, nullptr, nullptr, nullptr,
                                        nullptr, pq_hi, pq_lo, kM, kD, kD);

    split_kernel<<<nWDD / 256, blk>>>(Wk, pw_hi, pw_lo, nWDD);
    lora_t_kernel<<<kM, blk>>>(pa_hi, la_k, p_t);
    gemm_mma<0, 1><<<gD, blk, SMEM_G>>>(pa_hi, pa_lo, pw_hi, pw_lo,
                                        nullptr, nullptr, p_t, lb_k,
                                        nullptr, pk_hi, pk_lo, kM, kD, kD);

    split_kernel<<<nWDD / 256, blk>>>(Wv, pw_hi, pw_lo, nWDD);
    lora_t_kernel<<<kM, blk>>>(pa_hi, la_v, p_t);
    gemm_mma<0, 1><<<gD, blk, SMEM_G>>>(pa_hi, pa_lo, pw_hi, pw_lo,
                                        bv, nullptr, p_t, lb_v,
                                        nullptr, pv_hi, pv_lo, kM, kD, kD);

    attn_mma<<<dim3(8, kB * kH), blk, aSMEM>>>(pq_hi, pq_lo, pk_hi, pk_lo,
                                               pv_hi, pv_lo, pa_hi, pa_lo);

    lora_t_kernel<<<kM, blk>>>(pa_hi, la_o, p_t);
    split_kernel<<<nWDD / 256, blk>>>(Wo, pw_hi, pw_lo, nWDD);
    gemm_mma<0, 0><<<gD, blk, SMEM_G>>>(pa_hi, pa_lo, pw_hi, pw_lo,
                                        bo, x, p_t, lb_o,
                                        p_x1, nullptr, nullptr, kM, kD, kD);

    // ---- MLP half ----
    ln_split_kernel<<<kM, blk>>>(p_x1, gm, bmn, pa_hi, pa_lo);
    split_kernel<<<nWDF / 256, blk>>>(W1, pw_hi, pw_lo, nWDF);
    gemm_mma<1, 1><<<gF, blk, SMEM_G>>>(pa_hi, pa_lo, pw_hi, pw_lo,
                                        b1, nullptr, nullptr, nullptr,
                                        nullptr, pu_hi, pu_lo, kM, kDff, kD);

    split_kernel<<<nWDF / 256, blk>>>(W2, pw_hi, pw_lo, nWDF);
    gemm_mma<0, 0><<<gD, blk, SMEM_G>>>(pu_hi, pu_lo, pw_hi, pw_lo,
                                        b2, p_x1, nullptr, nullptr,
                                        out, nullptr, nullptr, kM, kD, kDff);
}

// round 9
// speedup vs baseline: 2.8936x; 1.0186x over previous
#include <cuda_runtime.h>
#include <cuda_bf16.h>
#include <cstdint>
#include <math.h>

// ---------------------------------------------------------------------------
// Shapes (fixed by the problem)
// ---------------------------------------------------------------------------
namespace {
constexpr int kD   = 1024;
constexpr int kDff = 4096;
constexpr int kB   = 8;
constexpr int kS   = 1024;
constexpr int kM   = kB * kS;   // 8192 rows
constexpr int kH   = 16;        // heads
}

// ---------------------------------------------------------------------------
// Scratch (static device globals -- no allocation allowed)
// ---------------------------------------------------------------------------
__device__ float g_q [(size_t)kM * kD];     // reused: bf16 q_hi / q_lo
__device__ float g_k [(size_t)kM * kD];     // reused: bf16 k_hi / k_lo
__device__ float g_v [(size_t)kM * kD];     // reused: bf16 v_hi / v_lo
__device__ float g_x1[(size_t)kM * kD];
__device__ float g_u [(size_t)kM * kDff];   // reused: bf16 u_hi / u_lo
__device__ __nv_bfloat16 g_a_hi[(size_t)kM * kD];
__device__ __nv_bfloat16 g_a_lo[(size_t)kM * kD];
__device__ __nv_bfloat16 g_w_hi[(size_t)kDff * kD];
__device__ __nv_bfloat16 g_w_lo[(size_t)kDff * kD];

// ---------------------------------------------------------------------------
// PTX helpers (portable sm_80+: cp.async / ldmatrix / mma.sync)
// ---------------------------------------------------------------------------
__device__ __forceinline__ uint32_t smem_u32(const void* p) {
    uint32_t a;
    asm("{ .reg .u64 t; cvta.to.shared.u64 t, %1; cvt.u32.u64 %0, t; }"
        : "=r"(a) : "l"(p));
    return a;
}

#define CP_ASYNC16(saddr, gptr) \
    asm volatile("cp.async.cg.shared.global [%0], [%1], 16;" \
        :: "r"(saddr), "l"(gptr))

#define CP_COMMIT() asm volatile("cp.async.commit_group;" ::: "memory")

#define LDSM_X4(r0, r1, r2, r3, addr) \
    asm volatile("ldmatrix.sync.aligned.m8n8.x4.shared.b16 {%0,%1,%2,%3}, [%4];" \
        : "=r"(r0), "=r"(r1), "=r"(r2), "=r"(r3) : "r"(addr))

#define LDSM_X4T(r0, r1, r2, r3, addr) \
    asm volatile("ldmatrix.sync.aligned.m8n8.x4.trans.shared.b16 {%0,%1,%2,%3}, [%4];" \
        : "=r"(r0), "=r"(r1), "=r"(r2), "=r"(r3) : "r"(addr))

#define MMA16816(d, a, b) \
    asm volatile("mma.sync.aligned.m16n8k16.row.col.f32.bf16.bf16.f32 " \
        "{%0,%1,%2,%3}, {%4,%5,%6,%7}, {%8,%9}, {%0,%1,%2,%3};" \
        : "+f"((d)[0]), "+f"((d)[1]), "+f"((d)[2]), "+f"((d)[3]) \
        : "r"((a)[0]), "r"((a)[1]), "r"((a)[2]), "r"((a)[3]), \
          "r"((b)[0]), "r"((b)[1]))

__device__ __forceinline__ void split1(float v, __nv_bfloat16& h, __nv_bfloat16& l) {
    h = __float2bfloat16(v);
    l = __float2bfloat16(v - __bfloat162float(h));
}

__device__ __forceinline__ uint32_t pack_bf16x2(float a, float b) {
    __nv_bfloat162 t = __floats2bfloat162_rn(a, b);   // .x = a (low half)
    return *(uint32_t*)&t;
}

__device__ __forceinline__ void st_shared_v4(uint32_t addr, uint4 v) {
    asm volatile("st.shared.v4.b32 [%0], {%1, %2, %3, %4};"
        :: "r"(addr), "r"(v.x), "r"(v.y), "r"(v.z), "r"(v.w));
}

// ---------------------------------------------------------------------------
// fp32 -> (bf16 hi, bf16 lo) split (plain weights / no LoRA)
// ---------------------------------------------------------------------------
__global__ void split_kernel(const float* __restrict__ x, __nv_bfloat16* __restrict__ hi,
                             __nv_bfloat16* __restrict__ lo, int n4)
{
    const int i = blockIdx.x * 256 + threadIdx.x;
    if (i >= n4) return;
    float4 v = ((const float4*)x)[i];
    __nv_bfloat16 h0, h1, h2, h3, l0, l1, l2, l3;
    split1(v.x, h0, l0); split1(v.y, h1, l1);
    split1(v.z, h2, l2); split1(v.w, h3, l3);
    __nv_bfloat162 hp0; hp0.x = h0; hp0.y = h1;
    __nv_bfloat162 hp1; hp1.x = h2; hp1.y = h3;
    __nv_bfloat162 lp0; lp0.x = l0; lp0.y = l1;
    __nv_bfloat162 lp1; lp1.x = l2; lp1.y = l3;
    ((__nv_bfloat162*)hi)[i * 2 + 0] = hp0;
    ((__nv_bfloat162*)hi)[i * 2 + 1] = hp1;
    ((__nv_bfloat162*)lo)[i * 2 + 0] = lp0;
    ((__nv_bfloat162*)lo)[i * 2 + 1] = lp1;
}

// ---------------------------------------------------------------------------
// Weight split with fused rank-4 LoRA fold:
//   W'[n,k] = W[n,k] + 0.25 * sum_r lb[n,r] * la[r,k]   (D x D weights only)
// ---------------------------------------------------------------------------
__global__ void split_lora_kernel(const float* __restrict__ W,
                                  const float* __restrict__ la,
                                  const float* __restrict__ lb,
                                  __nv_bfloat16* __restrict__ hi,
                                  __nv_bfloat16* __restrict__ lo)
{
    const int i = blockIdx.x * 256 + threadIdx.x;   // over D*D/4
    const int n  = i >> 8;            // row (D/4 = 256 float4 per row)
    const int k4 = (i & 255) * 4;
    float4 v = ((const float4*)W)[i];
    float4 lbv = ((const float4*)lb)[n];
    float4 a0 = *(const float4*)(la + 0 * kD + k4);
    float4 a1 = *(const float4*)(la + 1 * kD + k4);
    float4 a2 = *(const float4*)(la + 2 * kD + k4);
    float4 a3 = *(const float4*)(la + 3 * kD + k4);
    v.x += 0.25f * (lbv.x * a0.x + lbv.y * a1.x + lbv.z * a2.x + lbv.w * a3.x);
    v.y += 0.25f * (lbv.x * a0.y + lbv.y * a1.y + lbv.z * a2.y + lbv.w * a3.y);
    v.z += 0.25f * (lbv.x * a0.z + lbv.y * a1.z + lbv.z * a2.z + lbv.w * a3.z);
    v.w += 0.25f * (lbv.x * a0.w + lbv.y * a1.w + lbv.z * a2.w + lbv.w * a3.w);
    __nv_bfloat16 h0, h1, h2, h3, l0, l1, l2, l3;
    split1(v.x, h0, l0); split1(v.y, h1, l1);
    split1(v.z, h2, l2); split1(v.w, h3, l3);
    __nv_bfloat162 hp0; hp0.x = h0; hp0.y = h1;
    __nv_bfloat162 hp1; hp1.x = h2; hp1.y = h3;
    __nv_bfloat162 lp0; lp0.x = l0; lp0.y = l1;
    __nv_bfloat162 lp1; lp1.x = l2; lp1.y = l3;
    ((__nv_bfloat162*)hi)[i * 2 + 0] = hp0;
    ((__nv_bfloat162*)hi)[i * 2 + 1] = hp1;
    ((__nv_bfloat162*)lo)[i * 2 + 0] = lp0;
    ((__nv_bfloat162*)lo)[i * 2 + 1] = lp1;
}

// ---------------------------------------------------------------------------
// Tensor-core GEMM (mma.sync bf16, split hi/lo 3-term):
//   C = A @ B^T (+bias) (+GELU) (+res); SPLIT=1 -> bf16 hi/lo out
// CTA tile 256x128, warp tile 64x64 (8 warps = 4x2), BK=32,
// 3-stage cp.async ring, 1 barrier/iter, full fragment residency.
// ---------------------------------------------------------------------------
namespace {
constexpr int      kRowB   = 80;
constexpr uint32_t kTileA  = 256 * kRowB;   // 20480
constexpr uint32_t kTileB  = 128 * kRowB;   // 10240
constexpr uint32_t kStageG = 2 * kTileA + 2 * kTileB;  // 61440
constexpr uint32_t oAl = kTileA;            // 20480
constexpr uint32_t oBh = 2 * kTileA;        // 40960
constexpr uint32_t oBl = 2 * kTileA + kTileB;  // 51200
}

template <int GELU, int SPLIT>
__global__ void __launch_bounds__(256)
gemm_mma(const __nv_bfloat16* __restrict__ Ahi, const __nv_bfloat16* __restrict__ Alo,
         const __nv_bfloat16* __restrict__ Bhi, const __nv_bfloat16* __restrict__ Blo,
         const float* __restrict__ bias, const float* __restrict__ res,
         float* __restrict__ C,
         __nv_bfloat16* __restrict__ Chi, __nv_bfloat16* __restrict__ Clo,
         int M, int N, int K)
{
    extern __shared__ char smem[];
    const uint32_t sbase = smem_u32(smem);
    const int tid  = threadIdx.x;
    const int lane = tid & 31;
    const int wid  = tid >> 5;
    const int bm = blockIdx.y * 256;
    const int bn = blockIdx.x * 128;
    const int warp_m = (wid >> 1) * 64;    // 0,64,128,192
    const int warp_n = (wid & 1) * 64;     // 0,64

    const int r0  = tid >> 2;              // 0..63
    const int c8  = (tid & 3) * 8;
    const uint32_t so = (uint32_t)(r0 * kRowB + (tid & 3) * 16);

    float acc[4][8][4];
#pragma unroll
    for (int i = 0; i < 4; i++)
#pragma unroll
        for (int j = 0; j < 8; j++)
#pragma unroll
            for (int r = 0; r < 4; r++) acc[i][j][r] = 0.f;

    const uint32_t a_off = (uint32_t)((warp_m + (lane & 15)) * kRowB + (lane >> 4) * 16);
    const uint32_t b_off = (uint32_t)((warp_n + (lane & 7) + ((lane >> 4) & 1) * 8) * kRowB
                                      + ((lane >> 3) & 1) * 16);

    const int nIter = K >> 5;

    auto load_stage = [&](int it, int s) {
        const int k0 = it << 5;
        const uint32_t sbuf = sbase + (uint32_t)s * kStageG;
#pragma unroll
        for (int q = 0; q < 4; q++) {
            const size_t ga = (size_t)(bm + r0 + 64 * q) * K + k0 + c8;
            const uint32_t sq = so + (uint32_t)q * (64u * kRowB);
            CP_ASYNC16(sbuf +       sq, Ahi + ga);
            CP_ASYNC16(sbuf + oAl + sq, Alo + ga);
        }
#pragma unroll
        for (int q = 0; q < 2; q++) {
            const size_t gb = (size_t)(bn + r0 + 64 * q) * K + k0 + c8;
            const uint32_t sq = so + (uint32_t)q * (64u * kRowB);
            CP_ASYNC16(sbuf + oBh + sq, Bhi + gb);
            CP_ASYNC16(sbuf + oBl + sq, Blo + gb);
        }
        CP_COMMIT();
    };

    load_stage(0, 0);
    load_stage(1, 1);

    for (int it = 0; it < nIter; ++it) {
        if (it + 1 < nIter) {
            asm volatile("cp.async.wait_group 1;" ::: "memory");
        } else {
            asm volatile("cp.async.wait_group 0;" ::: "memory");
        }
        // Single barrier per iter: entering it, all warps finished compute(it-1),
        // so overwriting buffer (it+2)%3 == (it-1)%3 below is safe.
        __syncthreads();
        if (it + 2 < nIter) load_stage(it + 2, (it + 2) % 3);

        const uint32_t sbuf = sbase + (uint32_t)(it % 3) * kStageG;
        const uint32_t abase = sbuf + a_off;
        const uint32_t bbase = sbuf + oBh + b_off;

#pragma unroll
        for (int ks = 0; ks < 2; ks++) {
            const uint32_t ko = (uint32_t)ks * 32;
            uint32_t ah[4][4], al[4][4], bh[8][2], bl[8][2];
#pragma unroll
            for (int i = 0; i < 4; i++) {
                LDSM_X4(ah[i][0], ah[i][1], ah[i][2], ah[i][3],
                        abase + (uint32_t)i * (16 * kRowB) + ko);
            }
#pragma unroll
            for (int p = 0; p < 4; p++) {
                LDSM_X4(bh[2*p][0], bh[2*p][1], bh[2*p+1][0], bh[2*p+1][1],
                        bbase + (uint32_t)p * (16 * kRowB) + ko);
            }
#pragma unroll
            for (int i = 0; i < 4; i++) {
                LDSM_X4(al[i][0], al[i][1], al[i][2], al[i][3],
                        abase + oAl + (uint32_t)i * (16 * kRowB) + ko);
            }
#pragma unroll
            for (int p = 0; p < 4; p++) {
                LDSM_X4(bl[2*p][0], bl[2*p][1], bl[2*p+1][0], bl[2*p+1][1],
                        bbase + kTileB + (uint32_t)p * (16 * kRowB) + ko);
            }
            // term 1: Ahi * Bhi
#pragma unroll
            for (int i = 0; i < 4; i++)
#pragma unroll
                for (int j = 0; j < 8; j++)
                    MMA16816(acc[i][j], ah[i], bh[j]);
            // term 2: Ahi * Blo
#pragma unroll
            for (int i = 0; i < 4; i++)
#pragma unroll
                for (int j = 0; j < 8; j++)
                    MMA16816(acc[i][j], ah[i], bl[j]);
            // term 3: Alo * Bhi
#pragma unroll
            for (int i = 0; i < 4; i++)
#pragma unroll
                for (int j = 0; j < 8; j++)
                    MMA16816(acc[i][j], al[i], bh[j]);
        }
    }

    __syncthreads();   // all MMAs done before epilogue (paranoia-cheap, once)

    // ---- epilogue
    const int g  = lane >> 2;
    const int t4 = lane & 3;
#pragma unroll
    for (int i = 0; i < 4; i++) {
        const int mlo = bm + warp_m + 16 * i + g;
        const int mhi = mlo + 8;
#pragma unroll
        for (int j = 0; j < 8; j++) {
            const int n0 = bn + warp_n + 8 * j + 2 * t4;
            float b0 = 0.f, b1 = 0.f;
            if (bias) { b0 = bias[n0]; b1 = bias[n0 + 1]; }
            float v0 = acc[i][j][0] + b0;
            float v1 = acc[i][j][1] + b1;
            float v2 = acc[i][j][2] + b0;
            float v3 = acc[i][j][3] + b1;
            if (GELU) {
                v0 = 0.5f * v0 * (1.f + erff(v0 * 0.70710678118f));
                v1 = 0.5f * v1 * (1.f + erff(v1 * 0.70710678118f));
                v2 = 0.5f * v2 * (1.f + erff(v2 * 0.70710678118f));
                v3 = 0.5f * v3 * (1.f + erff(v3 * 0.70710678118f));
            }
            const size_t olo = (size_t)mlo * N + n0;
            const size_t ohi = (size_t)mhi * N + n0;
            if (SPLIT) {
                __nv_bfloat16 h0, h1, h2, h3, l0, l1, l2, l3;
                split1(v0, h0, l0); split1(v1, h1, l1);
                split1(v2, h2, l2); split1(v3, h3, l3);
                __nv_bfloat162 hp0; hp0.x = h0; hp0.y = h1;
                __nv_bfloat162 hp1; hp1.x = h2; hp1.y = h3;
                __nv_bfloat162 lp0; lp0.x = l0; lp0.y = l1;
                __nv_bfloat162 lp1; lp1.x = l2; lp1.y = l3;
                *(__nv_bfloat162*)(Chi + olo) = hp0;
                *(__nv_bfloat162*)(Chi + ohi) = hp1;
                *(__nv_bfloat162*)(Clo + olo) = lp0;
                *(__nv_bfloat162*)(Clo + ohi) = lp1;
            } else {
                if (res) {
                    float2 r0_ = *(const float2*)(res + olo);
                    float2 r1_ = *(const float2*)(res + ohi);
                    v0 += r0_.x; v1 += r0_.y; v2 += r1_.x; v3 += r1_.y;
                }
                *(float2*)(C + olo) = make_float2(v0, v1);
                *(float2*)(C + ohi) = make_float2(v2, v3);
            }
        }
    }
}

// ---------------------------------------------------------------------------
// LayerNorm -> split bf16 hi/lo directly
// ---------------------------------------------------------------------------
__global__ void ln_split_kernel(const float* __restrict__ x, const float* __restrict__ g,
                                const float* __restrict__ b,
                                __nv_bfloat16* __restrict__ yhi,
                                __nv_bfloat16* __restrict__ ylo)
{
    const int row = blockIdx.x;
    const int tid = threadIdx.x;
    float4 v = ((const float4*)(x + (size_t)row * kD))[tid];
    float s  = v.x + v.y + v.z + v.w;
    float sq = v.x*v.x + v.y*v.y + v.z*v.z + v.w*v.w;
#pragma unroll
    for (int o = 16; o; o >>= 1) {
        s  += __shfl_xor_sync(0xffffffffu, s,  o);
        sq += __shfl_xor_sync(0xffffffffu, sq, o);
    }
    __shared__ float ss[8], ssq[8];
    const int w = tid >> 5, lane = tid & 31;
    if (lane == 0) { ss[w] = s; ssq[w] = sq; }
    __syncthreads();
    if (w == 0) {
        float a = (lane < 8) ? ss[lane]  : 0.f;
        float c = (lane < 8) ? ssq[lane] : 0.f;
#pragma unroll
        for (int o = 4; o; o >>= 1) {
            a += __shfl_xor_sync(0xffffffffu, a, o);
            c += __shfl_xor_sync(0xffffffffu, c, o);
        }
        if (lane == 0) { ss[0] = a; ssq[0] = c; }
    }
    __syncthreads();
    const float mean = ss[0] * (1.f / kD);
    const float var  = ssq[0] * (1.f / kD) - mean * mean;
    const float rstd = rsqrtf(var + 1e-5f);
    float4 gv = ((const float4*)g)[tid];
    float4 bv = ((const float4*)b)[tid];
    float y0 = (v.x - mean) * rstd * gv.x + bv.x;
    float y1 = (v.y - mean) * rstd * gv.y + bv.y;
    float y2 = (v.z - mean) * rstd * gv.z + bv.z;
    float y3 = (v.w - mean) * rstd * gv.w + bv.w;
    __nv_bfloat16 h0, h1, h2, h3, l0, l1, l2, l3;
    split1(y0, h0, l0); split1(y1, h1, l1);
    split1(y2, h2, l2); split1(y3, h3, l3);
    __nv_bfloat162 hp0; hp0.x = h0; hp0.y = h1;
    __nv_bfloat162 hp1; hp1.x = h2; hp1.y = h3;
    __nv_bfloat162 lp0; lp0.x = l0; lp0.y = l1;
    __nv_bfloat162 lp1; lp1.x = l2; lp1.y = l3;
    ((__nv_bfloat162*)(yhi + (size_t)row * kD))[tid * 2 + 0] = hp0;
    ((__nv_bfloat162*)(yhi + (size_t)row * kD))[tid * 2 + 1] = hp1;
    ((__nv_bfloat162*)(ylo + (size_t)row * kD))[tid * 2 + 0] = lp0;
    ((__nv_bfloat162*)(ylo + (size_t)row * kD))[tid * 2 + 1] = lp1;
}

// ---------------------------------------------------------------------------
// Tensor-core flash attention (split-bf16 3-term for QK^T and PV).
// Block: 128 q-rows of one (b,h); 8 warps, each 16 q-rows x 64 keys.
// ---------------------------------------------------------------------------
namespace {
constexpr uint32_t aQH  = 0;
constexpr uint32_t aQL  = 18432;           // 128*144
constexpr uint32_t aKV0 = 36864;           // + stage*36864; Kh,Kl,Vh,Vl @ +9216 each
constexpr uint32_t aSMEM = 36864 + 2 * 36864;  // 110592
}

__global__ void __launch_bounds__(256)
attn_mma(const __nv_bfloat16* __restrict__ Qhi, const __nv_bfloat16* __restrict__ Qlo,
         const __nv_bfloat16* __restrict__ Khi, const __nv_bfloat16* __restrict__ Klo,
         const __nv_bfloat16* __restrict__ Vhi, const __nv_bfloat16* __restrict__ Vlo,
         __nv_bfloat16* __restrict__ Ohi, __nv_bfloat16* __restrict__ Olo)
{
    extern __shared__ char smem[];
    const uint32_t sb = smem_u32(smem);
    const int tid  = threadIdx.x;
    const int lane = tid & 31;
    const int wid  = tid >> 5;           // 0..7
    const int qt = blockIdx.x;           // 0..7
    const int bh = blockIdx.y;
    const int b  = bh >> 4, h = bh & 15;
    const size_t rowbase = (size_t)b * kS;
    const int cb = h * 64;
    const int warp_m = wid * 16;

    {
        const __nv_bfloat162 sc = __float2bfloat162_rn(0.125f);
#pragma unroll
        for (int i = tid; i < 1024; i += 256) {
            const int r = i >> 3, c = i & 7;
            const size_t go = (rowbase + qt * 128 + r) * kD + cb + c * 8;
            const uint32_t so = (uint32_t)(r * 144 + c * 16);
            uint4 vh = *(const uint4*)(Qhi + go);
            uint4 vl = *(const uint4*)(Qlo + go);
            __nv_bfloat162* ph = (__nv_bfloat162*)&vh;
            __nv_bfloat162* pl = (__nv_bfloat162*)&vl;
#pragma unroll
            for (int k = 0; k < 4; k++) { ph[k] = __hmul2(ph[k], sc); pl[k] = __hmul2(pl[k], sc); }
            st_shared_v4(sb + aQH + so, vh);
            st_shared_v4(sb + aQL + so, vl);
        }
    }

    auto load_kv = [&](int kt, int s) {
        const uint32_t st = sb + aKV0 + (uint32_t)s * 36864u;
#pragma unroll
        for (int i = tid; i < 512; i += 256) {
            const int r = i >> 3, c = i & 7;
            const size_t go = (rowbase + kt * 64 + r) * kD + cb + c * 8;
            const uint32_t so = (uint32_t)(r * 144 + c * 16);
            CP_ASYNC16(st +          so, Khi + go);
            CP_ASYNC16(st +  9216u + so, Klo + go);
            CP_ASYNC16(st + 18432u + so, Vhi + go);
            CP_ASYNC16(st + 27648u + so, Vlo + go);
        }
        CP_COMMIT();
    };
    load_kv(0, 0);
    __syncthreads();

    uint32_t qh[4][4], ql[4][4];
    {
        const uint32_t qa = sb + (uint32_t)((warp_m + (lane & 15)) * 144 + (lane >> 4) * 16);
#pragma unroll
        for (int kk = 0; kk < 4; kk++) {
            LDSM_X4(qh[kk][0], qh[kk][1], qh[kk][2], qh[kk][3], qa + aQH + kk * 32);
            LDSM_X4(ql[kk][0], ql[kk][1], ql[kk][2], ql[kk][3], qa + aQL + kk * 32);
        }
    }

    float m0 = -1e30f, m1 = -1e30f, l0 = 0.f, l1 = 0.f;
    float o[8][4];
#pragma unroll
    for (int j = 0; j < 8; j++)
#pragma unroll
        for (int c = 0; c < 4; c++) o[j][c] = 0.f;

    const uint32_t kboff = (uint32_t)(((lane & 7) + ((lane >> 4) & 1) * 8) * 144
                                      + ((lane >> 3) & 1) * 16);
    const uint32_t vaoff = (uint32_t)((lane & 15) * 144 + (lane >> 4) * 16);

    for (int kt = 0; kt < 16; kt++) {
        asm volatile("cp.async.wait_group 0;" ::: "memory");
        __syncthreads();
        if (kt + 1 < 16) load_kv(kt + 1, (kt + 1) & 1);
        const uint32_t st = sb + aKV0 + (uint32_t)(kt & 1) * 36864u;

        float s[8][4];
#pragma unroll
        for (int j = 0; j < 8; j++)
#pragma unroll
            for (int c = 0; c < 4; c++) s[j][c] = 0.f;

#pragma unroll
        for (int kk = 0; kk < 4; kk++) {
            uint32_t bh_[8][2], bl_[8][2];
#pragma unroll
            for (int p = 0; p < 4; p++) {
                LDSM_X4(bh_[2*p][0], bh_[2*p][1], bh_[2*p+1][0], bh_[2*p+1][1],
                        st + kboff + (uint32_t)p * (16 * 144) + kk * 32);
                LDSM_X4(bl_[2*p][0], bl_[2*p][1], bl_[2*p+1][0], bl_[2*p+1][1],
                        st + 9216u + kboff + (uint32_t)p * (16 * 144) + kk * 32);
            }
#pragma unroll
            for (int j = 0; j < 8; j++) MMA16816(s[j], qh[kk], bh_[j]);
#pragma unroll
            for (int j = 0; j < 8; j++) MMA16816(s[j], qh[kk], bl_[j]);
#pragma unroll
            for (int j = 0; j < 8; j++) MMA16816(s[j], ql[kk], bh_[j]);
        }

        float mx0 = m0, mx1 = m1;
#pragma unroll
        for (int j = 0; j < 8; j++) {
            mx0 = fmaxf(mx0, fmaxf(s[j][0], s[j][1]));
            mx1 = fmaxf(mx1, fmaxf(s[j][2], s[j][3]));
        }
        mx0 = fmaxf(mx0, __shfl_xor_sync(0xffffffffu, mx0, 1));
        mx0 = fmaxf(mx0, __shfl_xor_sync(0xffffffffu, mx0, 2));
        mx1 = fmaxf(mx1, __shfl_xor_sync(0xffffffffu, mx1, 1));
        mx1 = fmaxf(mx1, __shfl_xor_sync(0xffffffffu, mx1, 2));
        const float fac0 = __expf(m0 - mx0);
        const float fac1 = __expf(m1 - mx1);
        float sum0 = 0.f, sum1 = 0.f;
#pragma unroll
        for (int j = 0; j < 8; j++) {
            s[j][0] = __expf(s[j][0] - mx0);
            s[j][1] = __expf(s[j][1] - mx0);
            s[j][2] = __expf(s[j][2] - mx1);
            s[j][3] = __expf(s[j][3] - mx1);
            sum0 += s[j][0] + s[j][1];
            sum1 += s[j][2] + s[j][3];
        }
        sum0 += __shfl_xor_sync(0xffffffffu, sum0, 1);
        sum0 += __shfl_xor_sync(0xffffffffu, sum0, 2);
        sum1 += __shfl_xor_sync(0xffffffffu, sum1, 1);
        sum1 += __shfl_xor_sync(0xffffffffu, sum1, 2);
        l0 = l0 * fac0 + sum0;
        l1 = l1 * fac1 + sum1;
        m0 = mx0; m1 = mx1;
#pragma unroll
        for (int j = 0; j < 8; j++) {
            o[j][0] *= fac0; o[j][1] *= fac0;
            o[j][2] *= fac1; o[j][3] *= fac1;
        }

#pragma unroll
        for (int kk = 0; kk < 4; kk++) {
            uint32_t vh_[8][2], vl_[8][2];
#pragma unroll
            for (int nn = 0; nn < 4; nn++) {
                LDSM_X4T(vh_[2*nn][0], vh_[2*nn][1], vh_[2*nn+1][0], vh_[2*nn+1][1],
                         st + 18432u + vaoff + (uint32_t)kk * (16 * 144) + nn * 32);
                LDSM_X4T(vl_[2*nn][0], vl_[2*nn][1], vl_[2*nn+1][0], vl_[2*nn+1][1],
                         st + 27648u + vaoff + (uint32_t)kk * (16 * 144) + nn * 32);
            }
            const int j0 = 2 * kk, j1 = 2 * kk + 1;
            uint32_t ph[4], pl[4];
            ph[0] = pack_bf16x2(s[j0][0], s[j0][1]);
            ph[1] = pack_bf16x2(s[j0][2], s[j0][3]);
            ph[2] = pack_bf16x2(s[j1][0], s[j1][1]);
            ph[3] = pack_bf16x2(s[j1][2], s[j1][3]);
            {
                const float r00 = s[j0][0] - __bfloat162float(__float2bfloat16(s[j0][0]));
                const float r01 = s[j0][1] - __bfloat162float(__float2bfloat16(s[j0][1]));
                const float r02 = s[j0][2] - __bfloat162float(__float2bfloat16(s[j0][2]));
                const float r03 = s[j0][3] - __bfloat162float(__float2bfloat16(s[j0][3]));
                const float r10 = s[j1][0] - __bfloat162float(__float2bfloat16(s[j1][0]));
                const float r11 = s[j1][1] - __bfloat162float(__float2bfloat16(s[j1][1]));
                const float r12 = s[j1][2] - __bfloat162float(__float2bfloat16(s[j1][2]));
                const float r13 = s[j1][3] - __bfloat162float(__float2bfloat16(s[j1][3]));
                pl[0] = pack_bf16x2(r00, r01);
                pl[1] = pack_bf16x2(r02, r03);
                pl[2] = pack_bf16x2(r10, r11);
                pl[3] = pack_bf16x2(r12, r13);
            }
#pragma unroll
            for (int j = 0; j < 8; j++) MMA16816(o[j], ph, vh_[j]);
#pragma unroll
            for (int j = 0; j < 8; j++) MMA16816(o[j], ph, vl_[j]);
#pragma unroll
            for (int j = 0; j < 8; j++) MMA16816(o[j], pl, vh_[j]);
        }
    }

    const float inv0 = 1.f / l0, inv1 = 1.f / l1;
    const int g = lane >> 2, t4 = lane & 3;
    const size_t row0 = rowbase + qt * 128 + warp_m + g;
#pragma unroll
    for (int j = 0; j < 8; j++) {
        const int col = cb + 8 * j + 2 * t4;
        const float v0 = o[j][0] * inv0, v1 = o[j][1] * inv0;
        const float v2 = o[j][2] * inv1, v3 = o[j][3] * inv1;
        __nv_bfloat16 h0, h1, h2, h3, l0b, l1b, l2b, l3b;
        split1(v0, h0, l0b); split1(v1, h1, l1b);
        split1(v2, h2, l2b); split1(v3, h3, l3b);
        __nv_bfloat162 hp0; hp0.x = h0; hp0.y = h1;
        __nv_bfloat162 hp1; hp1.x = h2; hp1.y = h3;
        __nv_bfloat162 lp0; lp0.x = l0b; lp0.y = l1b;
        __nv_bfloat162 lp1; lp1.x = l2b; lp1.y = l3b;
        *(__nv_bfloat162*)(Ohi + row0 * kD + col)       = hp0;
        *(__nv_bfloat162*)(Olo + row0 * kD + col)       = lp0;
        *(__nv_bfloat162*)(Ohi + (row0 + 8) * kD + col) = hp1;
        *(__nv_bfloat162*)(Olo + (row0 + 8) * kD + col) = lp1;
    }
}

// ---------------------------------------------------------------------------
// Host launcher
// ---------------------------------------------------------------------------
extern "C" void kernel_launch(void* const* d_in, const int* in_sizes, int n_in,
                              void* d_out, int out_size)
{
    (void)in_sizes; (void)n_in; (void)out_size;
    const float* x    = (const float*)d_in[0];
    const float* Wq   = (const float*)d_in[1];
    const float* bq   = (const float*)d_in[2];
    const float* Wk   = (const float*)d_in[3];
    const float* Wv   = (const float*)d_in[4];
    const float* bv   = (const float*)d_in[5];
    const float* Wo   = (const float*)d_in[6];
    const float* bo   = (const float*)d_in[7];
    const float* la_k = (const float*)d_in[8];
    const float* lb_k = (const float*)d_in[9];
    const float* la_v = (const float*)d_in[10];
    const float* lb_v = (const float*)d_in[11];
    const float* la_o = (const float*)d_in[12];
    const float* lb_o = (const float*)d_in[13];
    const float* ga   = (const float*)d_in[14];
    const float* ba   = (const float*)d_in[15];
    const float* W1   = (const float*)d_in[16];
    const float* b1   = (const float*)d_in[17];
    const float* W2   = (const float*)d_in[18];
    const float* b2   = (const float*)d_in[19];
    const float* gm   = (const float*)d_in[20];
    const float* bmn  = (const float*)d_in[21];
    float* out = (float*)d_out;

    static float *p_x1 = nullptr, *p_u;
    static __nv_bfloat16 *pa_hi, *pa_lo, *pw_hi, *pw_lo, *pu_hi, *pu_lo;
    static __nv_bfloat16 *pq_hi, *pq_lo, *pk_hi, *pk_lo, *pv_hi, *pv_lo;
    if (!p_x1) {
        float* tmp;
        cudaGetSymbolAddress((void**)&tmp, g_q);
        pq_hi = (__nv_bfloat16*)tmp; pq_lo = pq_hi + (size_t)kM * kD;
        cudaGetSymbolAddress((void**)&tmp, g_k);
        pk_hi = (__nv_bfloat16*)tmp; pk_lo = pk_hi + (size_t)kM * kD;
        cudaGetSymbolAddress((void**)&tmp, g_v);
        pv_hi = (__nv_bfloat16*)tmp; pv_lo = pv_hi + (size_t)kM * kD;
        cudaGetSymbolAddress((void**)&p_u,   g_u);
        pu_hi = (__nv_bfloat16*)p_u; pu_lo = pu_hi + (size_t)kM * kDff;
        cudaGetSymbolAddress((void**)&pa_hi, g_a_hi);
        cudaGetSymbolAddress((void**)&pa_lo, g_a_lo);
        cudaGetSymbolAddress((void**)&pw_hi, g_w_hi);
        cudaGetSymbolAddress((void**)&pw_lo, g_w_lo);
        cudaFuncSetAttribute(attn_mma,
                             cudaFuncAttributeMaxDynamicSharedMemorySize, aSMEM);
        cudaFuncSetAttribute(gemm_mma<0, 0>,
                             cudaFuncAttributeMaxDynamicSharedMemorySize, 3 * kStageG);
        cudaFuncSetAttribute(gemm_mma<0, 1>,
                             cudaFuncAttributeMaxDynamicSharedMemorySize, 3 * kStageG);
        cudaFuncSetAttribute(gemm_mma<1, 1>,
                             cudaFuncAttributeMaxDynamicSharedMemorySize, 3 * kStageG);
        cudaGetSymbolAddress((void**)&p_x1,  g_x1);   // init flag last
    }

    const dim3 blk(256);
    const dim3 gD(kD / 128, kM / 256);      // (8, 32)
    const dim3 gF(kDff / 128, kM / 256);    // (32, 32)
    const int nWDD  = kD * kD / 4;
    const int nWDF  = kDff * kD / 4;
    const unsigned SMEM_G = 3 * kStageG;    // 184320 B

    // ---- attention half ----
    ln_split_kernel<<<kM, blk>>>(x, ga, ba, pa_hi, pa_lo);

    split_kernel<<<nWDD / 256, blk>>>(Wq, pw_hi, pw_lo, nWDD);
    gemm_mma<0, 1><<<gD, blk, SMEM_G>>>(pa_hi, pa_lo, pw_hi, pw_lo,
                                        bq, nullptr,
                                        nullptr, pq_hi, pq_lo, kM, kD, kD);

    split_lora_kernel<<<nWDD / 256, blk>>>(Wk, la_k, lb_k, pw_hi, pw_lo);
    gemm_mma<0, 1><<<gD, blk, SMEM_G>>>(pa_hi, pa_lo, pw_hi, pw_lo,
                                        nullptr, nullptr,
                                        nullptr, pk_hi, pk_lo, kM, kD, kD);

    split_lora_kernel<<<nWDD / 256, blk>>>(Wv, la_v, lb_v, pw_hi, pw_lo);
    gemm_mma<0, 1><<<gD, blk, SMEM_G>>>(pa_hi, pa_lo, pw_hi, pw_lo,
                                        bv, nullptr,
                                        nullptr, pv_hi, pv_lo, kM, kD, kD);

    attn_mma<<<dim3(8, kB * kH), blk, aSMEM>>>(pq_hi, pq_lo, pk_hi, pk_lo,
                                               pv_hi, pv_lo, pa_hi, pa_lo);

    split_lora_kernel<<<nWDD / 256, blk>>>(Wo, la_o, lb_o, pw_hi, pw_lo);
    gemm_mma<0, 0><<<gD, blk, SMEM_G>>>(pa_hi, pa_lo, pw_hi, pw_lo,
                                        bo, x,
                                        p_x1, nullptr, nullptr, kM, kD, kD);

    // ---- MLP half ----
    ln_split_kernel<<<kM, blk>>>(p_x1, gm, bmn, pa_hi, pa_lo);
    split_kernel<<<nWDF / 256, blk>>>(W1, pw_hi, pw_lo, nWDF);
    gemm_mma<1, 1><<<gF, blk, SMEM_G>>>(pa_hi, pa_lo, pw_hi, pw_lo,
                                        b1, nullptr,
                                        nullptr, pu_hi, pu_lo, kM, kDff, kD);

    split_kernel<<<nWDF / 256, blk>>>(W2, pw_hi, pw_lo, nWDF);
    gemm_mma<0, 0><<<gD, blk, SMEM_G>>>(pu_hi, pu_lo, pw_hi, pw_lo,
                                        b2, p_x1,
                                        out, nullptr, nullptr, kM, kD, kDff);
}

// round 10
// speedup vs baseline: 3.1576x; 1.0912x over previous
#include <cuda_runtime.h>
#include <cuda_bf16.h>
#include <cstdint>
#include <math.h>

// ---------------------------------------------------------------------------
// Shapes (fixed by the problem)
// ---------------------------------------------------------------------------
namespace {
constexpr int kD   = 1024;
constexpr int kDff = 4096;
constexpr int kB   = 8;
constexpr int kS   = 1024;
constexpr int kM   = kB * kS;   // 8192 rows
constexpr int kH   = 16;        // heads
}

// ---------------------------------------------------------------------------
// Scratch (static device globals -- no allocation allowed)
// ---------------------------------------------------------------------------
__device__ float g_q [(size_t)kM * kD];     // reused: bf16 q_hi / q_lo
__device__ float g_k [(size_t)kM * kD];     // reused: bf16 k_hi / k_lo
__device__ float g_v [(size_t)kM * kD];     // reused: bf16 v_hi / v_lo
__device__ float g_x1[(size_t)kM * kD];
__device__ float g_u [(size_t)kM * kDff];   // reused: bf16 u_hi / u_lo
__device__ __nv_bfloat16 g_a_hi[(size_t)kM * kD];
__device__ __nv_bfloat16 g_a_lo[(size_t)kM * kD];
__device__ __nv_bfloat16 g_w_hi[(size_t)kDff * kD];
__device__ __nv_bfloat16 g_w_lo[(size_t)kDff * kD];

// ---------------------------------------------------------------------------
// PTX helpers (portable sm_80+: cp.async / ldmatrix / mma.sync)
// ---------------------------------------------------------------------------
__device__ __forceinline__ uint32_t smem_u32(const void* p) {
    uint32_t a;
    asm("{ .reg .u64 t; cvta.to.shared.u64 t, %1; cvt.u32.u64 %0, t; }"
        : "=r"(a) : "l"(p));
    return a;
}

#define CP_ASYNC16(saddr, gptr) \
    asm volatile("cp.async.cg.shared.global [%0], [%1], 16;" \
        :: "r"(saddr), "l"(gptr))

#define CP_COMMIT() asm volatile("cp.async.commit_group;" ::: "memory")

#define LDSM_X4(r0, r1, r2, r3, addr) \
    asm volatile("ldmatrix.sync.aligned.m8n8.x4.shared.b16 {%0,%1,%2,%3}, [%4];" \
        : "=r"(r0), "=r"(r1), "=r"(r2), "=r"(r3) : "r"(addr))

#define LDSM_X4T(r0, r1, r2, r3, addr) \
    asm volatile("ldmatrix.sync.aligned.m8n8.x4.trans.shared.b16 {%0,%1,%2,%3}, [%4];" \
        : "=r"(r0), "=r"(r1), "=r"(r2), "=r"(r3) : "r"(addr))

#define MMA16816(d, a, b) \
    asm volatile("mma.sync.aligned.m16n8k16.row.col.f32.bf16.bf16.f32 " \
        "{%0,%1,%2,%3}, {%4,%5,%6,%7}, {%8,%9}, {%0,%1,%2,%3};" \
        : "+f"((d)[0]), "+f"((d)[1]), "+f"((d)[2]), "+f"((d)[3]) \
        : "r"((a)[0]), "r"((a)[1]), "r"((a)[2]), "r"((a)[3]), \
          "r"((b)[0]), "r"((b)[1]))

__device__ __forceinline__ void split1(float v, __nv_bfloat16& h, __nv_bfloat16& l) {
    h = __float2bfloat16(v);
    l = __float2bfloat16(v - __bfloat162float(h));
}

__device__ __forceinline__ uint32_t pack_bf16x2(float a, float b) {
    __nv_bfloat162 t = __floats2bfloat162_rn(a, b);   // .x = a (low half)
    return *(uint32_t*)&t;
}

__device__ __forceinline__ void st_shared_v4(uint32_t addr, uint4 v) {
    asm volatile("st.shared.v4.b32 [%0], {%1, %2, %3, %4};"
        :: "r"(addr), "r"(v.x), "r"(v.y), "r"(v.z), "r"(v.w));
}

// ---------------------------------------------------------------------------
// fp32 -> (bf16 hi, bf16 lo) split (plain weights / no LoRA)
// ---------------------------------------------------------------------------
__global__ void split_kernel(const float* __restrict__ x, __nv_bfloat16* __restrict__ hi,
                             __nv_bfloat16* __restrict__ lo, int n4)
{
    const int i = blockIdx.x * 256 + threadIdx.x;
    if (i >= n4) return;
    float4 v = ((const float4*)x)[i];
    __nv_bfloat16 h0, h1, h2, h3, l0, l1, l2, l3;
    split1(v.x, h0, l0); split1(v.y, h1, l1);
    split1(v.z, h2, l2); split1(v.w, h3, l3);
    __nv_bfloat162 hp0; hp0.x = h0; hp0.y = h1;
    __nv_bfloat162 hp1; hp1.x = h2; hp1.y = h3;
    __nv_bfloat162 lp0; lp0.x = l0; lp0.y = l1;
    __nv_bfloat162 lp1; lp1.x = l2; lp1.y = l3;
    ((__nv_bfloat162*)hi)[i * 2 + 0] = hp0;
    ((__nv_bfloat162*)hi)[i * 2 + 1] = hp1;
    ((__nv_bfloat162*)lo)[i * 2 + 0] = lp0;
    ((__nv_bfloat162*)lo)[i * 2 + 1] = lp1;
}

// ---------------------------------------------------------------------------
// Weight split with fused rank-4 LoRA fold:
//   W'[n,k] = W[n,k] + 0.25 * sum_r lb[n,r] * la[r,k]   (D x D weights only)
// ---------------------------------------------------------------------------
__global__ void split_lora_kernel(const float* __restrict__ W,
                                  const float* __restrict__ la,
                                  const float* __restrict__ lb,
                                  __nv_bfloat16* __restrict__ hi,
                                  __nv_bfloat16* __restrict__ lo)
{
    const int i = blockIdx.x * 256 + threadIdx.x;   // over D*D/4
    const int n  = i >> 8;            // row (D/4 = 256 float4 per row)
    const int k4 = (i & 255) * 4;
    float4 v = ((const float4*)W)[i];
    float4 lbv = ((const float4*)lb)[n];
    float4 a0 = *(const float4*)(la + 0 * kD + k4);
    float4 a1 = *(const float4*)(la + 1 * kD + k4);
    float4 a2 = *(const float4*)(la + 2 * kD + k4);
    float4 a3 = *(const float4*)(la + 3 * kD + k4);
    v.x += 0.25f * (lbv.x * a0.x + lbv.y * a1.x + lbv.z * a2.x + lbv.w * a3.x);
    v.y += 0.25f * (lbv.x * a0.y + lbv.y * a1.y + lbv.z * a2.y + lbv.w * a3.y);
    v.z += 0.25f * (lbv.x * a0.z + lbv.y * a1.z + lbv.z * a2.z + lbv.w * a3.z);
    v.w += 0.25f * (lbv.x * a0.w + lbv.y * a1.w + lbv.z * a2.w + lbv.w * a3.w);
    __nv_bfloat16 h0, h1, h2, h3, l0, l1, l2, l3;
    split1(v.x, h0, l0); split1(v.y, h1, l1);
    split1(v.z, h2, l2); split1(v.w, h3, l3);
    __nv_bfloat162 hp0; hp0.x = h0; hp0.y = h1;
    __nv_bfloat162 hp1; hp1.x = h2; hp1.y = h3;
    __nv_bfloat162 lp0; lp0.x = l0; lp0.y = l1;
    __nv_bfloat162 lp1; lp1.x = l2; lp1.y = l3;
    ((__nv_bfloat162*)hi)[i * 2 + 0] = hp0;
    ((__nv_bfloat162*)hi)[i * 2 + 1] = hp1;
    ((__nv_bfloat162*)lo)[i * 2 + 0] = lp0;
    ((__nv_bfloat162*)lo)[i * 2 + 1] = lp1;
}

// ---------------------------------------------------------------------------
// Tensor-core GEMM (mma.sync bf16, split hi/lo 3-term):
//   C = A @ B^T (+bias) (+GELU) (+res); SPLIT=1 -> bf16 hi/lo out
// CTA tile 128x128, warp tile 64x32 (8 warps = 2x4), BK=32,
// 2-stage cp.async ring, __launch_bounds__(256,2) -> 2 CTAs/SM for
// cross-CTA latency hiding (4 warps/SMSP).
// ---------------------------------------------------------------------------
namespace {
constexpr int      kRowB   = 80;
constexpr uint32_t kTile128 = 128 * kRowB;              // 10240
constexpr uint32_t kStage2  = 4 * kTile128;             // 40960 per stage
constexpr uint32_t oAl2 = kTile128;                     // 10240
constexpr uint32_t oBh2 = 2 * kTile128;                 // 20480
constexpr uint32_t oBl2 = 3 * kTile128;                 // 30720
}

template <int GELU, int SPLIT>
__global__ void __launch_bounds__(256, 2)
gemm_mma(const __nv_bfloat16* __restrict__ Ahi, const __nv_bfloat16* __restrict__ Alo,
         const __nv_bfloat16* __restrict__ Bhi, const __nv_bfloat16* __restrict__ Blo,
         const float* __restrict__ bias, const float* __restrict__ res,
         float* __restrict__ C,
         __nv_bfloat16* __restrict__ Chi, __nv_bfloat16* __restrict__ Clo,
         int M, int N, int K)
{
    extern __shared__ char smem[];
    const uint32_t sbase = smem_u32(smem);
    const int tid  = threadIdx.x;
    const int lane = tid & 31;
    const int wid  = tid >> 5;
    const int bm = blockIdx.y * 128;
    const int bn = blockIdx.x * 128;
    const int warp_m = (wid >> 2) * 64;    // 0 or 64
    const int warp_n = (wid & 3) * 32;     // 0,32,64,96

    const int r0 = tid >> 2;               // 0..63
    const int c8 = (tid & 3) * 8;
    const uint32_t so = (uint32_t)(r0 * kRowB + (tid & 3) * 16);

    float acc[4][4][4];
#pragma unroll
    for (int i = 0; i < 4; i++)
#pragma unroll
        for (int j = 0; j < 4; j++)
#pragma unroll
            for (int r = 0; r < 4; r++) acc[i][j][r] = 0.f;

    const uint32_t a_off = (uint32_t)((warp_m + (lane & 15)) * kRowB + (lane >> 4) * 16);
    const uint32_t b_off = (uint32_t)((warp_n + (lane & 7) + ((lane >> 4) & 1) * 8) * kRowB
                                      + ((lane >> 3) & 1) * 16);

    const int nIter = K >> 5;

    auto load_stage = [&](int it, int s) {
        const int k0 = it << 5;
        const uint32_t sbuf = sbase + (uint32_t)s * kStage2;
        const size_t ga0 = (size_t)(bm + r0) * K + k0 + c8;
        const size_t ga1 = ga0 + (size_t)64 * K;
        const size_t gb0 = (size_t)(bn + r0) * K + k0 + c8;
        const size_t gb1 = gb0 + (size_t)64 * K;
        const uint32_t so1 = so + 64u * kRowB;
        CP_ASYNC16(sbuf +        so,  Ahi + ga0);
        CP_ASYNC16(sbuf +        so1, Ahi + ga1);
        CP_ASYNC16(sbuf + oAl2 + so,  Alo + ga0);
        CP_ASYNC16(sbuf + oAl2 + so1, Alo + ga1);
        CP_ASYNC16(sbuf + oBh2 + so,  Bhi + gb0);
        CP_ASYNC16(sbuf + oBh2 + so1, Bhi + gb1);
        CP_ASYNC16(sbuf + oBl2 + so,  Blo + gb0);
        CP_ASYNC16(sbuf + oBl2 + so1, Blo + gb1);
        CP_COMMIT();
    };

    load_stage(0, 0);

    for (int it = 0; it < nIter; ++it) {
        // prefetch next into the buffer consumed two iters ago (trailing
        // barrier of it-1 guarantees everyone finished reading it)
        if (it + 1 < nIter) {
            load_stage(it + 1, (it + 1) & 1);
            asm volatile("cp.async.wait_group 1;" ::: "memory");
        } else {
            asm volatile("cp.async.wait_group 0;" ::: "memory");
        }
        __syncthreads();

        const uint32_t sbuf = sbase + (uint32_t)(it & 1) * kStage2;
        const uint32_t abase = sbuf + a_off;
        const uint32_t bbase = sbuf + oBh2 + b_off;

#pragma unroll
        for (int ks = 0; ks < 2; ks++) {
            const uint32_t ko = (uint32_t)ks * 32;
            uint32_t ah[4][4], al[4][4], bh[4][2], bl[4][2];
#pragma unroll
            for (int i = 0; i < 4; i++) {
                LDSM_X4(ah[i][0], ah[i][1], ah[i][2], ah[i][3],
                        abase + (uint32_t)i * (16 * kRowB) + ko);
            }
#pragma unroll
            for (int p = 0; p < 2; p++) {
                LDSM_X4(bh[2*p][0], bh[2*p][1], bh[2*p+1][0], bh[2*p+1][1],
                        bbase + (uint32_t)p * (16 * kRowB) + ko);
            }
#pragma unroll
            for (int i = 0; i < 4; i++) {
                LDSM_X4(al[i][0], al[i][1], al[i][2], al[i][3],
                        abase + oAl2 + (uint32_t)i * (16 * kRowB) + ko);
            }
#pragma unroll
            for (int p = 0; p < 2; p++) {
                LDSM_X4(bl[2*p][0], bl[2*p][1], bl[2*p+1][0], bl[2*p+1][1],
                        bbase + kTile128 + (uint32_t)p * (16 * kRowB) + ko);
            }
            // term 1: Ahi * Bhi
#pragma unroll
            for (int i = 0; i < 4; i++)
#pragma unroll
                for (int j = 0; j < 4; j++)
                    MMA16816(acc[i][j], ah[i], bh[j]);
            // term 2: Ahi * Blo
#pragma unroll
            for (int i = 0; i < 4; i++)
#pragma unroll
                for (int j = 0; j < 4; j++)
                    MMA16816(acc[i][j], ah[i], bl[j]);
            // term 3: Alo * Bhi
#pragma unroll
            for (int i = 0; i < 4; i++)
#pragma unroll
                for (int j = 0; j < 4; j++)
                    MMA16816(acc[i][j], al[i], bh[j]);
        }
        __syncthreads();
    }

    // ---- epilogue
    const int g  = lane >> 2;
    const int t4 = lane & 3;
#pragma unroll
    for (int i = 0; i < 4; i++) {
        const int mlo = bm + warp_m + 16 * i + g;
        const int mhi = mlo + 8;
#pragma unroll
        for (int j = 0; j < 4; j++) {
            const int n0 = bn + warp_n + 8 * j + 2 * t4;
            float b0 = 0.f, b1 = 0.f;
            if (bias) { b0 = bias[n0]; b1 = bias[n0 + 1]; }
            float v0 = acc[i][j][0] + b0;
            float v1 = acc[i][j][1] + b1;
            float v2 = acc[i][j][2] + b0;
            float v3 = acc[i][j][3] + b1;
            if (GELU) {
                v0 = 0.5f * v0 * (1.f + erff(v0 * 0.70710678118f));
                v1 = 0.5f * v1 * (1.f + erff(v1 * 0.70710678118f));
                v2 = 0.5f * v2 * (1.f + erff(v2 * 0.70710678118f));
                v3 = 0.5f * v3 * (1.f + erff(v3 * 0.70710678118f));
            }
            const size_t olo = (size_t)mlo * N + n0;
            const size_t ohi = (size_t)mhi * N + n0;
            if (SPLIT) {
                __nv_bfloat16 h0, h1, h2, h3, l0, l1, l2, l3;
                split1(v0, h0, l0); split1(v1, h1, l1);
                split1(v2, h2, l2); split1(v3, h3, l3);
                __nv_bfloat162 hp0; hp0.x = h0; hp0.y = h1;
                __nv_bfloat162 hp1; hp1.x = h2; hp1.y = h3;
                __nv_bfloat162 lp0; lp0.x = l0; lp0.y = l1;
                __nv_bfloat162 lp1; lp1.x = l2; lp1.y = l3;
                *(__nv_bfloat162*)(Chi + olo) = hp0;
                *(__nv_bfloat162*)(Chi + ohi) = hp1;
                *(__nv_bfloat162*)(Clo + olo) = lp0;
                *(__nv_bfloat162*)(Clo + ohi) = lp1;
            } else {
                if (res) {
                    float2 r0_ = *(const float2*)(res + olo);
                    float2 r1_ = *(const float2*)(res + ohi);
                    v0 += r0_.x; v1 += r0_.y; v2 += r1_.x; v3 += r1_.y;
                }
                *(float2*)(C + olo) = make_float2(v0, v1);
                *(float2*)(C + ohi) = make_float2(v2, v3);
            }
        }
    }
}

// ---------------------------------------------------------------------------
// LayerNorm -> split bf16 hi/lo directly
// ---------------------------------------------------------------------------
__global__ void ln_split_kernel(const float* __restrict__ x, const float* __restrict__ g,
                                const float* __restrict__ b,
                                __nv_bfloat16* __restrict__ yhi,
                                __nv_bfloat16* __restrict__ ylo)
{
    const int row = blockIdx.x;
    const int tid = threadIdx.x;
    float4 v = ((const float4*)(x + (size_t)row * kD))[tid];
    float s  = v.x + v.y + v.z + v.w;
    float sq = v.x*v.x + v.y*v.y + v.z*v.z + v.w*v.w;
#pragma unroll
    for (int o = 16; o; o >>= 1) {
        s  += __shfl_xor_sync(0xffffffffu, s,  o);
        sq += __shfl_xor_sync(0xffffffffu, sq, o);
    }
    __shared__ float ss[8], ssq[8];
    const int w = tid >> 5, lane = tid & 31;
    if (lane == 0) { ss[w] = s; ssq[w] = sq; }
    __syncthreads();
    if (w == 0) {
        float a = (lane < 8) ? ss[lane]  : 0.f;
        float c = (lane < 8) ? ssq[lane] : 0.f;
#pragma unroll
        for (int o = 4; o; o >>= 1) {
            a += __shfl_xor_sync(0xffffffffu, a, o);
            c += __shfl_xor_sync(0xffffffffu, c, o);
        }
        if (lane == 0) { ss[0] = a; ssq[0] = c; }
    }
    __syncthreads();
    const float mean = ss[0] * (1.f / kD);
    const float var  = ssq[0] * (1.f / kD) - mean * mean;
    const float rstd = rsqrtf(var + 1e-5f);
    float4 gv = ((const float4*)g)[tid];
    float4 bv = ((const float4*)b)[tid];
    float y0 = (v.x - mean) * rstd * gv.x + bv.x;
    float y1 = (v.y - mean) * rstd * gv.y + bv.y;
    float y2 = (v.z - mean) * rstd * gv.z + bv.z;
    float y3 = (v.w - mean) * rstd * gv.w + bv.w;
    __nv_bfloat16 h0, h1, h2, h3, l0, l1, l2, l3;
    split1(y0, h0, l0); split1(y1, h1, l1);
    split1(y2, h2, l2); split1(y3, h3, l3);
    __nv_bfloat162 hp0; hp0.x = h0; hp0.y = h1;
    __nv_bfloat162 hp1; hp1.x = h2; hp1.y = h3;
    __nv_bfloat162 lp0; lp0.x = l0; lp0.y = l1;
    __nv_bfloat162 lp1; lp1.x = l2; lp1.y = l3;
    ((__nv_bfloat162*)(yhi + (size_t)row * kD))[tid * 2 + 0] = hp0;
    ((__nv_bfloat162*)(yhi + (size_t)row * kD))[tid * 2 + 1] = hp1;
    ((__nv_bfloat162*)(ylo + (size_t)row * kD))[tid * 2 + 0] = lp0;
    ((__nv_bfloat162*)(ylo + (size_t)row * kD))[tid * 2 + 1] = lp1;
}

// ---------------------------------------------------------------------------
// Tensor-core flash attention (split-bf16 3-term for QK^T and PV).
// Block: 128 q-rows of one (b,h); 8 warps, each 16 q-rows x 64 keys.
// ---------------------------------------------------------------------------
namespace {
constexpr uint32_t aQH  = 0;
constexpr uint32_t aQL  = 18432;           // 128*144
constexpr uint32_t aKV0 = 36864;           // + stage*36864; Kh,Kl,Vh,Vl @ +9216 each
constexpr uint32_t aSMEM = 36864 + 2 * 36864;  // 110592
}

__global__ void __launch_bounds__(256)
attn_mma(const __nv_bfloat16* __restrict__ Qhi, const __nv_bfloat16* __restrict__ Qlo,
         const __nv_bfloat16* __restrict__ Khi, const __nv_bfloat16* __restrict__ Klo,
         const __nv_bfloat16* __restrict__ Vhi, const __nv_bfloat16* __restrict__ Vlo,
         __nv_bfloat16* __restrict__ Ohi, __nv_bfloat16* __restrict__ Olo)
{
    extern __shared__ char smem[];
    const uint32_t sb = smem_u32(smem);
    const int tid  = threadIdx.x;
    const int lane = tid & 31;
    const int wid  = tid >> 5;           // 0..7
    const int qt = blockIdx.x;           // 0..7
    const int bh = blockIdx.y;
    const int b  = bh >> 4, h = bh & 15;
    const size_t rowbase = (size_t)b * kS;
    const int cb = h * 64;
    const int warp_m = wid * 16;

    {
        const __nv_bfloat162 sc = __float2bfloat162_rn(0.125f);
#pragma unroll
        for (int i = tid; i < 1024; i += 256) {
            const int r = i >> 3, c = i & 7;
            const size_t go = (rowbase + qt * 128 + r) * kD + cb + c * 8;
            const uint32_t so = (uint32_t)(r * 144 + c * 16);
            uint4 vh = *(const uint4*)(Qhi + go);
            uint4 vl = *(const uint4*)(Qlo + go);
            __nv_bfloat162* ph = (__nv_bfloat162*)&vh;
            __nv_bfloat162* pl = (__nv_bfloat162*)&vl;
#pragma unroll
            for (int k = 0; k < 4; k++) { ph[k] = __hmul2(ph[k], sc); pl[k] = __hmul2(pl[k], sc); }
            st_shared_v4(sb + aQH + so, vh);
            st_shared_v4(sb + aQL + so, vl);
        }
    }

    auto load_kv = [&](int kt, int s) {
        const uint32_t st = sb + aKV0 + (uint32_t)s * 36864u;
#pragma unroll
        for (int i = tid; i < 512; i += 256) {
            const int r = i >> 3, c = i & 7;
            const size_t go = (rowbase + kt * 64 + r) * kD + cb + c * 8;
            const uint32_t so = (uint32_t)(r * 144 + c * 16);
            CP_ASYNC16(st +          so, Khi + go);
            CP_ASYNC16(st +  9216u + so, Klo + go);
            CP_ASYNC16(st + 18432u + so, Vhi + go);
            CP_ASYNC16(st + 27648u + so, Vlo + go);
        }
        CP_COMMIT();
    };
    load_kv(0, 0);
    __syncthreads();

    uint32_t qh[4][4], ql[4][4];
    {
        const uint32_t qa = sb + (uint32_t)((warp_m + (lane & 15)) * 144 + (lane >> 4) * 16);
#pragma unroll
        for (int kk = 0; kk < 4; kk++) {
            LDSM_X4(qh[kk][0], qh[kk][1], qh[kk][2], qh[kk][3], qa + aQH + kk * 32);
            LDSM_X4(ql[kk][0], ql[kk][1], ql[kk][2], ql[kk][3], qa + aQL + kk * 32);
        }
    }

    float m0 = -1e30f, m1 = -1e30f, l0 = 0.f, l1 = 0.f;
    float o[8][4];
#pragma unroll
    for (int j = 0; j < 8; j++)
#pragma unroll
        for (int c = 0; c < 4; c++) o[j][c] = 0.f;

    const uint32_t kboff = (uint32_t)(((lane & 7) + ((lane >> 4) & 1) * 8) * 144
                                      + ((lane >> 3) & 1) * 16);
    const uint32_t vaoff = (uint32_t)((lane & 15) * 144 + (lane >> 4) * 16);

    for (int kt = 0; kt < 16; kt++) {
        asm volatile("cp.async.wait_group 0;" ::: "memory");
        __syncthreads();
        if (kt + 1 < 16) load_kv(kt + 1, (kt + 1) & 1);
        const uint32_t st = sb + aKV0 + (uint32_t)(kt & 1) * 36864u;

        float s[8][4];
#pragma unroll
        for (int j = 0; j < 8; j++)
#pragma unroll
            for (int c = 0; c < 4; c++) s[j][c] = 0.f;

#pragma unroll
        for (int kk = 0; kk < 4; kk++) {
            uint32_t bh_[8][2], bl_[8][2];
#pragma unroll
            for (int p = 0; p < 4; p++) {
                LDSM_X4(bh_[2*p][0], bh_[2*p][1], bh_[2*p+1][0], bh_[2*p+1][1],
                        st + kboff + (uint32_t)p * (16 * 144) + kk * 32);
                LDSM_X4(bl_[2*p][0], bl_[2*p][1], bl_[2*p+1][0], bl_[2*p+1][1],
                        st + 9216u + kboff + (uint32_t)p * (16 * 144) + kk * 32);
            }
#pragma unroll
            for (int j = 0; j < 8; j++) MMA16816(s[j], qh[kk], bh_[j]);
#pragma unroll
            for (int j = 0; j < 8; j++) MMA16816(s[j], qh[kk], bl_[j]);
#pragma unroll
            for (int j = 0; j < 8; j++) MMA16816(s[j], ql[kk], bh_[j]);
        }

        float mx0 = m0, mx1 = m1;
#pragma unroll
        for (int j = 0; j < 8; j++) {
            mx0 = fmaxf(mx0, fmaxf(s[j][0], s[j][1]));
            mx1 = fmaxf(mx1, fmaxf(s[j][2], s[j][3]));
        }
        mx0 = fmaxf(mx0, __shfl_xor_sync(0xffffffffu, mx0, 1));
        mx0 = fmaxf(mx0, __shfl_xor_sync(0xffffffffu, mx0, 2));
        mx1 = fmaxf(mx1, __shfl_xor_sync(0xffffffffu, mx1, 1));
        mx1 = fmaxf(mx1, __shfl_xor_sync(0xffffffffu, mx1, 2));
        const float fac0 = __expf(m0 - mx0);
        const float fac1 = __expf(m1 - mx1);
        float sum0 = 0.f, sum1 = 0.f;
#pragma unroll
        for (int j = 0; j < 8; j++) {
            s[j][0] = __expf(s[j][0] - mx0);
            s[j][1] = __expf(s[j][1] - mx0);
            s[j][2] = __expf(s[j][2] - mx1);
            s[j][3] = __expf(s[j][3] - mx1);
            sum0 += s[j][0] + s[j][1];
            sum1 += s[j][2] + s[j][3];
        }
        sum0 += __shfl_xor_sync(0xffffffffu, sum0, 1);
        sum0 += __shfl_xor_sync(0xffffffffu, sum0, 2);
        sum1 += __shfl_xor_sync(0xffffffffu, sum1, 1);
        sum1 += __shfl_xor_sync(0xffffffffu, sum1, 2);
        l0 = l0 * fac0 + sum0;
        l1 = l1 * fac1 + sum1;
        m0 = mx0; m1 = mx1;
#pragma unroll
        for (int j = 0; j < 8; j++) {
            o[j][0] *= fac0; o[j][1] *= fac0;
            o[j][2] *= fac1; o[j][3] *= fac1;
        }

#pragma unroll
        for (int kk = 0; kk < 4; kk++) {
            uint32_t vh_[8][2], vl_[8][2];
#pragma unroll
            for (int nn = 0; nn < 4; nn++) {
                LDSM_X4T(vh_[2*nn][0], vh_[2*nn][1], vh_[2*nn+1][0], vh_[2*nn+1][1],
                         st + 18432u + vaoff + (uint32_t)kk * (16 * 144) + nn * 32);
                LDSM_X4T(vl_[2*nn][0], vl_[2*nn][1], vl_[2*nn+1][0], vl_[2*nn+1][1],
                         st + 27648u + vaoff + (uint32_t)kk * (16 * 144) + nn * 32);
            }
            const int j0 = 2 * kk, j1 = 2 * kk + 1;
            uint32_t ph[4], pl[4];
            ph[0] = pack_bf16x2(s[j0][0], s[j0][1]);
            ph[1] = pack_bf16x2(s[j0][2], s[j0][3]);
            ph[2] = pack_bf16x2(s[j1][0], s[j1][1]);
            ph[3] = pack_bf16x2(s[j1][2], s[j1][3]);
            {
                const float r00 = s[j0][0] - __bfloat162float(__float2bfloat16(s[j0][0]));
                const float r01 = s[j0][1] - __bfloat162float(__float2bfloat16(s[j0][1]));
                const float r02 = s[j0][2] - __bfloat162float(__float2bfloat16(s[j0][2]));
                const float r03 = s[j0][3] - __bfloat162float(__float2bfloat16(s[j0][3]));
                const float r10 = s[j1][0] - __bfloat162float(__float2bfloat16(s[j1][0]));
                const float r11 = s[j1][1] - __bfloat162float(__float2bfloat16(s[j1][1]));
                const float r12 = s[j1][2] - __bfloat162float(__float2bfloat16(s[j1][2]));
                const float r13 = s[j1][3] - __bfloat162float(__float2bfloat16(s[j1][3]));
                pl[0] = pack_bf16x2(r00, r01);
                pl[1] = pack_bf16x2(r02, r03);
                pl[2] = pack_bf16x2(r10, r11);
                pl[3] = pack_bf16x2(r12, r13);
            }
#pragma unroll
            for (int j = 0; j < 8; j++) MMA16816(o[j], ph, vh_[j]);
#pragma unroll
            for (int j = 0; j < 8; j++) MMA16816(o[j], ph, vl_[j]);
#pragma unroll
            for (int j = 0; j < 8; j++) MMA16816(o[j], pl, vh_[j]);
        }
    }

    const float inv0 = 1.f / l0, inv1 = 1.f / l1;
    const int g = lane >> 2, t4 = lane & 3;
    const size_t row0 = rowbase + qt * 128 + warp_m + g;
#pragma unroll
    for (int j = 0; j < 8; j++) {
        const int col = cb + 8 * j + 2 * t4;
        const float v0 = o[j][0] * inv0, v1 = o[j][1] * inv0;
        const float v2 = o[j][2] * inv1, v3 = o[j][3] * inv1;
        __nv_bfloat16 h0, h1, h2, h3, l0b, l1b, l2b, l3b;
        split1(v0, h0, l0b); split1(v1, h1, l1b);
        split1(v2, h2, l2b); split1(v3, h3, l3b);
        __nv_bfloat162 hp0; hp0.x = h0; hp0.y = h1;
        __nv_bfloat162 hp1; hp1.x = h2; hp1.y = h3;
        __nv_bfloat162 lp0; lp0.x = l0b; lp0.y = l1b;
        __nv_bfloat162 lp1; lp1.x = l2b; lp1.y = l3b;
        *(__nv_bfloat162*)(Ohi + row0 * kD + col)       = hp0;
        *(__nv_bfloat162*)(Olo + row0 * kD + col)       = lp0;
        *(__nv_bfloat162*)(Ohi + (row0 + 8) * kD + col) = hp1;
        *(__nv_bfloat162*)(Olo + (row0 + 8) * kD + col) = lp1;
    }
}

// ---------------------------------------------------------------------------
// Host launcher
// ---------------------------------------------------------------------------
extern "C" void kernel_launch(void* const* d_in, const int* in_sizes, int n_in,
                              void* d_out, int out_size)
{
    (void)in_sizes; (void)n_in; (void)out_size;
    const float* x    = (const float*)d_in[0];
    const float* Wq   = (const float*)d_in[1];
    const float* bq   = (const float*)d_in[2];
    const float* Wk   = (const float*)d_in[3];
    const float* Wv   = (const float*)d_in[4];
    const float* bv   = (const float*)d_in[5];
    const float* Wo   = (const float*)d_in[6];
    const float* bo   = (const float*)d_in[7];
    const float* la_k = (const float*)d_in[8];
    const float* lb_k = (const float*)d_in[9];
    const float* la_v = (const float*)d_in[10];
    const float* lb_v = (const float*)d_in[11];
    const float* la_o = (const float*)d_in[12];
    const float* lb_o = (const float*)d_in[13];
    const float* ga   = (const float*)d_in[14];
    const float* ba   = (const float*)d_in[15];
    const float* W1   = (const float*)d_in[16];
    const float* b1   = (const float*)d_in[17];
    const float* W2   = (const float*)d_in[18];
    const float* b2   = (const float*)d_in[19];
    const float* gm   = (const float*)d_in[20];
    const float* bmn  = (const float*)d_in[21];
    float* out = (float*)d_out;

    static float *p_x1 = nullptr, *p_u;
    static __nv_bfloat16 *pa_hi, *pa_lo, *pw_hi, *pw_lo, *pu_hi, *pu_lo;
    static __nv_bfloat16 *pq_hi, *pq_lo, *pk_hi, *pk_lo, *pv_hi, *pv_lo;
    if (!p_x1) {
        float* tmp;
        cudaGetSymbolAddress((void**)&tmp, g_q);
        pq_hi = (__nv_bfloat16*)tmp; pq_lo = pq_hi + (size_t)kM * kD;
        cudaGetSymbolAddress((void**)&tmp, g_k);
        pk_hi = (__nv_bfloat16*)tmp; pk_lo = pk_hi + (size_t)kM * kD;
        cudaGetSymbolAddress((void**)&tmp, g_v);
        pv_hi = (__nv_bfloat16*)tmp; pv_lo = pv_hi + (size_t)kM * kD;
        cudaGetSymbolAddress((void**)&p_u,   g_u);
        pu_hi = (__nv_bfloat16*)p_u; pu_lo = pu_hi + (size_t)kM * kDff;
        cudaGetSymbolAddress((void**)&pa_hi, g_a_hi);
        cudaGetSymbolAddress((void**)&pa_lo, g_a_lo);
        cudaGetSymbolAddress((void**)&pw_hi, g_w_hi);
        cudaGetSymbolAddress((void**)&pw_lo, g_w_lo);
        cudaFuncSetAttribute(attn_mma,
                             cudaFuncAttributeMaxDynamicSharedMemorySize, aSMEM);
        cudaFuncSetAttribute(gemm_mma<0, 0>,
                             cudaFuncAttributeMaxDynamicSharedMemorySize, 2 * kStage2);
        cudaFuncSetAttribute(gemm_mma<0, 1>,
                             cudaFuncAttributeMaxDynamicSharedMemorySize, 2 * kStage2);
        cudaFuncSetAttribute(gemm_mma<1, 1>,
                             cudaFuncAttributeMaxDynamicSharedMemorySize, 2 * kStage2);
        cudaGetSymbolAddress((void**)&p_x1,  g_x1);   // init flag last
    }

    const dim3 blk(256);
    const dim3 gD(kD / 128, kM / 128);      // (8, 64)
    const dim3 gF(kDff / 128, kM / 128);    // (32, 64)
    const int nWDD  = kD * kD / 4;
    const int nWDF  = kDff * kD / 4;
    const unsigned SMEM_G = 2 * kStage2;    // 81920 B per CTA -> 2 CTAs/SM

    // ---- attention half ----
    ln_split_kernel<<<kM, blk>>>(x, ga, ba, pa_hi, pa_lo);

    split_kernel<<<nWDD / 256, blk>>>(Wq, pw_hi, pw_lo, nWDD);
    gemm_mma<0, 1><<<gD, blk, SMEM_G>>>(pa_hi, pa_lo, pw_hi, pw_lo,
                                        bq, nullptr,
                                        nullptr, pq_hi, pq_lo, kM, kD, kD);

    split_lora_kernel<<<nWDD / 256, blk>>>(Wk, la_k, lb_k, pw_hi, pw_lo);
    gemm_mma<0, 1><<<gD, blk, SMEM_G>>>(pa_hi, pa_lo, pw_hi, pw_lo,
                                        nullptr, nullptr,
                                        nullptr, pk_hi, pk_lo, kM, kD, kD);

    split_lora_kernel<<<nWDD / 256, blk>>>(Wv, la_v, lb_v, pw_hi, pw_lo);
    gemm_mma<0, 1><<<gD, blk, SMEM_G>>>(pa_hi, pa_lo, pw_hi, pw_lo,
                                        bv, nullptr,
                                        nullptr, pv_hi, pv_lo, kM, kD, kD);

    attn_mma<<<dim3(8, kB * kH), blk, aSMEM>>>(pq_hi, pq_lo, pk_hi, pk_lo,
                                               pv_hi, pv_lo, pa_hi, pa_lo);

    split_lora_kernel<<<nWDD / 256, blk>>>(Wo, la_o, lb_o, pw_hi, pw_lo);
    gemm_mma<0, 0><<<gD, blk, SMEM_G>>>(pa_hi, pa_lo, pw_hi, pw_lo,
                                        bo, x,
                                        p_x1, nullptr, nullptr, kM, kD, kD);

    // ---- MLP half ----
    ln_split_kernel<<<kM, blk>>>(p_x1, gm, bmn, pa_hi, pa_lo);
    split_kernel<<<nWDF / 256, blk>>>(W1, pw_hi, pw_lo, nWDF);
    gemm_mma<1, 1><<<gF, blk, SMEM_G>>>(pa_hi, pa_lo, pw_hi, pw_lo,
                                        b1, nullptr,
                                        nullptr, pu_hi, pu_lo, kM, kDff, kD);

    split_kernel<<<nWDF / 256, blk>>>(W2, pw_hi, pw_lo, nWDF);
    gemm_mma<0, 0><<<gD, blk, SMEM_G>>>(pu_hi, pu_lo, pw_hi, pw_lo,
                                        b2, p_x1,
                                        out, nullptr, nullptr, kM, kD, kDff);
}

// round 14
// speedup vs baseline: 3.2482x; 1.0287x over previous
#include <cuda_runtime.h>
#include <cuda_bf16.h>
#include <cstdint>
#include <math.h>

// ---------------------------------------------------------------------------
// Shapes (fixed by the problem)
// ---------------------------------------------------------------------------
namespace {
constexpr int kD   = 1024;
constexpr int kDff = 4096;
constexpr int kB   = 8;
constexpr int kS   = 1024;
constexpr int kM   = kB * kS;   // 8192 rows
constexpr int kH   = 16;        // heads
}

// ---------------------------------------------------------------------------
// Scratch (static device globals -- no allocation allowed)
// ---------------------------------------------------------------------------
__device__ float g_q [(size_t)kM * kD];     // reused: bf16 q_hi / q_lo
__device__ float g_k [(size_t)kM * kD];     // reused: bf16 k_hi / k_lo
__device__ float g_v [(size_t)kM * kD];     // reused: bf16 v_hi / v_lo
__device__ float g_x1[(size_t)kM * kD];
__device__ float g_u [(size_t)kM * kDff];   // reused: bf16 u_hi / u_lo
__device__ __nv_bfloat16 g_a_hi[(size_t)kM * kD];
__device__ __nv_bfloat16 g_a_lo[(size_t)kM * kD];
// per-weight split buffers (so weight splits can overlap compute)
__device__ __nv_bfloat16 g_wq_hi[(size_t)kD * kD],  g_wq_lo[(size_t)kD * kD];
__device__ __nv_bfloat16 g_wk_hi[(size_t)kD * kD],  g_wk_lo[(size_t)kD * kD];
__device__ __nv_bfloat16 g_wv_hi[(size_t)kD * kD],  g_wv_lo[(size_t)kD * kD];
__device__ __nv_bfloat16 g_wo_hi[(size_t)kD * kD],  g_wo_lo[(size_t)kD * kD];
__device__ __nv_bfloat16 g_w1_hi[(size_t)kDff * kD], g_w1_lo[(size_t)kDff * kD];
__device__ __nv_bfloat16 g_w2_hi[(size_t)kDff * kD], g_w2_lo[(size_t)kDff * kD];

// ---------------------------------------------------------------------------
// PTX helpers (portable sm_80+: cp.async / ldmatrix / mma.sync)
// ---------------------------------------------------------------------------
__device__ __forceinline__ uint32_t smem_u32(const void* p) {
    uint32_t a;
    asm("{ .reg .u64 t; cvta.to.shared.u64 t, %1; cvt.u32.u64 %0, t; }"
        : "=r"(a) : "l"(p));
    return a;
}

#define CP_ASYNC16(saddr, gptr) \
    asm volatile("cp.async.cg.shared.global [%0], [%1], 16;" \
        :: "r"(saddr), "l"(gptr))

#define CP_COMMIT() asm volatile("cp.async.commit_group;" ::: "memory")

#define LDSM_X4(r0, r1, r2, r3, addr) \
    asm volatile("ldmatrix.sync.aligned.m8n8.x4.shared.b16 {%0,%1,%2,%3}, [%4];" \
        : "=r"(r0), "=r"(r1), "=r"(r2), "=r"(r3) : "r"(addr))

#define LDSM_X4T(r0, r1, r2, r3, addr) \
    asm volatile("ldmatrix.sync.aligned.m8n8.x4.trans.shared.b16 {%0,%1,%2,%3}, [%4];" \
        : "=r"(r0), "=r"(r1), "=r"(r2), "=r"(r3) : "r"(addr))

#define MMA16816(d, a, b) \
    asm volatile("mma.sync.aligned.m16n8k16.row.col.f32.bf16.bf16.f32 " \
        "{%0,%1,%2,%3}, {%4,%5,%6,%7}, {%8,%9}, {%0,%1,%2,%3};" \
        : "+f"((d)[0]), "+f"((d)[1]), "+f"((d)[2]), "+f"((d)[3]) \
        : "r"((a)[0]), "r"((a)[1]), "r"((a)[2]), "r"((a)[3]), \
          "r"((b)[0]), "r"((b)[1]))

__device__ __forceinline__ void split1(float v, __nv_bfloat16& h, __nv_bfloat16& l) {
    h = __float2bfloat16(v);
    l = __float2bfloat16(v - __bfloat162float(h));
}

__device__ __forceinline__ uint32_t pack_bf16x2(float a, float b) {
    __nv_bfloat162 t = __floats2bfloat162_rn(a, b);   // .x = a (low half)
    return *(uint32_t*)&t;
}

__device__ __forceinline__ void st_shared_v4(uint32_t addr, uint4 v) {
    asm volatile("st.shared.v4.b32 [%0], {%1, %2, %3, %4};"
        :: "r"(addr), "r"(v.x), "r"(v.y), "r"(v.z), "r"(v.w));
}

// ---------------------------------------------------------------------------
// fp32 -> (bf16 hi, bf16 lo) split (plain weights / no LoRA)
// ---------------------------------------------------------------------------
__global__ void split_kernel(const float* __restrict__ x, __nv_bfloat16* __restrict__ hi,
                             __nv_bfloat16* __restrict__ lo, int n4)
{
    const int i = blockIdx.x * 256 + threadIdx.x;
    if (i >= n4) return;
    float4 v = ((const float4*)x)[i];
    __nv_bfloat16 h0, h1, h2, h3, l0, l1, l2, l3;
    split1(v.x, h0, l0); split1(v.y, h1, l1);
    split1(v.z, h2, l2); split1(v.w, h3, l3);
    __nv_bfloat162 hp0; hp0.x = h0; hp0.y = h1;
    __nv_bfloat162 hp1; hp1.x = h2; hp1.y = h3;
    __nv_bfloat162 lp0; lp0.x = l0; lp0.y = l1;
    __nv_bfloat162 lp1; lp1.x = l2; lp1.y = l3;
    ((__nv_bfloat162*)hi)[i * 2 + 0] = hp0;
    ((__nv_bfloat162*)hi)[i * 2 + 1] = hp1;
    ((__nv_bfloat162*)lo)[i * 2 + 0] = lp0;
    ((__nv_bfloat162*)lo)[i * 2 + 1] = lp1;
}

// ---------------------------------------------------------------------------
// Weight split with fused rank-4 LoRA fold:
//   W'[n,k] = W[n,k] + 0.25 * sum_r lb[n,r] * la[r,k]   (D x D weights only)
// ---------------------------------------------------------------------------
__global__ void split_lora_kernel(const float* __restrict__ W,
                                  const float* __restrict__ la,
                                  const float* __restrict__ lb,
                                  __nv_bfloat16* __restrict__ hi,
                                  __nv_bfloat16* __restrict__ lo)
{
    const int i = blockIdx.x * 256 + threadIdx.x;   // over D*D/4
    const int n  = i >> 8;            // row (D/4 = 256 float4 per row)
    const int k4 = (i & 255) * 4;
    float4 v = ((const float4*)W)[i];
    float4 lbv = ((const float4*)lb)[n];
    float4 a0 = *(const float4*)(la + 0 * kD + k4);
    float4 a1 = *(const float4*)(la + 1 * kD + k4);
    float4 a2 = *(const float4*)(la + 2 * kD + k4);
    float4 a3 = *(const float4*)(la + 3 * kD + k4);
    v.x += 0.25f * (lbv.x * a0.x + lbv.y * a1.x + lbv.z * a2.x + lbv.w * a3.x);
    v.y += 0.25f * (lbv.x * a0.y + lbv.y * a1.y + lbv.z * a2.y + lbv.w * a3.y);
    v.z += 0.25f * (lbv.x * a0.z + lbv.y * a1.z + lbv.z * a2.z + lbv.w * a3.z);
    v.w += 0.25f * (lbv.x * a0.w + lbv.y * a1.w + lbv.z * a2.w + lbv.w * a3.w);
    __nv_bfloat16 h0, h1, h2, h3, l0, l1, l2, l3;
    split1(v.x, h0, l0); split1(v.y, h1, l1);
    split1(v.z, h2, l2); split1(v.w, h3, l3);
    __nv_bfloat162 hp0; hp0.x = h0; hp0.y = h1;
    __nv_bfloat162 hp1; hp1.x = h2; hp1.y = h3;
    __nv_bfloat162 lp0; lp0.x = l0; lp0.y = l1;
    __nv_bfloat162 lp1; lp1.x = l2; lp1.y = l3;
    ((__nv_bfloat162*)hi)[i * 2 + 0] = hp0;
    ((__nv_bfloat162*)hi)[i * 2 + 1] = hp1;
    ((__nv_bfloat162*)lo)[i * 2 + 0] = lp0;
    ((__nv_bfloat162*)lo)[i * 2 + 1] = lp1;
}

// ---------------------------------------------------------------------------
// Tensor-core GEMM (mma.sync bf16, split hi/lo 3-term):
//   C = A @ B^T (+bias) (+GELU) (+res); SPLIT=1 -> bf16 hi/lo out
// CTA tile 128x128, warp tile 64x32 (8 warps = 2x4), BK=32,
// 2-stage cp.async ring, __launch_bounds__(256,2) -> 2 CTAs/SM.
// ---------------------------------------------------------------------------
namespace {
constexpr int      kRowB   = 80;
constexpr uint32_t kTile128 = 128 * kRowB;              // 10240
constexpr uint32_t kStage2  = 4 * kTile128;             // 40960 per stage
constexpr uint32_t oAl2 = kTile128;                     // 10240
constexpr uint32_t oBh2 = 2 * kTile128;                 // 20480
constexpr uint32_t oBl2 = 3 * kTile128;                 // 30720
}

template <int GELU, int SPLIT>
__global__ void __launch_bounds__(256, 2)
gemm_mma(const __nv_bfloat16* __restrict__ Ahi, const __nv_bfloat16* __restrict__ Alo,
         const __nv_bfloat16* __restrict__ Bhi, const __nv_bfloat16* __restrict__ Blo,
         const float* __restrict__ bias, const float* __restrict__ res,
         float* __restrict__ C,
         __nv_bfloat16* __restrict__ Chi, __nv_bfloat16* __restrict__ Clo,
         int M, int N, int K)
{
    extern __shared__ char smem[];
    const uint32_t sbase = smem_u32(smem);
    const int tid  = threadIdx.x;
    const int lane = tid & 31;
    const int wid  = tid >> 5;
    const int bm = blockIdx.y * 128;
    const int bn = blockIdx.x * 128;
    const int warp_m = (wid >> 2) * 64;    // 0 or 64
    const int warp_n = (wid & 3) * 32;     // 0,32,64,96

    const int r0 = tid >> 2;               // 0..63
    const int c8 = (tid & 3) * 8;
    const uint32_t so = (uint32_t)(r0 * kRowB + (tid & 3) * 16);

    float acc[4][4][4];
#pragma unroll
    for (int i = 0; i < 4; i++)
#pragma unroll
        for (int j = 0; j < 4; j++)
#pragma unroll
            for (int r = 0; r < 4; r++) acc[i][j][r] = 0.f;

    const uint32_t a_off = (uint32_t)((warp_m + (lane & 15)) * kRowB + (lane >> 4) * 16);
    const uint32_t b_off = (uint32_t)((warp_n + (lane & 7) + ((lane >> 4) & 1) * 8) * kRowB
                                      + ((lane >> 3) & 1) * 16);

    const int nIter = K >> 5;

    auto load_stage = [&](int it, int s) {
        const int k0 = it << 5;
        const uint32_t sbuf = sbase + (uint32_t)s * kStage2;
        const size_t ga0 = (size_t)(bm + r0) * K + k0 + c8;
        const size_t ga1 = ga0 + (size_t)64 * K;
        const size_t gb0 = (size_t)(bn + r0) * K + k0 + c8;
        const size_t gb1 = gb0 + (size_t)64 * K;
        const uint32_t so1 = so + 64u * kRowB;
        CP_ASYNC16(sbuf +        so,  Ahi + ga0);
        CP_ASYNC16(sbuf +        so1, Ahi + ga1);
        CP_ASYNC16(sbuf + oAl2 + so,  Alo + ga0);
        CP_ASYNC16(sbuf + oAl2 + so1, Alo + ga1);
        CP_ASYNC16(sbuf + oBh2 + so,  Bhi + gb0);
        CP_ASYNC16(sbuf + oBh2 + so1, Bhi + gb1);
        CP_ASYNC16(sbuf + oBl2 + so,  Blo + gb0);
        CP_ASYNC16(sbuf + oBl2 + so1, Blo + gb1);
        CP_COMMIT();
    };

    load_stage(0, 0);

    for (int it = 0; it < nIter; ++it) {
        if (it + 1 < nIter) {
            load_stage(it + 1, (it + 1) & 1);
            asm volatile("cp.async.wait_group 1;" ::: "memory");
        } else {
            asm volatile("cp.async.wait_group 0;" ::: "memory");
        }
        __syncthreads();

        const uint32_t sbuf = sbase + (uint32_t)(it & 1) * kStage2;
        const uint32_t abase = sbuf + a_off;
        const uint32_t bbase = sbuf + oBh2 + b_off;

#pragma unroll
        for (int ks = 0; ks < 2; ks++) {
            const uint32_t ko = (uint32_t)ks * 32;
            uint32_t ah[4][4], al[4][4], bh[4][2], bl[4][2];
#pragma unroll
            for (int i = 0; i < 4; i++) {
                LDSM_X4(ah[i][0], ah[i][1], ah[i][2], ah[i][3],
                        abase + (uint32_t)i * (16 * kRowB) + ko);
            }
#pragma unroll
            for (int p = 0; p < 2; p++) {
                LDSM_X4(bh[2*p][0], bh[2*p][1], bh[2*p+1][0], bh[2*p+1][1],
                        bbase + (uint32_t)p * (16 * kRowB) + ko);
            }
#pragma unroll
            for (int i = 0; i < 4; i++) {
                LDSM_X4(al[i][0], al[i][1], al[i][2], al[i][3],
                        abase + oAl2 + (uint32_t)i * (16 * kRowB) + ko);
            }
#pragma unroll
            for (int p = 0; p < 2; p++) {
                LDSM_X4(bl[2*p][0], bl[2*p][1], bl[2*p+1][0], bl[2*p+1][1],
                        bbase + kTile128 + (uint32_t)p * (16 * kRowB) + ko);
            }
            // term 1: Ahi * Bhi
#pragma unroll
            for (int i = 0; i < 4; i++)
#pragma unroll
                for (int j = 0; j < 4; j++)
                    MMA16816(acc[i][j], ah[i], bh[j]);
            // term 2: Ahi * Blo
#pragma unroll
            for (int i = 0; i < 4; i++)
#pragma unroll
                for (int j = 0; j < 4; j++)
                    MMA16816(acc[i][j], ah[i], bl[j]);
            // term 3: Alo * Bhi
#pragma unroll
            for (int i = 0; i < 4; i++)
#pragma unroll
                for (int j = 0; j < 4; j++)
                    MMA16816(acc[i][j], al[i], bh[j]);
        }
        __syncthreads();
    }

    // ---- epilogue
    const int g  = lane >> 2;
    const int t4 = lane & 3;
#pragma unroll
    for (int i = 0; i < 4; i++) {
        const int mlo = bm + warp_m + 16 * i + g;
        const int mhi = mlo + 8;
#pragma unroll
        for (int j = 0; j < 4; j++) {
            const int n0 = bn + warp_n + 8 * j + 2 * t4;
            float b0 = 0.f, b1 = 0.f;
            if (bias) { b0 = bias[n0]; b1 = bias[n0 + 1]; }
            float v0 = acc[i][j][0] + b0;
            float v1 = acc[i][j][1] + b1;
            float v2 = acc[i][j][2] + b0;
            float v3 = acc[i][j][3] + b1;
            if (GELU) {
                v0 = 0.5f * v0 * (1.f + erff(v0 * 0.70710678118f));
                v1 = 0.5f * v1 * (1.f + erff(v1 * 0.70710678118f));
                v2 = 0.5f * v2 * (1.f + erff(v2 * 0.70710678118f));
                v3 = 0.5f * v3 * (1.f + erff(v3 * 0.70710678118f));
            }
            const size_t olo = (size_t)mlo * N + n0;
            const size_t ohi = (size_t)mhi * N + n0;
            if (SPLIT) {
                __nv_bfloat16 h0, h1, h2, h3, l0, l1, l2, l3;
                split1(v0, h0, l0); split1(v1, h1, l1);
                split1(v2, h2, l2); split1(v3, h3, l3);
                __nv_bfloat162 hp0; hp0.x = h0; hp0.y = h1;
                __nv_bfloat162 hp1; hp1.x = h2; hp1.y = h3;
                __nv_bfloat162 lp0; lp0.x = l0; lp0.y = l1;
                __nv_bfloat162 lp1; lp1.x = l2; lp1.y = l3;
                *(__nv_bfloat162*)(Chi + olo) = hp0;
                *(__nv_bfloat162*)(Chi + ohi) = hp1;
                *(__nv_bfloat162*)(Clo + olo) = lp0;
                *(__nv_bfloat162*)(Clo + ohi) = lp1;
            } else {
                if (res) {
                    float2 r0_ = *(const float2*)(res + olo);
                    float2 r1_ = *(const float2*)(res + ohi);
                    v0 += r0_.x; v1 += r0_.y; v2 += r1_.x; v3 += r1_.y;
                }
                *(float2*)(C + olo) = make_float2(v0, v1);
                *(float2*)(C + ohi) = make_float2(v2, v3);
            }
        }
    }
}

// ---------------------------------------------------------------------------
// LayerNorm -> split bf16 hi/lo directly
// ---------------------------------------------------------------------------
__global__ void ln_split_kernel(const float* __restrict__ x, const float* __restrict__ g,
                                const float* __restrict__ b,
                                __nv_bfloat16* __restrict__ yhi,
                                __nv_bfloat16* __restrict__ ylo)
{
    const int row = blockIdx.x;
    const int tid = threadIdx.x;
    float4 v = ((const float4*)(x + (size_t)row * kD))[tid];
    float s  = v.x + v.y + v.z + v.w;
    float sq = v.x*v.x + v.y*v.y + v.z*v.z + v.w*v.w;
#pragma unroll
    for (int o = 16; o; o >>= 1) {
        s  += __shfl_xor_sync(0xffffffffu, s,  o);
        sq += __shfl_xor_sync(0xffffffffu, sq, o);
    }
    __shared__ float ss[8], ssq[8];
    const int w = tid >> 5, lane = tid & 31;
    if (lane == 0) { ss[w] = s; ssq[w] = sq; }
    __syncthreads();
    if (w == 0) {
        float a = (lane < 8) ? ss[lane]  : 0.f;
        float c = (lane < 8) ? ssq[lane] : 0.f;
#pragma unroll
        for (int o = 4; o; o >>= 1) {
            a += __shfl_xor_sync(0xffffffffu, a, o);
            c += __shfl_xor_sync(0xffffffffu, c, o);
        }
        if (lane == 0) { ss[0] = a; ssq[0] = c; }
    }
    __syncthreads();
    const float mean = ss[0] * (1.f / kD);
    const float var  = ssq[0] * (1.f / kD) - mean * mean;
    const float rstd = rsqrtf(var + 1e-5f);
    float4 gv = ((const float4*)g)[tid];
    float4 bv = ((const float4*)b)[tid];
    float y0 = (v.x - mean) * rstd * gv.x + bv.x;
    float y1 = (v.y - mean) * rstd * gv.y + bv.y;
    float y2 = (v.z - mean) * rstd * gv.z + bv.z;
    float y3 = (v.w - mean) * rstd * gv.w + bv.w;
    __nv_bfloat16 h0, h1, h2, h3, l0, l1, l2, l3;
    split1(y0, h0, l0); split1(y1, h1, l1);
    split1(y2, h2, l2); split1(y3, h3, l3);
    __nv_bfloat162 hp0; hp0.x = h0; hp0.y = h1;
    __nv_bfloat162 hp1; hp1.x = h2; hp1.y = h3;
    __nv_bfloat162 lp0; lp0.x = l0; lp0.y = l1;
    __nv_bfloat162 lp1; lp1.x = l2; lp1.y = l3;
    ((__nv_bfloat162*)(yhi + (size_t)row * kD))[tid * 2 + 0] = hp0;
    ((__nv_bfloat162*)(yhi + (size_t)row * kD))[tid * 2 + 1] = hp1;
    ((__nv_bfloat162*)(ylo + (size_t)row * kD))[tid * 2 + 0] = lp0;
    ((__nv_bfloat162*)(ylo + (size_t)row * kD))[tid * 2 + 1] = lp1;
}

// ---------------------------------------------------------------------------
// Tensor-core flash attention (split-bf16 3-term for QK^T and PV).
// Block: 128 q-rows of one (b,h); 8 warps, each 16 q-rows x 64 keys.
// ---------------------------------------------------------------------------
namespace {
constexpr uint32_t aQH  = 0;
constexpr uint32_t aQL  = 18432;           // 128*144
constexpr uint32_t aKV0 = 36864;           // + stage*36864; Kh,Kl,Vh,Vl @ +9216 each
constexpr uint32_t aSMEM = 36864 + 2 * 36864;  // 110592
}

__global__ void __launch_bounds__(256)
attn_mma(const __nv_bfloat16* __restrict__ Qhi, const __nv_bfloat16* __restrict__ Qlo,
         const __nv_bfloat16* __restrict__ Khi, const __nv_bfloat16* __restrict__ Klo,
         const __nv_bfloat16* __restrict__ Vhi, const __nv_bfloat16* __restrict__ Vlo,
         __nv_bfloat16* __restrict__ Ohi, __nv_bfloat16* __restrict__ Olo)
{
    extern __shared__ char smem[];
    const uint32_t sb = smem_u32(smem);
    const int tid  = threadIdx.x;
    const int lane = tid & 31;
    const int wid  = tid >> 5;           // 0..7
    const int qt = blockIdx.x;           // 0..7
    const int bh = blockIdx.y;
    const int b  = bh >> 4, h = bh & 15;
    const size_t rowbase = (size_t)b * kS;
    const int cb = h * 64;
    const int warp_m = wid * 16;

    {
        const __nv_bfloat162 sc = __float2bfloat162_rn(0.125f);
#pragma unroll
        for (int i = tid; i < 1024; i += 256) {
            const int r = i >> 3, c = i & 7;
            const size_t go = (rowbase + qt * 128 + r) * kD + cb + c * 8;
            const uint32_t so = (uint32_t)(r * 144 + c * 16);
            uint4 vh = *(const uint4*)(Qhi + go);
            uint4 vl = *(const uint4*)(Qlo + go);
            __nv_bfloat162* ph = (__nv_bfloat162*)&vh;
            __nv_bfloat162* pl = (__nv_bfloat162*)&vl;
#pragma unroll
            for (int k = 0; k < 4; k++) { ph[k] = __hmul2(ph[k], sc); pl[k] = __hmul2(pl[k], sc); }
            st_shared_v4(sb + aQH + so, vh);
            st_shared_v4(sb + aQL + so, vl);
        }
    }

    auto load_kv = [&](int kt, int s) {
        const uint32_t st = sb + aKV0 + (uint32_t)s * 36864u;
#pragma unroll
        for (int i = tid; i < 512; i += 256) {
            const int r = i >> 3, c = i & 7;
            const size_t go = (rowbase + kt * 64 + r) * kD + cb + c * 8;
            const uint32_t so = (uint32_t)(r * 144 + c * 16);
            CP_ASYNC16(st +          so, Khi + go);
            CP_ASYNC16(st +  9216u + so, Klo + go);
            CP_ASYNC16(st + 18432u + so, Vhi + go);
            CP_ASYNC16(st + 27648u + so, Vlo + go);
        }
        CP_COMMIT();
    };
    load_kv(0, 0);
    __syncthreads();

    uint32_t qh[4][4], ql[4][4];
    {
        const uint32_t qa = sb + (uint32_t)((warp_m + (lane & 15)) * 144 + (lane >> 4) * 16);
#pragma unroll
        for (int kk = 0; kk < 4; kk++) {
            LDSM_X4(qh[kk][0], qh[kk][1], qh[kk][2], qh[kk][3], qa + aQH + kk * 32);
            LDSM_X4(ql[kk][0], ql[kk][1], ql[kk][2], ql[kk][3], qa + aQL + kk * 32);
        }
    }

    float m0 = -1e30f, m1 = -1e30f, l0 = 0.f, l1 = 0.f;
    float o[8][4];
#pragma unroll
    for (int j = 0; j < 8; j++)
#pragma unroll
        for (int c = 0; c < 4; c++) o[j][c] = 0.f;

    const uint32_t kboff = (uint32_t)(((lane & 7) + ((lane >> 4) & 1) * 8) * 144
                                      + ((lane >> 3) & 1) * 16);
    const uint32_t vaoff = (uint32_t)((lane & 15) * 144 + (lane >> 4) * 16);

    for (int kt = 0; kt < 16; kt++) {
        asm volatile("cp.async.wait_group 0;" ::: "memory");
        __syncthreads();
        if (kt + 1 < 16) load_kv(kt + 1, (kt + 1) & 1);
        const uint32_t st = sb + aKV0 + (uint32_t)(kt & 1) * 36864u;

        float s[8][4];
#pragma unroll
        for (int j = 0; j < 8; j++)
#pragma unroll
            for (int c = 0; c < 4; c++) s[j][c] = 0.f;

#pragma unroll
        for (int kk = 0; kk < 4; kk++) {
            uint32_t bh_[8][2], bl_[8][2];
#pragma unroll
            for (int p = 0; p < 4; p++) {
                LDSM_X4(bh_[2*p][0], bh_[2*p][1], bh_[2*p+1][0], bh_[2*p+1][1],
                        st + kboff + (uint32_t)p * (16 * 144) + kk * 32);
                LDSM_X4(bl_[2*p][0], bl_[2*p][1], bl_[2*p+1][0], bl_[2*p+1][1],
                        st + 9216u + kboff + (uint32_t)p * (16 * 144) + kk * 32);
            }
#pragma unroll
            for (int j = 0; j < 8; j++) MMA16816(s[j], qh[kk], bh_[j]);
#pragma unroll
            for (int j = 0; j < 8; j++) MMA16816(s[j], qh[kk], bl_[j]);
#pragma unroll
            for (int j = 0; j < 8; j++) MMA16816(s[j], ql[kk], bh_[j]);
        }

        float mx0 = m0, mx1 = m1;
#pragma unroll
        for (int j = 0; j < 8; j++) {
            mx0 = fmaxf(mx0, fmaxf(s[j][0], s[j][1]));
            mx1 = fmaxf(mx1, fmaxf(s[j][2], s[j][3]));
        }
        mx0 = fmaxf(mx0, __shfl_xor_sync(0xffffffffu, mx0, 1));
        mx0 = fmaxf(mx0, __shfl_xor_sync(0xffffffffu, mx0, 2));
        mx1 = fmaxf(mx1, __shfl_xor_sync(0xffffffffu, mx1, 1));
        mx1 = fmaxf(mx1, __shfl_xor_sync(0xffffffffu, mx1, 2));
        const float fac0 = __expf(m0 - mx0);
        const float fac1 = __expf(m1 - mx1);
        float sum0 = 0.f, sum1 = 0.f;
#pragma unroll
        for (int j = 0; j < 8; j++) {
            s[j][0] = __expf(s[j][0] - mx0);
            s[j][1] = __expf(s[j][1] - mx0);
            s[j][2] = __expf(s[j][2] - mx1);
            s[j][3] = __expf(s[j][3] - mx1);
            sum0 += s[j][0] + s[j][1];
            sum1 += s[j][2] + s[j][3];
        }
        sum0 += __shfl_xor_sync(0xffffffffu, sum0, 1);
        sum0 += __shfl_xor_sync(0xffffffffu, sum0, 2);
        sum1 += __shfl_xor_sync(0xffffffffu, sum1, 1);
        sum1 += __shfl_xor_sync(0xffffffffu, sum1, 2);
        l0 = l0 * fac0 + sum0;
        l1 = l1 * fac1 + sum1;
        m0 = mx0; m1 = mx1;
#pragma unroll
        for (int j = 0; j < 8; j++) {
            o[j][0] *= fac0; o[j][1] *= fac0;
            o[j][2] *= fac1; o[j][3] *= fac1;
        }

#pragma unroll
        for (int kk = 0; kk < 4; kk++) {
            uint32_t vh_[8][2], vl_[8][2];
#pragma unroll
            for (int nn = 0; nn < 4; nn++) {
                LDSM_X4T(vh_[2*nn][0], vh_[2*nn][1], vh_[2*nn+1][0], vh_[2*nn+1][1],
                         st + 18432u + vaoff + (uint32_t)kk * (16 * 144) + nn * 32);
                LDSM_X4T(vl_[2*nn][0], vl_[2*nn][1], vl_[2*nn+1][0], vl_[2*nn+1][1],
                         st + 27648u + vaoff + (uint32_t)kk * (16 * 144) + nn * 32);
            }
            const int j0 = 2 * kk, j1 = 2 * kk + 1;
            uint32_t ph[4], pl[4];
            ph[0] = pack_bf16x2(s[j0][0], s[j0][1]);
            ph[1] = pack_bf16x2(s[j0][2], s[j0][3]);
            ph[2] = pack_bf16x2(s[j1][0], s[j1][1]);
            ph[3] = pack_bf16x2(s[j1][2], s[j1][3]);
            {
                const float r00 = s[j0][0] - __bfloat162float(__float2bfloat16(s[j0][0]));
                const float r01 = s[j0][1] - __bfloat162float(__float2bfloat16(s[j0][1]));
                const float r02 = s[j0][2] - __bfloat162float(__float2bfloat16(s[j0][2]));
                const float r03 = s[j0][3] - __bfloat162float(__float2bfloat16(s[j0][3]));
                const float r10 = s[j1][0] - __bfloat162float(__float2bfloat16(s[j1][0]));
                const float r11 = s[j1][1] - __bfloat162float(__float2bfloat16(s[j1][1]));
                const float r12 = s[j1][2] - __bfloat162float(__float2bfloat16(s[j1][2]));
                const float r13 = s[j1][3] - __bfloat162float(__float2bfloat16(s[j1][3]));
                pl[0] = pack_bf16x2(r00, r01);
                pl[1] = pack_bf16x2(r02, r03);
                pl[2] = pack_bf16x2(r10, r11);
                pl[3] = pack_bf16x2(r12, r13);
            }
#pragma unroll
            for (int j = 0; j < 8; j++) MMA16816(o[j], ph, vh_[j]);
#pragma unroll
            for (int j = 0; j < 8; j++) MMA16816(o[j], ph, vl_[j]);
#pragma unroll
            for (int j = 0; j < 8; j++) MMA16816(o[j], pl, vh_[j]);
        }
    }

    const float inv0 = 1.f / l0, inv1 = 1.f / l1;
    const int g = lane >> 2, t4 = lane & 3;
    const size_t row0 = rowbase + qt * 128 + warp_m + g;
#pragma unroll
    for (int j = 0; j < 8; j++) {
        const int col = cb + 8 * j + 2 * t4;
        const float v0 = o[j][0] * inv0, v1 = o[j][1] * inv0;
        const float v2 = o[j][2] * inv1, v3 = o[j][3] * inv1;
        __nv_bfloat16 h0, h1, h2, h3, l0b, l1b, l2b, l3b;
        split1(v0, h0, l0b); split1(v1, h1, l1b);
        split1(v2, h2, l2b); split1(v3, h3, l3b);
        __nv_bfloat162 hp0; hp0.x = h0; hp0.y = h1;
        __nv_bfloat162 hp1; hp1.x = h2; hp1.y = h3;
        __nv_bfloat162 lp0; lp0.x = l0b; lp0.y = l1b;
        __nv_bfloat162 lp1; lp1.x = l2b; lp1.y = l3b;
        *(__nv_bfloat162*)(Ohi + row0 * kD + col)       = hp0;
        *(__nv_bfloat162*)(Olo + row0 * kD + col)       = lp0;
        *(__nv_bfloat162*)(Ohi + (row0 + 8) * kD + col) = hp1;
        *(__nv_bfloat162*)(Olo + (row0 + 8) * kD + col) = lp1;
    }
}

// ---------------------------------------------------------------------------
// Host launcher -- multi-stream overlap (graph-capture-safe fork/join)
// ---------------------------------------------------------------------------
extern "C" void kernel_launch(void* const* d_in, const int* in_sizes, int n_in,
                              void* d_out, int out_size)
{
    (void)in_sizes; (void)n_in; (void)out_size;
    const float* x    = (const float*)d_in[0];
    const float* Wq   = (const float*)d_in[1];
    const float* bq   = (const float*)d_in[2];
    const float* Wk   = (const float*)d_in[3];
    const float* Wv   = (const float*)d_in[4];
    const float* bv   = (const float*)d_in[5];
    const float* Wo   = (const float*)d_in[6];
    const float* bo   = (const float*)d_in[7];
    const float* la_k = (const float*)d_in[8];
    const float* lb_k = (const float*)d_in[9];
    const float* la_v = (const float*)d_in[10];
    const float* lb_v = (const float*)d_in[11];
    const float* la_o = (const float*)d_in[12];
    const float* lb_o = (const float*)d_in[13];
    const float* ga   = (const float*)d_in[14];
    const float* ba   = (const float*)d_in[15];
    const float* W1   = (const float*)d_in[16];
    const float* b1   = (const float*)d_in[17];
    const float* W2   = (const float*)d_in[18];
    const float* b2   = (const float*)d_in[19];
    const float* gm   = (const float*)d_in[20];
    const float* bmn  = (const float*)d_in[21];
    float* out = (float*)d_out;

    static float *p_x1 = nullptr, *p_u;
    static __nv_bfloat16 *pa_hi, *pa_lo, *pu_hi, *pu_lo;
    static __nv_bfloat16 *pq_hi, *pq_lo, *pk_hi, *pk_lo, *pv_hi, *pv_lo;
    static __nv_bfloat16 *wq_hi, *wq_lo, *wk_hi, *wk_lo, *wv_hi, *wv_lo;
    static __nv_bfloat16 *wo_hi, *wo_lo, *w1_hi, *w1_lo, *w2_hi, *w2_lo;
    static cudaStream_t s1, s2, sW;
    static cudaEvent_t evStart, evLn, evSWq, evSWk, evSWv, evSWo, evSW1, evSW2, evGK, evGV;
    if (!p_x1) {
        float* tmp;
        cudaGetSymbolAddress((void**)&tmp, g_q);
        pq_hi = (__nv_bfloat16*)tmp; pq_lo = pq_hi + (size_t)kM * kD;
        cudaGetSymbolAddress((void**)&tmp, g_k);
        pk_hi = (__nv_bfloat16*)tmp; pk_lo = pk_hi + (size_t)kM * kD;
        cudaGetSymbolAddress((void**)&tmp, g_v);
        pv_hi = (__nv_bfloat16*)tmp; pv_lo = pv_hi + (size_t)kM * kD;
        cudaGetSymbolAddress((void**)&p_u,   g_u);
        pu_hi = (__nv_bfloat16*)p_u; pu_lo = pu_hi + (size_t)kM * kDff;
        cudaGetSymbolAddress((void**)&pa_hi, g_a_hi);
        cudaGetSymbolAddress((void**)&pa_lo, g_a_lo);
        cudaGetSymbolAddress((void**)&wq_hi, g_wq_hi);
        cudaGetSymbolAddress((void**)&wq_lo, g_wq_lo);
        cudaGetSymbolAddress((void**)&wk_hi, g_wk_hi);
        cudaGetSymbolAddress((void**)&wk_lo, g_wk_lo);
        cudaGetSymbolAddress((void**)&wv_hi, g_wv_hi);
        cudaGetSymbolAddress((void**)&wv_lo, g_wv_lo);
        cudaGetSymbolAddress((void**)&wo_hi, g_wo_hi);
        cudaGetSymbolAddress((void**)&wo_lo, g_wo_lo);
        cudaGetSymbolAddress((void**)&w1_hi, g_w1_hi);
        cudaGetSymbolAddress((void**)&w1_lo, g_w1_lo);
        cudaGetSymbolAddress((void**)&w2_hi, g_w2_hi);
        cudaGetSymbolAddress((void**)&w2_lo, g_w2_lo);
        cudaStreamCreateWithFlags(&s1, cudaStreamNonBlocking);
        cudaStreamCreateWithFlags(&s2, cudaStreamNonBlocking);
        cudaStreamCreateWithFlags(&sW, cudaStreamNonBlocking);
        cudaEventCreateWithFlags(&evStart, cudaEventDisableTiming);
        cudaEventCreateWithFlags(&evLn,    cudaEventDisableTiming);
        cudaEventCreateWithFlags(&evSWq,   cudaEventDisableTiming);
        cudaEventCreateWithFlags(&evSWk,   cudaEventDisableTiming);
        cudaEventCreateWithFlags(&evSWv,   cudaEventDisableTiming);
        cudaEventCreateWithFlags(&evSWo,   cudaEventDisableTiming);
        cudaEventCreateWithFlags(&evSW1,   cudaEventDisableTiming);
        cudaEventCreateWithFlags(&evSW2,   cudaEventDisableTiming);
        cudaEventCreateWithFlags(&evGK,    cudaEventDisableTiming);
        cudaEventCreateWithFlags(&evGV,    cudaEventDisableTiming);
        cudaFuncSetAttribute(attn_mma,
                             cudaFuncAttributeMaxDynamicSharedMemorySize, aSMEM);
        cudaFuncSetAttribute(gemm_mma<0, 0>,
                             cudaFuncAttributeMaxDynamicSharedMemorySize, 2 * kStage2);
        cudaFuncSetAttribute(gemm_mma<0, 1>,
                             cudaFuncAttributeMaxDynamicSharedMemorySize, 2 * kStage2);
        cudaFuncSetAttribute(gemm_mma<1, 1>,
                             cudaFuncAttributeMaxDynamicSharedMemorySize, 2 * kStage2);
        cudaGetSymbolAddress((void**)&p_x1,  g_x1);   // init flag last
    }

    const dim3 blk(256);
    const dim3 gD(kD / 128, kM / 128);      // (8, 64)
    const dim3 gF(kDff / 128, kM / 128);    // (32, 64)
    const int nWDD  = kD * kD / 4;
    const int nWDF  = kDff * kD / 4;
    const unsigned SMEM_G = 2 * kStage2;    // 81920 B per CTA -> 2 CTAs/SM

    // ---- fork: weight splits run on sW concurrently with the main chain
    cudaEventRecord(evStart, 0);
    cudaStreamWaitEvent(sW, evStart, 0);

    split_kernel<<<nWDD / 256, blk, 0, sW>>>(Wq, wq_hi, wq_lo, nWDD);
    cudaEventRecord(evSWq, sW);
    split_lora_kernel<<<nWDD / 256, blk, 0, sW>>>(Wk, la_k, lb_k, wk_hi, wk_lo);
    cudaEventRecord(evSWk, sW);
    split_lora_kernel<<<nWDD / 256, blk, 0, sW>>>(Wv, la_v, lb_v, wv_hi, wv_lo);
    cudaEventRecord(evSWv, sW);
    split_lora_kernel<<<nWDD / 256, blk, 0, sW>>>(Wo, la_o, lb_o, wo_hi, wo_lo);
    cudaEventRecord(evSWo, sW);
    split_kernel<<<nWDF / 256, blk, 0, sW>>>(W1, w1_hi, w1_lo, nWDF);
    cudaEventRecord(evSW1, sW);
    split_kernel<<<nWDF / 256, blk, 0, sW>>>(W2, w2_hi, w2_lo, nWDF);
    cudaEventRecord(evSW2, sW);

    // ---- main chain (stream 0)
    ln_split_kernel<<<kM, blk>>>(x, ga, ba, pa_hi, pa_lo);
    cudaEventRecord(evLn, 0);
    cudaStreamWaitEvent(s1, evLn, 0);
    cudaStreamWaitEvent(s2, evLn, 0);

    // QKV GEMMs on three streams (independent; tails overlap)
    cudaStreamWaitEvent(0, evSWq, 0);
    gemm_mma<0, 1><<<gD, blk, SMEM_G>>>(pa_hi, pa_lo, wq_hi, wq_lo,
                                        bq, nullptr,
                                        nullptr, pq_hi, pq_lo, kM, kD, kD);

    cudaStreamWaitEvent(s1, evSWk, 0);
    gemm_mma<0, 1><<<gD, blk, SMEM_G, s1>>>(pa_hi, pa_lo, wk_hi, wk_lo,
                                            nullptr, nullptr,
                                            nullptr, pk_hi, pk_lo, kM, kD, kD);
    cudaEventRecord(evGK, s1);

    cudaStreamWaitEvent(s2, evSWv, 0);
    gemm_mma<0, 1><<<gD, blk, SMEM_G, s2>>>(pa_hi, pa_lo, wv_hi, wv_lo,
                                            bv, nullptr,
                                            nullptr, pv_hi, pv_lo, kM, kD, kD);
    cudaEventRecord(evGV, s2);

    // attention (stream 0): after Q (same stream) + K, V (events)
    cudaStreamWaitEvent(0, evGK, 0);
    cudaStreamWaitEvent(0, evGV, 0);
    attn_mma<<<dim3(8, kB * kH), blk, aSMEM>>>(pq_hi, pq_lo, pk_hi, pk_lo,
                                               pv_hi, pv_lo, pa_hi, pa_lo);

    cudaStreamWaitEvent(0, evSWo, 0);
    gemm_mma<0, 0><<<gD, blk, SMEM_G>>>(pa_hi, pa_lo, wo_hi, wo_lo,
                                        bo, x,
                                        p_x1, nullptr, nullptr, kM, kD, kD);

    // ---- MLP half (stream 0)
    ln_split_kernel<<<kM, blk>>>(p_x1, gm, bmn, pa_hi, pa_lo);
    cudaStreamWaitEvent(0, evSW1, 0);
    gemm_mma<1, 1><<<gF, blk, SMEM_G>>>(pa_hi, pa_lo, w1_hi, w1_lo,
                                        b1, nullptr,
                                        nullptr, pu_hi, pu_lo, kM, kDff, kD);

    cudaStreamWaitEvent(0, evSW2, 0);
    gemm_mma<0, 0><<<gD, blk, SMEM_G>>>(pu_hi, pu_lo, w2_hi, w2_lo,
                                        b2, p_x1,
                                        out, nullptr, nullptr, kM, kD, kDff);
}

// round 15
// speedup vs baseline: 3.2940x; 1.0141x over previous
#include <cuda_runtime.h>
#include <cuda_bf16.h>
#include <cstdint>
#include <math.h>

// ---------------------------------------------------------------------------
// Shapes (fixed by the problem)
// ---------------------------------------------------------------------------
namespace {
constexpr int kD   = 1024;
constexpr int kDff = 4096;
constexpr int kB   = 8;
constexpr int kS   = 1024;
constexpr int kM   = kB * kS;   // 8192 rows
constexpr int kH   = 16;        // heads
}

// ---------------------------------------------------------------------------
// Scratch (static device globals -- no allocation allowed)
// ---------------------------------------------------------------------------
__device__ float g_q [(size_t)kM * kD];     // reused: bf16 q_hi / q_lo
__device__ float g_k [(size_t)kM * kD];     // reused: bf16 k_hi / k_lo
__device__ float g_v [(size_t)kM * kD];     // reused: bf16 v_hi / v_lo
__device__ float g_x1[(size_t)kM * kD];
__device__ float g_u [(size_t)kM * kDff];   // reused: bf16 u_hi / u_lo
__device__ __nv_bfloat16 g_a_hi[(size_t)kM * kD];
__device__ __nv_bfloat16 g_a_lo[(size_t)kM * kD];
// per-weight split buffers (so weight splits can overlap compute)
__device__ __nv_bfloat16 g_wq_hi[(size_t)kD * kD],  g_wq_lo[(size_t)kD * kD];
__device__ __nv_bfloat16 g_wk_hi[(size_t)kD * kD],  g_wk_lo[(size_t)kD * kD];
__device__ __nv_bfloat16 g_wv_hi[(size_t)kD * kD],  g_wv_lo[(size_t)kD * kD];
__device__ __nv_bfloat16 g_wo_hi[(size_t)kD * kD],  g_wo_lo[(size_t)kD * kD];
__device__ __nv_bfloat16 g_w1_hi[(size_t)kDff * kD], g_w1_lo[(size_t)kDff * kD];
__device__ __nv_bfloat16 g_w2_hi[(size_t)kDff * kD], g_w2_lo[(size_t)kDff * kD];

// ---------------------------------------------------------------------------
// PTX helpers (portable sm_80+: cp.async / ldmatrix / mma.sync)
// ---------------------------------------------------------------------------
__device__ __forceinline__ uint32_t smem_u32(const void* p) {
    uint32_t a;
    asm("{ .reg .u64 t; cvta.to.shared.u64 t, %1; cvt.u32.u64 %0, t; }"
        : "=r"(a) : "l"(p));
    return a;
}

#define CP_ASYNC16(saddr, gptr) \
    asm volatile("cp.async.cg.shared.global [%0], [%1], 16;" \
        :: "r"(saddr), "l"(gptr))

#define CP_COMMIT() asm volatile("cp.async.commit_group;" ::: "memory")

#define LDSM_X4(r0, r1, r2, r3, addr) \
    asm volatile("ldmatrix.sync.aligned.m8n8.x4.shared.b16 {%0,%1,%2,%3}, [%4];" \
        : "=r"(r0), "=r"(r1), "=r"(r2), "=r"(r3) : "r"(addr))

#define LDSM_X4T(r0, r1, r2, r3, addr) \
    asm volatile("ldmatrix.sync.aligned.m8n8.x4.trans.shared.b16 {%0,%1,%2,%3}, [%4];" \
        : "=r"(r0), "=r"(r1), "=r"(r2), "=r"(r3) : "r"(addr))

#define MMA16816(d, a, b) \
    asm volatile("mma.sync.aligned.m16n8k16.row.col.f32.bf16.bf16.f32 " \
        "{%0,%1,%2,%3}, {%4,%5,%6,%7}, {%8,%9}, {%0,%1,%2,%3};" \
        : "+f"((d)[0]), "+f"((d)[1]), "+f"((d)[2]), "+f"((d)[3]) \
        : "r"((a)[0]), "r"((a)[1]), "r"((a)[2]), "r"((a)[3]), \
          "r"((b)[0]), "r"((b)[1]))

__device__ __forceinline__ void split1(float v, __nv_bfloat16& h, __nv_bfloat16& l) {
    h = __float2bfloat16(v);
    l = __float2bfloat16(v - __bfloat162float(h));
}

__device__ __forceinline__ uint32_t pack_bf16x2(float a, float b) {
    __nv_bfloat162 t = __floats2bfloat162_rn(a, b);   // .x = a (low half)
    return *(uint32_t*)&t;
}

__device__ __forceinline__ void st_shared_v4(uint32_t addr, uint4 v) {
    asm volatile("st.shared.v4.b32 [%0], {%1, %2, %3, %4};"
        :: "r"(addr), "r"(v.x), "r"(v.y), "r"(v.z), "r"(v.w));
}

// ---------------------------------------------------------------------------
// fp32 -> (bf16 hi, bf16 lo) split (plain weights / no LoRA)
// ---------------------------------------------------------------------------
__global__ void split_kernel(const float* __restrict__ x, __nv_bfloat16* __restrict__ hi,
                             __nv_bfloat16* __restrict__ lo, int n4)
{
    const int i = blockIdx.x * 256 + threadIdx.x;
    if (i >= n4) return;
    float4 v = ((const float4*)x)[i];
    __nv_bfloat16 h0, h1, h2, h3, l0, l1, l2, l3;
    split1(v.x, h0, l0); split1(v.y, h1, l1);
    split1(v.z, h2, l2); split1(v.w, h3, l3);
    __nv_bfloat162 hp0; hp0.x = h0; hp0.y = h1;
    __nv_bfloat162 hp1; hp1.x = h2; hp1.y = h3;
    __nv_bfloat162 lp0; lp0.x = l0; lp0.y = l1;
    __nv_bfloat162 lp1; lp1.x = l2; lp1.y = l3;
    ((__nv_bfloat162*)hi)[i * 2 + 0] = hp0;
    ((__nv_bfloat162*)hi)[i * 2 + 1] = hp1;
    ((__nv_bfloat162*)lo)[i * 2 + 0] = lp0;
    ((__nv_bfloat162*)lo)[i * 2 + 1] = lp1;
}

// ---------------------------------------------------------------------------
// Weight split with fused rank-4 LoRA fold:
//   W'[n,k] = W[n,k] + 0.25 * sum_r lb[n,r] * la[r,k]   (D x D weights only)
// ---------------------------------------------------------------------------
__global__ void split_lora_kernel(const float* __restrict__ W,
                                  const float* __restrict__ la,
                                  const float* __restrict__ lb,
                                  __nv_bfloat16* __restrict__ hi,
                                  __nv_bfloat16* __restrict__ lo)
{
    const int i = blockIdx.x * 256 + threadIdx.x;   // over D*D/4
    const int n  = i >> 8;            // row (D/4 = 256 float4 per row)
    const int k4 = (i & 255) * 4;
    float4 v = ((const float4*)W)[i];
    float4 lbv = ((const float4*)lb)[n];
    float4 a0 = *(const float4*)(la + 0 * kD + k4);
    float4 a1 = *(const float4*)(la + 1 * kD + k4);
    float4 a2 = *(const float4*)(la + 2 * kD + k4);
    float4 a3 = *(const float4*)(la + 3 * kD + k4);
    v.x += 0.25f * (lbv.x * a0.x + lbv.y * a1.x + lbv.z * a2.x + lbv.w * a3.x);
    v.y += 0.25f * (lbv.x * a0.y + lbv.y * a1.y + lbv.z * a2.y + lbv.w * a3.y);
    v.z += 0.25f * (lbv.x * a0.z + lbv.y * a1.z + lbv.z * a2.z + lbv.w * a3.z);
    v.w += 0.25f * (lbv.x * a0.w + lbv.y * a1.w + lbv.z * a2.w + lbv.w * a3.w);
    __nv_bfloat16 h0, h1, h2, h3, l0, l1, l2, l3;
    split1(v.x, h0, l0); split1(v.y, h1, l1);
    split1(v.z, h2, l2); split1(v.w, h3, l3);
    __nv_bfloat162 hp0; hp0.x = h0; hp0.y = h1;
    __nv_bfloat162 hp1; hp1.x = h2; hp1.y = h3;
    __nv_bfloat162 lp0; lp0.x = l0; lp0.y = l1;
    __nv_bfloat162 lp1; lp1.x = l2; lp1.y = l3;
    ((__nv_bfloat162*)hi)[i * 2 + 0] = hp0;
    ((__nv_bfloat162*)hi)[i * 2 + 1] = hp1;
    ((__nv_bfloat162*)lo)[i * 2 + 0] = lp0;
    ((__nv_bfloat162*)lo)[i * 2 + 1] = lp1;
}

// ---------------------------------------------------------------------------
// Tensor-core GEMM (mma.sync bf16, split hi/lo 3-term):
//   C = A @ B^T (+bias) (+GELU) (+res); SPLIT=1 -> bf16 hi/lo out
// CTA tile 128x128, warp tile 64x32 (8 warps = 2x4), BK=32,
// 2-stage cp.async ring, __launch_bounds__(256,2) -> 2 CTAs/SM.
// ---------------------------------------------------------------------------
namespace {
constexpr int      kRowB   = 80;
constexpr uint32_t kTile128 = 128 * kRowB;              // 10240
constexpr uint32_t kStage2  = 4 * kTile128;             // 40960 per stage
constexpr uint32_t oAl2 = kTile128;                     // 10240
constexpr uint32_t oBh2 = 2 * kTile128;                 // 20480
constexpr uint32_t oBl2 = 3 * kTile128;                 // 30720
}

template <int GELU, int SPLIT>
__global__ void __launch_bounds__(256, 2)
gemm_mma(const __nv_bfloat16* __restrict__ Ahi, const __nv_bfloat16* __restrict__ Alo,
         const __nv_bfloat16* __restrict__ Bhi, const __nv_bfloat16* __restrict__ Blo,
         const float* __restrict__ bias, const float* __restrict__ res,
         float* __restrict__ C,
         __nv_bfloat16* __restrict__ Chi, __nv_bfloat16* __restrict__ Clo,
         int M, int N, int K)
{
    extern __shared__ char smem[];
    const uint32_t sbase = smem_u32(smem);
    const int tid  = threadIdx.x;
    const int lane = tid & 31;
    const int wid  = tid >> 5;
    const int bm = blockIdx.y * 128;
    const int bn = blockIdx.x * 128;
    const int warp_m = (wid >> 2) * 64;    // 0 or 64
    const int warp_n = (wid & 3) * 32;     // 0,32,64,96

    const int r0 = tid >> 2;               // 0..63
    const int c8 = (tid & 3) * 8;
    const uint32_t so = (uint32_t)(r0 * kRowB + (tid & 3) * 16);

    float acc[4][4][4];
#pragma unroll
    for (int i = 0; i < 4; i++)
#pragma unroll
        for (int j = 0; j < 4; j++)
#pragma unroll
            for (int r = 0; r < 4; r++) acc[i][j][r] = 0.f;

    const uint32_t a_off = (uint32_t)((warp_m + (lane & 15)) * kRowB + (lane >> 4) * 16);
    const uint32_t b_off = (uint32_t)((warp_n + (lane & 7) + ((lane >> 4) & 1) * 8) * kRowB
                                      + ((lane >> 3) & 1) * 16);

    const int nIter = K >> 5;

    auto load_stage = [&](int it, int s) {
        const int k0 = it << 5;
        const uint32_t sbuf = sbase + (uint32_t)s * kStage2;
        const size_t ga0 = (size_t)(bm + r0) * K + k0 + c8;
        const size_t ga1 = ga0 + (size_t)64 * K;
        const size_t gb0 = (size_t)(bn + r0) * K + k0 + c8;
        const size_t gb1 = gb0 + (size_t)64 * K;
        const uint32_t so1 = so + 64u * kRowB;
        CP_ASYNC16(sbuf +        so,  Ahi + ga0);
        CP_ASYNC16(sbuf +        so1, Ahi + ga1);
        CP_ASYNC16(sbuf + oAl2 + so,  Alo + ga0);
        CP_ASYNC16(sbuf + oAl2 + so1, Alo + ga1);
        CP_ASYNC16(sbuf + oBh2 + so,  Bhi + gb0);
        CP_ASYNC16(sbuf + oBh2 + so1, Bhi + gb1);
        CP_ASYNC16(sbuf + oBl2 + so,  Blo + gb0);
        CP_ASYNC16(sbuf + oBl2 + so1, Blo + gb1);
        CP_COMMIT();
    };

    load_stage(0, 0);

    for (int it = 0; it < nIter; ++it) {
        if (it + 1 < nIter) {
            load_stage(it + 1, (it + 1) & 1);
            asm volatile("cp.async.wait_group 1;" ::: "memory");
        } else {
            asm volatile("cp.async.wait_group 0;" ::: "memory");
        }
        __syncthreads();

        const uint32_t sbuf = sbase + (uint32_t)(it & 1) * kStage2;
        const uint32_t abase = sbuf + a_off;
        const uint32_t bbase = sbuf + oBh2 + b_off;

#pragma unroll
        for (int ks = 0; ks < 2; ks++) {
            const uint32_t ko = (uint32_t)ks * 32;
            uint32_t ah[4][4], al[4][4], bh[4][2], bl[4][2];
#pragma unroll
            for (int i = 0; i < 4; i++) {
                LDSM_X4(ah[i][0], ah[i][1], ah[i][2], ah[i][3],
                        abase + (uint32_t)i * (16 * kRowB) + ko);
            }
#pragma unroll
            for (int p = 0; p < 2; p++) {
                LDSM_X4(bh[2*p][0], bh[2*p][1], bh[2*p+1][0], bh[2*p+1][1],
                        bbase + (uint32_t)p * (16 * kRowB) + ko);
            }
#pragma unroll
            for (int i = 0; i < 4; i++) {
                LDSM_X4(al[i][0], al[i][1], al[i][2], al[i][3],
                        abase + oAl2 + (uint32_t)i * (16 * kRowB) + ko);
            }
#pragma unroll
            for (int p = 0; p < 2; p++) {
                LDSM_X4(bl[2*p][0], bl[2*p][1], bl[2*p+1][0], bl[2*p+1][1],
                        bbase + kTile128 + (uint32_t)p * (16 * kRowB) + ko);
            }
            // term 1: Ahi * Bhi
#pragma unroll
            for (int i = 0; i < 4; i++)
#pragma unroll
                for (int j = 0; j < 4; j++)
                    MMA16816(acc[i][j], ah[i], bh[j]);
            // term 2: Ahi * Blo
#pragma unroll
            for (int i = 0; i < 4; i++)
#pragma unroll
                for (int j = 0; j < 4; j++)
                    MMA16816(acc[i][j], ah[i], bl[j]);
            // term 3: Alo * Bhi
#pragma unroll
            for (int i = 0; i < 4; i++)
#pragma unroll
                for (int j = 0; j < 4; j++)
                    MMA16816(acc[i][j], al[i], bh[j]);
        }
        __syncthreads();
    }

    // ---- epilogue
    const int g  = lane >> 2;
    const int t4 = lane & 3;
#pragma unroll
    for (int i = 0; i < 4; i++) {
        const int mlo = bm + warp_m + 16 * i + g;
        const int mhi = mlo + 8;
#pragma unroll
        for (int j = 0; j < 4; j++) {
            const int n0 = bn + warp_n + 8 * j + 2 * t4;
            float b0 = 0.f, b1 = 0.f;
            if (bias) { b0 = bias[n0]; b1 = bias[n0 + 1]; }
            float v0 = acc[i][j][0] + b0;
            float v1 = acc[i][j][1] + b1;
            float v2 = acc[i][j][2] + b0;
            float v3 = acc[i][j][3] + b1;
            if (GELU) {
                v0 = 0.5f * v0 * (1.f + erff(v0 * 0.70710678118f));
                v1 = 0.5f * v1 * (1.f + erff(v1 * 0.70710678118f));
                v2 = 0.5f * v2 * (1.f + erff(v2 * 0.70710678118f));
                v3 = 0.5f * v3 * (1.f + erff(v3 * 0.70710678118f));
            }
            const size_t olo = (size_t)mlo * N + n0;
            const size_t ohi = (size_t)mhi * N + n0;
            if (SPLIT) {
                __nv_bfloat16 h0, h1, h2, h3, l0, l1, l2, l3;
                split1(v0, h0, l0); split1(v1, h1, l1);
                split1(v2, h2, l2); split1(v3, h3, l3);
                __nv_bfloat162 hp0; hp0.x = h0; hp0.y = h1;
                __nv_bfloat162 hp1; hp1.x = h2; hp1.y = h3;
                __nv_bfloat162 lp0; lp0.x = l0; lp0.y = l1;
                __nv_bfloat162 lp1; lp1.x = l2; lp1.y = l3;
                *(__nv_bfloat162*)(Chi + olo) = hp0;
                *(__nv_bfloat162*)(Chi + ohi) = hp1;
                *(__nv_bfloat162*)(Clo + olo) = lp0;
                *(__nv_bfloat162*)(Clo + ohi) = lp1;
            } else {
                if (res) {
                    float2 r0_ = *(const float2*)(res + olo);
                    float2 r1_ = *(const float2*)(res + ohi);
                    v0 += r0_.x; v1 += r0_.y; v2 += r1_.x; v3 += r1_.y;
                }
                *(float2*)(C + olo) = make_float2(v0, v1);
                *(float2*)(C + ohi) = make_float2(v2, v3);
            }
        }
    }
}

// ---------------------------------------------------------------------------
// LayerNorm -> split bf16 hi/lo directly
// ---------------------------------------------------------------------------
__global__ void ln_split_kernel(const float* __restrict__ x, const float* __restrict__ g,
                                const float* __restrict__ b,
                                __nv_bfloat16* __restrict__ yhi,
                                __nv_bfloat16* __restrict__ ylo)
{
    const int row = blockIdx.x;
    const int tid = threadIdx.x;
    float4 v = ((const float4*)(x + (size_t)row * kD))[tid];
    float s  = v.x + v.y + v.z + v.w;
    float sq = v.x*v.x + v.y*v.y + v.z*v.z + v.w*v.w;
#pragma unroll
    for (int o = 16; o; o >>= 1) {
        s  += __shfl_xor_sync(0xffffffffu, s,  o);
        sq += __shfl_xor_sync(0xffffffffu, sq, o);
    }
    __shared__ float ss[8], ssq[8];
    const int w = tid >> 5, lane = tid & 31;
    if (lane == 0) { ss[w] = s; ssq[w] = sq; }
    __syncthreads();
    if (w == 0) {
        float a = (lane < 8) ? ss[lane]  : 0.f;
        float c = (lane < 8) ? ssq[lane] : 0.f;
#pragma unroll
        for (int o = 4; o; o >>= 1) {
            a += __shfl_xor_sync(0xffffffffu, a, o);
            c += __shfl_xor_sync(0xffffffffu, c, o);
        }
        if (lane == 0) { ss[0] = a; ssq[0] = c; }
    }
    __syncthreads();
    const float mean = ss[0] * (1.f / kD);
    const float var  = ssq[0] * (1.f / kD) - mean * mean;
    const float rstd = rsqrtf(var + 1e-5f);
    float4 gv = ((const float4*)g)[tid];
    float4 bv = ((const float4*)b)[tid];
    float y0 = (v.x - mean) * rstd * gv.x + bv.x;
    float y1 = (v.y - mean) * rstd * gv.y + bv.y;
    float y2 = (v.z - mean) * rstd * gv.z + bv.z;
    float y3 = (v.w - mean) * rstd * gv.w + bv.w;
    __nv_bfloat16 h0, h1, h2, h3, l0, l1, l2, l3;
    split1(y0, h0, l0); split1(y1, h1, l1);
    split1(y2, h2, l2); split1(y3, h3, l3);
    __nv_bfloat162 hp0; hp0.x = h0; hp0.y = h1;
    __nv_bfloat162 hp1; hp1.x = h2; hp1.y = h3;
    __nv_bfloat162 lp0; lp0.x = l0; lp0.y = l1;
    __nv_bfloat162 lp1; lp1.x = l2; lp1.y = l3;
    ((__nv_bfloat162*)(yhi + (size_t)row * kD))[tid * 2 + 0] = hp0;
    ((__nv_bfloat162*)(yhi + (size_t)row * kD))[tid * 2 + 1] = hp1;
    ((__nv_bfloat162*)(ylo + (size_t)row * kD))[tid * 2 + 0] = lp0;
    ((__nv_bfloat162*)(ylo + (size_t)row * kD))[tid * 2 + 1] = lp1;
}

// ---------------------------------------------------------------------------
// Tensor-core flash attention (split-bf16 3-term for QK^T and PV).
// Block: 128 q-rows of one (b,h); 8 warps, each 16 q-rows x 64 keys.
// Register-squeezed (B/V frags loaded in halves) for 2 CTAs/SM.
// ---------------------------------------------------------------------------
namespace {
constexpr uint32_t aQH  = 0;
constexpr uint32_t aQL  = 18432;           // 128*144
constexpr uint32_t aKV0 = 36864;           // + stage*36864; Kh,Kl,Vh,Vl @ +9216 each
constexpr uint32_t aSMEM = 36864 + 2 * 36864;  // 110592
}

__global__ void __launch_bounds__(256, 2)
attn_mma(const __nv_bfloat16* __restrict__ Qhi, const __nv_bfloat16* __restrict__ Qlo,
         const __nv_bfloat16* __restrict__ Khi, const __nv_bfloat16* __restrict__ Klo,
         const __nv_bfloat16* __restrict__ Vhi, const __nv_bfloat16* __restrict__ Vlo,
         __nv_bfloat16* __restrict__ Ohi, __nv_bfloat16* __restrict__ Olo)
{
    extern __shared__ char smem[];
    const uint32_t sb = smem_u32(smem);
    const int tid  = threadIdx.x;
    const int lane = tid & 31;
    const int wid  = tid >> 5;           // 0..7
    const int qt = blockIdx.x;           // 0..7
    const int bh = blockIdx.y;
    const int b  = bh >> 4, h = bh & 15;
    const size_t rowbase = (size_t)b * kS;
    const int cb = h * 64;
    const int warp_m = wid * 16;

    {
        const __nv_bfloat162 sc = __float2bfloat162_rn(0.125f);
#pragma unroll
        for (int i = tid; i < 1024; i += 256) {
            const int r = i >> 3, c = i & 7;
            const size_t go = (rowbase + qt * 128 + r) * kD + cb + c * 8;
            const uint32_t so = (uint32_t)(r * 144 + c * 16);
            uint4 vh = *(const uint4*)(Qhi + go);
            uint4 vl = *(const uint4*)(Qlo + go);
            __nv_bfloat162* ph = (__nv_bfloat162*)&vh;
            __nv_bfloat162* pl = (__nv_bfloat162*)&vl;
#pragma unroll
            for (int k = 0; k < 4; k++) { ph[k] = __hmul2(ph[k], sc); pl[k] = __hmul2(pl[k], sc); }
            st_shared_v4(sb + aQH + so, vh);
            st_shared_v4(sb + aQL + so, vl);
        }
    }

    auto load_kv = [&](int kt, int s) {
        const uint32_t st = sb + aKV0 + (uint32_t)s * 36864u;
#pragma unroll
        for (int i = tid; i < 512; i += 256) {
            const int r = i >> 3, c = i & 7;
            const size_t go = (rowbase + kt * 64 + r) * kD + cb + c * 8;
            const uint32_t so = (uint32_t)(r * 144 + c * 16);
            CP_ASYNC16(st +          so, Khi + go);
            CP_ASYNC16(st +  9216u + so, Klo + go);
            CP_ASYNC16(st + 18432u + so, Vhi + go);
            CP_ASYNC16(st + 27648u + so, Vlo + go);
        }
        CP_COMMIT();
    };
    load_kv(0, 0);
    __syncthreads();

    uint32_t qh[4][4], ql[4][4];
    {
        const uint32_t qa = sb + (uint32_t)((warp_m + (lane & 15)) * 144 + (lane >> 4) * 16);
#pragma unroll
        for (int kk = 0; kk < 4; kk++) {
            LDSM_X4(qh[kk][0], qh[kk][1], qh[kk][2], qh[kk][3], qa + aQH + kk * 32);
            LDSM_X4(ql[kk][0], ql[kk][1], ql[kk][2], ql[kk][3], qa + aQL + kk * 32);
        }
    }

    float m0 = -1e30f, m1 = -1e30f, l0 = 0.f, l1 = 0.f;
    float o[8][4];
#pragma unroll
    for (int j = 0; j < 8; j++)
#pragma unroll
        for (int c = 0; c < 4; c++) o[j][c] = 0.f;

    const uint32_t kboff = (uint32_t)(((lane & 7) + ((lane >> 4) & 1) * 8) * 144
                                      + ((lane >> 3) & 1) * 16);
    const uint32_t vaoff = (uint32_t)((lane & 15) * 144 + (lane >> 4) * 16);

    for (int kt = 0; kt < 16; kt++) {
        asm volatile("cp.async.wait_group 0;" ::: "memory");
        __syncthreads();
        if (kt + 1 < 16) load_kv(kt + 1, (kt + 1) & 1);
        const uint32_t st = sb + aKV0 + (uint32_t)(kt & 1) * 36864u;

        float s[8][4];
#pragma unroll
        for (int j = 0; j < 8; j++)
#pragma unroll
            for (int c = 0; c < 4; c++) s[j][c] = 0.f;

        // QK^T: B-frags loaded 32 keys at a time (halves -> lower reg peak)
#pragma unroll
        for (int kk = 0; kk < 4; kk++) {
#pragma unroll
            for (int half = 0; half < 2; half++) {
                uint32_t bh_[4][2], bl_[4][2];
#pragma unroll
                for (int p = 0; p < 2; p++) {
                    const uint32_t po = (uint32_t)(half * 2 + p) * (16 * 144);
                    LDSM_X4(bh_[2*p][0], bh_[2*p][1], bh_[2*p+1][0], bh_[2*p+1][1],
                            st + kboff + po + kk * 32);
                    LDSM_X4(bl_[2*p][0], bl_[2*p][1], bl_[2*p+1][0], bl_[2*p+1][1],
                            st + 9216u + kboff + po + kk * 32);
                }
                float* sj = &s[half * 4][0];
#pragma unroll
                for (int j = 0; j < 4; j++) MMA16816((sj + 4 * j), qh[kk], bh_[j]);
#pragma unroll
                for (int j = 0; j < 4; j++) MMA16816((sj + 4 * j), qh[kk], bl_[j]);
#pragma unroll
                for (int j = 0; j < 4; j++) MMA16816((sj + 4 * j), ql[kk], bh_[j]);
            }
        }

        float mx0 = m0, mx1 = m1;
#pragma unroll
        for (int j = 0; j < 8; j++) {
            mx0 = fmaxf(mx0, fmaxf(s[j][0], s[j][1]));
            mx1 = fmaxf(mx1, fmaxf(s[j][2], s[j][3]));
        }
        mx0 = fmaxf(mx0, __shfl_xor_sync(0xffffffffu, mx0, 1));
        mx0 = fmaxf(mx0, __shfl_xor_sync(0xffffffffu, mx0, 2));
        mx1 = fmaxf(mx1, __shfl_xor_sync(0xffffffffu, mx1, 1));
        mx1 = fmaxf(mx1, __shfl_xor_sync(0xffffffffu, mx1, 2));
        const float fac0 = __expf(m0 - mx0);
        const float fac1 = __expf(m1 - mx1);
        float sum0 = 0.f, sum1 = 0.f;
#pragma unroll
        for (int j = 0; j < 8; j++) {
            s[j][0] = __expf(s[j][0] - mx0);
            s[j][1] = __expf(s[j][1] - mx0);
            s[j][2] = __expf(s[j][2] - mx1);
            s[j][3] = __expf(s[j][3] - mx1);
            sum0 += s[j][0] + s[j][1];
            sum1 += s[j][2] + s[j][3];
        }
        sum0 += __shfl_xor_sync(0xffffffffu, sum0, 1);
        sum0 += __shfl_xor_sync(0xffffffffu, sum0, 2);
        sum1 += __shfl_xor_sync(0xffffffffu, sum1, 1);
        sum1 += __shfl_xor_sync(0xffffffffu, sum1, 2);
        l0 = l0 * fac0 + sum0;
        l1 = l1 * fac1 + sum1;
        m0 = mx0; m1 = mx1;
#pragma unroll
        for (int j = 0; j < 8; j++) {
            o[j][0] *= fac0; o[j][1] *= fac0;
            o[j][2] *= fac1; o[j][3] *= fac1;
        }

        // O += P V : V-frags loaded 32 output-cols at a time (halves)
#pragma unroll
        for (int kk = 0; kk < 4; kk++) {
            const int j0 = 2 * kk, j1 = 2 * kk + 1;
            uint32_t ph[4], pl[4];
            ph[0] = pack_bf16x2(s[j0][0], s[j0][1]);
            ph[1] = pack_bf16x2(s[j0][2], s[j0][3]);
            ph[2] = pack_bf16x2(s[j1][0], s[j1][1]);
            ph[3] = pack_bf16x2(s[j1][2], s[j1][3]);
            {
                const float r00 = s[j0][0] - __bfloat162float(__float2bfloat16(s[j0][0]));
                const float r01 = s[j0][1] - __bfloat162float(__float2bfloat16(s[j0][1]));
                const float r02 = s[j0][2] - __bfloat162float(__float2bfloat16(s[j0][2]));
                const float r03 = s[j0][3] - __bfloat162float(__float2bfloat16(s[j0][3]));
                const float r10 = s[j1][0] - __bfloat162float(__float2bfloat16(s[j1][0]));
                const float r11 = s[j1][1] - __bfloat162float(__float2bfloat16(s[j1][1]));
                const float r12 = s[j1][2] - __bfloat162float(__float2bfloat16(s[j1][2]));
                const float r13 = s[j1][3] - __bfloat162float(__float2bfloat16(s[j1][3]));
                pl[0] = pack_bf16x2(r00, r01);
                pl[1] = pack_bf16x2(r02, r03);
                pl[2] = pack_bf16x2(r10, r11);
                pl[3] = pack_bf16x2(r12, r13);
            }
#pragma unroll
            for (int half = 0; half < 2; half++) {
                uint32_t vh_[4][2], vl_[4][2];
#pragma unroll
                for (int nn = 0; nn < 2; nn++) {
                    const uint32_t no = (uint32_t)(half * 2 + nn) * 32;
                    LDSM_X4T(vh_[2*nn][0], vh_[2*nn][1], vh_[2*nn+1][0], vh_[2*nn+1][1],
                             st + 18432u + vaoff + (uint32_t)kk * (16 * 144) + no);
                    LDSM_X4T(vl_[2*nn][0], vl_[2*nn][1], vl_[2*nn+1][0], vl_[2*nn+1][1],
                             st + 27648u + vaoff + (uint32_t)kk * (16 * 144) + no);
                }
                float* oj = &o[half * 4][0];
#pragma unroll
                for (int j = 0; j < 4; j++) MMA16816((oj + 4 * j), ph, vh_[j]);
#pragma unroll
                for (int j = 0; j < 4; j++) MMA16816((oj + 4 * j), ph, vl_[j]);
#pragma unroll
                for (int j = 0; j < 4; j++) MMA16816((oj + 4 * j), pl, vh_[j]);
            }
        }
    }

    const float inv0 = 1.f / l0, inv1 = 1.f / l1;
    const int g = lane >> 2, t4 = lane & 3;
    const size_t row0 = rowbase + qt * 128 + warp_m + g;
#pragma unroll
    for (int j = 0; j < 8; j++) {
        const int col = cb + 8 * j + 2 * t4;
        const float v0 = o[j][0] * inv0, v1 = o[j][1] * inv0;
        const float v2 = o[j][2] * inv1, v3 = o[j][3] * inv1;
        __nv_bfloat16 h0, h1, h2, h3, l0b, l1b, l2b, l3b;
        split1(v0, h0, l0b); split1(v1, h1, l1b);
        split1(v2, h2, l2b); split1(v3, h3, l3b);
        __nv_bfloat162 hp0; hp0.x = h0; hp0.y = h1;
        __nv_bfloat162 hp1; hp1.x = h2; hp1.y = h3;
        __nv_bfloat162 lp0; lp0.x = l0b; lp0.y = l1b;
        __nv_bfloat162 lp1; lp1.x = l2b; lp1.y = l3b;
        *(__nv_bfloat162*)(Ohi + row0 * kD + col)       = hp0;
        *(__nv_bfloat162*)(Olo + row0 * kD + col)       = lp0;
        *(__nv_bfloat162*)(Ohi + (row0 + 8) * kD + col) = hp1;
        *(__nv_bfloat162*)(Olo + (row0 + 8) * kD + col) = lp1;
    }
}

// ---------------------------------------------------------------------------
// Host launcher -- multi-stream overlap (graph-capture-safe fork/join)
// ---------------------------------------------------------------------------
extern "C" void kernel_launch(void* const* d_in, const int* in_sizes, int n_in,
                              void* d_out, int out_size)
{
    (void)in_sizes; (void)n_in; (void)out_size;
    const float* x    = (const float*)d_in[0];
    const float* Wq   = (const float*)d_in[1];
    const float* bq   = (const float*)d_in[2];
    const float* Wk   = (const float*)d_in[3];
    const float* Wv   = (const float*)d_in[4];
    const float* bv   = (const float*)d_in[5];
    const float* Wo   = (const float*)d_in[6];
    const float* bo   = (const float*)d_in[7];
    const float* la_k = (const float*)d_in[8];
    const float* lb_k = (const float*)d_in[9];
    const float* la_v = (const float*)d_in[10];
    const float* lb_v = (const float*)d_in[11];
    const float* la_o = (const float*)d_in[12];
    const float* lb_o = (const float*)d_in[13];
    const float* ga   = (const float*)d_in[14];
    const float* ba   = (const float*)d_in[15];
    const float* W1   = (const float*)d_in[16];
    const float* b1   = (const float*)d_in[17];
    const float* W2   = (const float*)d_in[18];
    const float* b2   = (const float*)d_in[19];
    const float* gm   = (const float*)d_in[20];
    const float* bmn  = (const float*)d_in[21];
    float* out = (float*)d_out;

    static float *p_x1 = nullptr, *p_u;
    static __nv_bfloat16 *pa_hi, *pa_lo, *pu_hi, *pu_lo;
    static __nv_bfloat16 *pq_hi, *pq_lo, *pk_hi, *pk_lo, *pv_hi, *pv_lo;
    static __nv_bfloat16 *wq_hi, *wq_lo, *wk_hi, *wk_lo, *wv_hi, *wv_lo;
    static __nv_bfloat16 *wo_hi, *wo_lo, *w1_hi, *w1_lo, *w2_hi, *w2_lo;
    static cudaStream_t s1, s2, sW;
    static cudaEvent_t evStart, evLn, evSWq, evSWk, evSWv, evSWo, evSW1, evSW2, evGK, evGV;
    if (!p_x1) {
        float* tmp;
        cudaGetSymbolAddress((void**)&tmp, g_q);
        pq_hi = (__nv_bfloat16*)tmp; pq_lo = pq_hi + (size_t)kM * kD;
        cudaGetSymbolAddress((void**)&tmp, g_k);
        pk_hi = (__nv_bfloat16*)tmp; pk_lo = pk_hi + (size_t)kM * kD;
        cudaGetSymbolAddress((void**)&tmp, g_v);
        pv_hi = (__nv_bfloat16*)tmp; pv_lo = pv_hi + (size_t)kM * kD;
        cudaGetSymbolAddress((void**)&p_u,   g_u);
        pu_hi = (__nv_bfloat16*)p_u; pu_lo = pu_hi + (size_t)kM * kDff;
        cudaGetSymbolAddress((void**)&pa_hi, g_a_hi);
        cudaGetSymbolAddress((void**)&pa_lo, g_a_lo);
        cudaGetSymbolAddress((void**)&wq_hi, g_wq_hi);
        cudaGetSymbolAddress((void**)&wq_lo, g_wq_lo);
        cudaGetSymbolAddress((void**)&wk_hi, g_wk_hi);
        cudaGetSymbolAddress((void**)&wk_lo, g_wk_lo);
        cudaGetSymbolAddress((void**)&wv_hi, g_wv_hi);
        cudaGetSymbolAddress((void**)&wv_lo, g_wv_lo);
        cudaGetSymbolAddress((void**)&wo_hi, g_wo_hi);
        cudaGetSymbolAddress((void**)&wo_lo, g_wo_lo);
        cudaGetSymbolAddress((void**)&w1_hi, g_w1_hi);
        cudaGetSymbolAddress((void**)&w1_lo, g_w1_lo);
        cudaGetSymbolAddress((void**)&w2_hi, g_w2_hi);
        cudaGetSymbolAddress((void**)&w2_lo, g_w2_lo);
        cudaStreamCreateWithFlags(&s1, cudaStreamNonBlocking);
        cudaStreamCreateWithFlags(&s2, cudaStreamNonBlocking);
        cudaStreamCreateWithFlags(&sW, cudaStreamNonBlocking);
        cudaEventCreateWithFlags(&evStart, cudaEventDisableTiming);
        cudaEventCreateWithFlags(&evLn,    cudaEventDisableTiming);
        cudaEventCreateWithFlags(&evSWq,   cudaEventDisableTiming);
        cudaEventCreateWithFlags(&evSWk,   cudaEventDisableTiming);
        cudaEventCreateWithFlags(&evSWv,   cudaEventDisableTiming);
        cudaEventCreateWithFlags(&evSWo,   cudaEventDisableTiming);
        cudaEventCreateWithFlags(&evSW1,   cudaEventDisableTiming);
        cudaEventCreateWithFlags(&evSW2,   cudaEventDisableTiming);
        cudaEventCreateWithFlags(&evGK,    cudaEventDisableTiming);
        cudaEventCreateWithFlags(&evGV,    cudaEventDisableTiming);
        cudaFuncSetAttribute(attn_mma,
                             cudaFuncAttributeMaxDynamicSharedMemorySize, aSMEM);
        cudaFuncSetAttribute(gemm_mma<0, 0>,
                             cudaFuncAttributeMaxDynamicSharedMemorySize, 2 * kStage2);
        cudaFuncSetAttribute(gemm_mma<0, 1>,
                             cudaFuncAttributeMaxDynamicSharedMemorySize, 2 * kStage2);
        cudaFuncSetAttribute(gemm_mma<1, 1>,
                             cudaFuncAttributeMaxDynamicSharedMemorySize, 2 * kStage2);
        cudaGetSymbolAddress((void**)&p_x1,  g_x1);   // init flag last
    }

    const dim3 blk(256);
    const dim3 gD(kD / 128, kM / 128);      // (8, 64)
    const dim3 gF(kDff / 128, kM / 128);    // (32, 64)
    const int nWDD  = kD * kD / 4;
    const int nWDF  = kDff * kD / 4;
    const unsigned SMEM_G = 2 * kStage2;    // 81920 B per CTA -> 2 CTAs/SM

    // ---- fork: weight splits run on sW concurrently with the main chain
    cudaEventRecord(evStart, 0);
    cudaStreamWaitEvent(sW, evStart, 0);

    split_kernel<<<nWDD / 256, blk, 0, sW>>>(Wq, wq_hi, wq_lo, nWDD);
    cudaEventRecord(evSWq, sW);
    split_lora_kernel<<<nWDD / 256, blk, 0, sW>>>(Wk, la_k, lb_k, wk_hi, wk_lo);
    cudaEventRecord(evSWk, sW);
    split_lora_kernel<<<nWDD / 256, blk, 0, sW>>>(Wv, la_v, lb_v, wv_hi, wv_lo);
    cudaEventRecord(evSWv, sW);
    split_lora_kernel<<<nWDD / 256, blk, 0, sW>>>(Wo, la_o, lb_o, wo_hi, wo_lo);
    cudaEventRecord(evSWo, sW);
    split_kernel<<<nWDF / 256, blk, 0, sW>>>(W1, w1_hi, w1_lo, nWDF);
    cudaEventRecord(evSW1, sW);
    split_kernel<<<nWDF / 256, blk, 0, sW>>>(W2, w2_hi, w2_lo, nWDF);
    cudaEventRecord(evSW2, sW);

    // ---- main chain (stream 0)
    ln_split_kernel<<<kM, blk>>>(x, ga, ba, pa_hi, pa_lo);
    cudaEventRecord(evLn, 0);
    cudaStreamWaitEvent(s1, evLn, 0);
    cudaStreamWaitEvent(s2, evLn, 0);

    // QKV GEMMs on three streams (independent; tails overlap)
    cudaStreamWaitEvent(0, evSWq, 0);
    gemm_mma<0, 1><<<gD, blk, SMEM_G>>>(pa_hi, pa_lo, wq_hi, wq_lo,
                                        bq, nullptr,
                                        nullptr, pq_hi, pq_lo, kM, kD, kD);

    cudaStreamWaitEvent(s1, evSWk, 0);
    gemm_mma<0, 1><<<gD, blk, SMEM_G, s1>>>(pa_hi, pa_lo, wk_hi, wk_lo,
                                            nullptr, nullptr,
                                            nullptr, pk_hi, pk_lo, kM, kD, kD);
    cudaEventRecord(evGK, s1);

    cudaStreamWaitEvent(s2, evSWv, 0);
    gemm_mma<0, 1><<<gD, blk, SMEM_G, s2>>>(pa_hi, pa_lo, wv_hi, wv_lo,
                                            bv, nullptr,
                                            nullptr, pv_hi, pv_lo, kM, kD, kD);
    cudaEventRecord(evGV, s2);

    // attention (stream 0): after Q (same stream) + K, V (events)
    cudaStreamWaitEvent(0, evGK, 0);
    cudaStreamWaitEvent(0, evGV, 0);
    attn_mma<<<dim3(8, kB * kH), blk, aSMEM>>>(pq_hi, pq_lo, pk_hi, pk_lo,
                                               pv_hi, pv_lo, pa_hi, pa_lo);

    cudaStreamWaitEvent(0, evSWo, 0);
    gemm_mma<0, 0><<<gD, blk, SMEM_G>>>(pa_hi, pa_lo, wo_hi, wo_lo,
                                        bo, x,
                                        p_x1, nullptr, nullptr, kM, kD, kD);

    // ---- MLP half (stream 0)
    ln_split_kernel<<<kM, blk>>>(p_x1, gm, bmn, pa_hi, pa_lo);
    cudaStreamWaitEvent(0, evSW1, 0);
    gemm_mma<1, 1><<<gF, blk, SMEM_G>>>(pa_hi, pa_lo, w1_hi, w1_lo,
                                        b1, nullptr,
                                        nullptr, pu_hi, pu_lo, kM, kDff, kD);

    cudaStreamWaitEvent(0, evSW2, 0);
    gemm_mma<0, 0><<<gD, blk, SMEM_G>>>(pu_hi, pu_lo, w2_hi, w2_lo,
                                        b2, p_x1,
                                        out, nullptr, nullptr, kM, kD, kDff);
}